// round 1
// baseline (speedup 1.0000x reference)
#include <cuda_runtime.h>
#include <math.h>

// Problem constants (fixed by the reference)
#define MAIL   8
#define DMEM   128
#define DMSG   128
#define DTIME  128
#define DCAT   256      // DMSG + DTIME
#define HEADS  2
#define NPB    4        // nodes per block
#define NTHR   256

// Transposed-weight scratch (weights are small; transpose once per launch so
// the hot loop reads them coalesced: wT[k*128 + ch], ch = lane-contiguous).
__device__ float g_wqT[DMEM * DMEM];          // [k][ch]
__device__ float g_wkT[DCAT * DMEM];          // [k][ch]
__device__ float g_wvT[DCAT * DMEM];          // [k][ch]
__device__ float g_mlpT[DMEM * DMEM];         // [k][ch]

__global__ void transpose_weights(const float* __restrict__ wq,
                                  const float* __restrict__ wk,
                                  const float* __restrict__ wv,
                                  const float* __restrict__ mlp) {
    int i = blockIdx.x * blockDim.x + threadIdx.x;   // 0 .. 32767
    if (i < DMEM * DMEM) {
        int ch = i / DMEM, k = i % DMEM;
        g_wqT[k * DMEM + ch]  = wq[i];
        g_mlpT[k * DMEM + ch] = mlp[i];
    }
    if (i < DMEM * DCAT) {
        int ch = i / DCAT, k = i % DCAT;
        g_wkT[k * DMEM + ch] = wk[i];
        g_wvT[k * DMEM + ch] = wv[i];
    }
}

__global__ __launch_bounds__(NTHR)
void attn_mem_update_kernel(
    const int*   __restrict__ nodes,
    const float* __restrict__ times,
    const float* __restrict__ mem,
    const float* __restrict__ mail,
    const float* __restrict__ mail_time,
    const float* __restrict__ time_w,
    const float* __restrict__ time_b,
    const float* __restrict__ wq_b,
    const float* __restrict__ wk_b,
    const float* __restrict__ wv_b,
    const float* __restrict__ mlp_b,
    const float* __restrict__ ln_g,
    const float* __restrict__ ln_b,
    float*       __restrict__ out,
    int size)
{
    // m_cat buffer, later reused to hold K and V (each NPB*8*128 floats)
    __shared__ __align__(16) float s_m[NPB * MAIL * DCAT];   // 32 KB
    __shared__ __align__(16) float s_mem[NPB][DMEM];         // 2 KB
    __shared__ __align__(16) float s_q[NPB][DMEM];           // 2 KB
    __shared__ float s_attn[NPB][MAIL][HEADS];               // 256 B
    __shared__ __align__(16) float s_out[NPB][DMEM];         // 2 KB
    __shared__ int   s_node[NPB];
    __shared__ float s_time[NPB];

    const int tid  = threadIdx.x;
    const int warp = tid >> 5;
    const int lane = tid & 31;
    const int blk  = blockIdx.x;
    const int base = blk * NPB;

    // ---- Phase 1: node ids / times ----
    if (tid < NPB) {
        int g = base + tid;
        int nd = (g < size) ? nodes[g] : 0;
        s_node[tid] = nd;
        s_time[tid] = (g < size) ? times[g] : 0.0f;
    }
    __syncthreads();

    // ---- Phase 2: gather mem_data [NPB][128] ----
    for (int i = tid; i < NPB * DMEM; i += NTHR) {
        int n = i >> 7, c = i & 127;
        s_mem[n][c] = __ldg(mem + (size_t)s_node[n] * DMEM + c);
    }

    // ---- Phase 3: build m_cat = [mail | cos(dt*time_w + time_b)] ----
    for (int i = tid; i < NPB * MAIL * DCAT; i += NTHR) {
        int n = i >> 11;              // / 2048
        int r = i & 2047;
        int slot = r >> 8;
        int c = r & 255;
        int node = s_node[n];
        float v;
        if (c < DMSG) {
            v = __ldg(mail + ((size_t)node * MAIL + slot) * DMSG + c);
        } else {
            int j = c - DMSG;
            float dt = s_time[n] - __ldg(mail_time + (size_t)node * MAIL + slot);
            v = cosf(fmaf(dt, __ldg(time_w + j), __ldg(time_b + j)));
        }
        s_m[(n * MAIL + slot) * DCAT + c] = v;
    }
    __syncthreads();

    // ---- Phase 4: Q = mem_data @ wq^T + b  (512 dots of 128) ----
    {
        const int ch = tid & 127;
        const int nsel = tid >> 7;
        #pragma unroll
        for (int nn = 0; nn < 2; nn++) {
            int n = nsel + 2 * nn;
            float acc = __ldg(wq_b + ch);
            #pragma unroll 8
            for (int k = 0; k < DMEM; k++)
                acc = fmaf(__ldg(g_wqT + k * DMEM + ch), s_mem[n][k], acc);
            s_q[n][ch] = acc;
        }
    }

    // ---- Phase 5: K/V projections (dominant). Thread owns one channel of
    // K (tid<128) or V (tid>=128) across all 32 (node,slot) pairs. ----
    {
        const int ch = tid & 127;
        const int kv = tid >> 7;                // 0 = K, 1 = V
        const float* wT = kv ? g_wvT : g_wkT;
        const float  bias = kv ? __ldg(wv_b + ch) : __ldg(wk_b + ch);

        float acc[NPB * MAIL];
        #pragma unroll
        for (int i = 0; i < NPB * MAIL; i++) acc[i] = bias;

        #pragma unroll 1
        for (int kk = 0; kk < DCAT; kk += 8) {
            float w[8];
            #pragma unroll
            for (int u = 0; u < 8; u++)
                w[u] = __ldg(wT + (kk + u) * DMEM + ch);   // coalesced
            #pragma unroll
            for (int ns = 0; ns < NPB * MAIL; ns++) {
                const float4 m0 = *(const float4*)(s_m + ns * DCAT + kk);
                const float4 m1 = *(const float4*)(s_m + ns * DCAT + kk + 4);
                acc[ns] = fmaf(m0.x, w[0], acc[ns]);
                acc[ns] = fmaf(m0.y, w[1], acc[ns]);
                acc[ns] = fmaf(m0.z, w[2], acc[ns]);
                acc[ns] = fmaf(m0.w, w[3], acc[ns]);
                acc[ns] = fmaf(m1.x, w[4], acc[ns]);
                acc[ns] = fmaf(m1.y, w[5], acc[ns]);
                acc[ns] = fmaf(m1.z, w[6], acc[ns]);
                acc[ns] = fmaf(m1.w, w[7], acc[ns]);
            }
        }

        __syncthreads();                         // all reads of s_m done
        float* dst = s_m + kv * (NPB * MAIL * DMEM);   // reuse s_m: [K | V]
        #pragma unroll
        for (int ns = 0; ns < NPB * MAIL; ns++)
            dst[ns * DMEM + ch] = acc[ns];
    }
    __syncthreads();

    const float* s_K = s_m;
    const float* s_V = s_m + NPB * MAIL * DMEM;

    // ---- Phase 6: attention logits + LeakyReLU ----
    {
        #pragma unroll
        for (int r = 0; r < 8; r++) {
            int idx = warp * 8 + r;              // 0..63 = (n, s, h)
            int h = idx & 1;
            int s = (idx >> 1) & 7;
            int n = idx >> 4;
            const float* Kp = s_K + (n * MAIL + s) * DMEM + h * 64;
            const float* Qp = &s_q[n][h * 64];
            int d = lane * 2;
            float p = Qp[d] * Kp[d] + Qp[d + 1] * Kp[d + 1];
            #pragma unroll
            for (int off = 16; off; off >>= 1)
                p += __shfl_xor_sync(0xffffffffu, p, off);
            if (lane == 0) {
                s_attn[n][s][h] = (p >= 0.0f) ? p : 0.2f * p;
            }
        }
    }
    __syncthreads();

    // ---- softmax over mailbox slots per (node, head) ----
    if (tid < NPB * HEADS) {
        int n = tid >> 1, h = tid & 1;
        float mx = -1e30f;
        #pragma unroll
        for (int s = 0; s < MAIL; s++) mx = fmaxf(mx, s_attn[n][s][h]);
        float e[MAIL], sum = 0.0f;
        #pragma unroll
        for (int s = 0; s < MAIL; s++) { e[s] = expf(s_attn[n][s][h] - mx); sum += e[s]; }
        float inv = 1.0f / sum;
        #pragma unroll
        for (int s = 0; s < MAIL; s++) s_attn[n][s][h] = e[s] * inv;
    }
    __syncthreads();

    // ---- Phase 7: weighted V sum + residual ----
    {
        const int ch = tid & 127;
        const int h = ch >> 6;
        #pragma unroll
        for (int nn = 0; nn < 2; nn++) {
            int n = (tid >> 7) + 2 * nn;
            float o = s_mem[n][ch];
            #pragma unroll
            for (int s = 0; s < MAIL; s++)
                o = fmaf(s_attn[n][s][h], s_V[(n * MAIL + s) * DMEM + ch], o);
            s_out[n][ch] = o;
        }
    }
    __syncthreads();

    // ---- Phase 8: LayerNorm (warp w handles node w) ----
    if (warp < NPB) {
        int n = warp;
        float x[4], sum = 0.0f, sq = 0.0f;
        #pragma unroll
        for (int u = 0; u < 4; u++) {
            x[u] = s_out[n][lane * 4 + u];
            sum += x[u];
            sq  = fmaf(x[u], x[u], sq);
        }
        #pragma unroll
        for (int off = 16; off; off >>= 1) {
            sum += __shfl_xor_sync(0xffffffffu, sum, off);
            sq  += __shfl_xor_sync(0xffffffffu, sq, off);
        }
        float mu = sum * (1.0f / DMEM);
        float var = sq * (1.0f / DMEM) - mu * mu;
        float rstd = rsqrtf(var + 1e-5f);
        #pragma unroll
        for (int u = 0; u < 4; u++) {
            int c = lane * 4 + u;
            s_out[n][c] = (x[u] - mu) * rstd * __ldg(ln_g + c) + __ldg(ln_b + c);
        }
    }
    __syncthreads();

    // ---- Phase 9: MLP + ReLU, write output ----
    {
        const int ch = tid & 127;
        const int nsel = tid >> 7;
        #pragma unroll
        for (int nn = 0; nn < 2; nn++) {
            int n = nsel + 2 * nn;
            int g = base + n;
            if (g >= size) continue;
            float acc = __ldg(mlp_b + ch);
            #pragma unroll 8
            for (int k = 0; k < DMEM; k++)
                acc = fmaf(__ldg(g_mlpT + k * DMEM + ch), s_out[n][k], acc);
            out[(size_t)g * DMEM + ch] = fmaxf(acc, 0.0f);
        }
    }
}

extern "C" void kernel_launch(void* const* d_in, const int* in_sizes, int n_in,
                              void* d_out, int out_size) {
    const int*   nodes     = (const int*)  d_in[0];
    const float* times     = (const float*)d_in[1];
    const float* mem       = (const float*)d_in[2];
    const float* mail      = (const float*)d_in[3];
    const float* mail_time = (const float*)d_in[4];
    const float* time_w    = (const float*)d_in[5];
    const float* time_b    = (const float*)d_in[6];
    const float* wq_w      = (const float*)d_in[7];
    const float* wq_b      = (const float*)d_in[8];
    const float* wk_w      = (const float*)d_in[9];
    const float* wk_b      = (const float*)d_in[10];
    const float* wv_w      = (const float*)d_in[11];
    const float* wv_b      = (const float*)d_in[12];
    const float* mlp_w     = (const float*)d_in[13];
    const float* mlp_b     = (const float*)d_in[14];
    const float* ln_g      = (const float*)d_in[15];
    const float* ln_b      = (const float*)d_in[16];

    int size = in_sizes[0];

    transpose_weights<<<128, 256>>>(wq_w, wk_w, wv_w, mlp_w);

    int nblk = (size + NPB - 1) / NPB;
    attn_mem_update_kernel<<<nblk, NTHR>>>(
        nodes, times, mem, mail, mail_time, time_w, time_b,
        wq_b, wk_b, wv_b, mlp_b, ln_g, ln_b,
        (float*)d_out, size);
}

// round 3
// speedup vs baseline: 1.5875x; 1.5875x over previous
#include <cuda_runtime.h>
#include <cuda_fp16.h>
#include <cstdint>
#include <math.h>

#define MAIL   8
#define DMEM   128
#define DCAT   256
#define NPB    16
#define ROWS   128
#define NTHR   512

#define AH 264        // A row stride in halves (256 + 8 pad)
#define BH 72         // B row stride in halves (64 + 8 pad)
#define CS 257        // C row stride in floats (odd -> conflict-free columns)

// ---- smem byte offsets ----
#define OFF_NODE 0
#define OFF_TIME 64
#define OFF_BK   128
#define OFF_BV   640
#define OFF_ATT  1152                     // 128 x 2 floats
#define OFF_Q    2176                     // 16 x 132 floats
#define OFF_MEM  10624                    // 16 x 128 floats
#define OFF_OUT  18816                    // 16 x 128 floats
#define OFF_A_HI 27136                    // 128 x 264 halves = 67584 B
#define OFF_A_LO (OFF_A_HI + 67584)
#define OFF_B    (OFF_A_LO + 67584)       // 256 x 72 halves = 36864 B
#define SMEM_TOTAL (OFF_B + 36864)        // 199168 B
#define OFF_C    OFF_A_HI                 // C overlays A after GEMM (131584 B)

__device__ float g_wqT[DMEM * DMEM];                     // [k][ch]
__device__ float g_mlpT[DMEM * DMEM];                    // [k][ch]
__device__ __align__(16) __half g_B[4 * 256 * BH];       // [kchunk][out][BH]

__device__ __forceinline__ uint32_t smem_u32(const void* p) {
    uint32_t a;
    asm("{ .reg .u64 t; cvta.to.shared.u64 t, %1; cvt.u32.u64 %0, t; }"
        : "=r"(a) : "l"(p));
    return a;
}
__device__ __forceinline__ void ldsm4(uint32_t addr, uint32_t& r0, uint32_t& r1,
                                      uint32_t& r2, uint32_t& r3) {
    asm volatile("ldmatrix.sync.aligned.m8n8.x4.shared.b16 {%0,%1,%2,%3}, [%4];"
                 : "=r"(r0), "=r"(r1), "=r"(r2), "=r"(r3) : "r"(addr));
}
__device__ __forceinline__ void mma16816(float* c, uint32_t a0, uint32_t a1,
                                         uint32_t a2, uint32_t a3,
                                         uint32_t b0, uint32_t b1) {
    asm volatile("mma.sync.aligned.m16n8k16.row.col.f32.f16.f16.f32 "
                 "{%0,%1,%2,%3},{%4,%5,%6,%7},{%8,%9},{%0,%1,%2,%3};"
                 : "+f"(c[0]), "+f"(c[1]), "+f"(c[2]), "+f"(c[3])
                 : "r"(a0), "r"(a1), "r"(a2), "r"(a3), "r"(b0), "r"(b1));
}

// ---- prep: transpose fp32 weights; pack B = [Wk;Wv] as padded fp16 tiles ----
__global__ void prep_weights(const float* __restrict__ wq,
                             const float* __restrict__ wk,
                             const float* __restrict__ wv,
                             const float* __restrict__ mlp) {
    int i = blockIdx.x * 256 + threadIdx.x;          // 0..65535
    if (i < DMEM * DMEM) {
        int ch = i >> 7, k = i & 127;
        g_wqT[k * 128 + ch]  = wq[i];
        g_mlpT[k * 128 + ch] = mlp[i];
    }
    int o = i >> 8, k = i & 255;
    float w = (o < 128) ? wk[o * 256 + k] : wv[(o - 128) * 256 + k];
    g_B[(k >> 6) * 256 * BH + o * BH + (k & 63)] = __float2half_rn(w);
}

__global__ __launch_bounds__(NTHR, 1)
void attn_mma_kernel(
    const int*   __restrict__ nodes,
    const float* __restrict__ times,
    const float* __restrict__ mem,
    const float* __restrict__ mail,
    const float* __restrict__ mail_time,
    const float* __restrict__ time_w,
    const float* __restrict__ time_b,
    const float* __restrict__ wq_b,
    const float* __restrict__ wk_b,
    const float* __restrict__ wv_b,
    const float* __restrict__ mlp_b,
    const float* __restrict__ ln_g,
    const float* __restrict__ ln_b,
    float*       __restrict__ out,
    int size)
{
    extern __shared__ __align__(1024) char smem[];
    const uint32_t sb = smem_u32(smem);
    const int tid = threadIdx.x, warp = tid >> 5, lane = tid & 31;
    const int base = blockIdx.x * NPB;

    int*   s_node = (int*)(smem + OFF_NODE);
    float* s_time = (float*)(smem + OFF_TIME);
    float* s_bk   = (float*)(smem + OFF_BK);
    float* s_bv   = (float*)(smem + OFF_BV);
    float* s_att  = (float*)(smem + OFF_ATT);
    float* s_q    = (float*)(smem + OFF_Q);      // stride 132
    float* s_memf = (float*)(smem + OFF_MEM);
    float* s_out  = (float*)(smem + OFF_OUT);
    float* s_C    = (float*)(smem + OFF_C);      // stride CS

    if (tid < NPB) {
        int g = base + tid; if (g >= size) g = size - 1;
        s_node[tid] = nodes[g];
        s_time[tid] = times[g];
    }
    if (tid >= 128 && tid < 256) { int c = tid - 128; s_bk[c] = wk_b[c]; s_bv[c] = wv_b[c]; }
    __syncthreads();

    // gather mem rows [16][128]
    {
        float4* d4 = (float4*)s_memf;
        for (int i = tid; i < NPB * DMEM / 4; i += NTHR) {
            int n = i >> 5, c4 = i & 31;
            d4[i] = *(const float4*)(mem + (size_t)s_node[n] * DMEM + c4 * 4);
        }
    }

    // build A = Mcat as exact fp16 hi+lo split
    for (int i = tid * 2; i < ROWS * DCAT; i += NTHR * 2) {
        int r = i >> 8, k = i & 255;
        int n = r >> 3, slot = r & 7;
        long nm = (long)s_node[n] * MAIL + slot;
        float v0, v1;
        if (k < 128) {
            const float* mp = mail + nm * 128 + k;
            v0 = mp[0]; v1 = mp[1];
        } else {
            float dt = s_time[n] - __ldg(mail_time + nm);
            int j = k - 128;
            v0 = cosf(fmaf(dt, __ldg(time_w + j),     __ldg(time_b + j)));
            v1 = cosf(fmaf(dt, __ldg(time_w + j + 1), __ldg(time_b + j + 1)));
        }
        __half h0 = __float2half_rn(v0), h1 = __float2half_rn(v1);
        __half l0 = __float2half_rn(v0 - __half2float(h0));
        __half l1 = __float2half_rn(v1 - __half2float(h1));
        *(__half2*)(smem + OFF_A_HI + ((size_t)r * AH + k) * 2) = __halves2half2(h0, h1);
        *(__half2*)(smem + OFF_A_LO + ((size_t)r * AH + k) * 2) = __halves2half2(l0, l1);
    }
    __syncthreads();

    // Q = mem @ wqT + b (fp32 exact)
    {
        int ch = tid & 127, ng = tid >> 7;       // ng 0..3
        #pragma unroll
        for (int nn = 0; nn < 4; nn++) {
            int n = ng * 4 + nn;
            float acc = __ldg(wq_b + ch);
            #pragma unroll 8
            for (int k = 0; k < 128; k++)
                acc = fmaf(__ldg(g_wqT + k * 128 + ch), s_memf[n * 128 + k], acc);
            s_q[n * 132 + ch] = acc;
        }
    }

    // ---- GEMM: C[128x256] = (Ahi + Alo)[128x256] x B^T, fp32 accum ----
    const int rb = warp >> 2, cb = warp & 3;     // row-block 32, col-block 64
    const int m0 = rb * 32, n0 = cb * 64;
    const int g8 = lane >> 3, lr = lane & 7;

    // A frag lane address components
    const int a_row = m0 + lr + ((g8 & 1) << 3);
    const int a_koff = (g8 >> 1) << 3;
    const uint32_t aHiB = sb + OFF_A_HI + ((uint32_t)a_row * AH + a_koff) * 2;
    const uint32_t aLoB = sb + OFF_A_LO + ((uint32_t)a_row * AH + a_koff) * 2;
    // B frag lane address components
    const int b_out = lr + ((g8 >> 1) << 3);
    const int b_koff = (g8 & 1) << 3;
    const uint32_t bB = sb + OFF_B + (((uint32_t)n0 + b_out) * BH + b_koff) * 2;

    float acc[2][8][4];
    #pragma unroll
    for (int h = 0; h < 2; h++)
        #pragma unroll
        for (int t = 0; t < 8; t++)
            #pragma unroll
            for (int u = 0; u < 4; u++) acc[h][t][u] = 0.f;

    #pragma unroll 1
    for (int c = 0; c < 4; c++) {
        __syncthreads();                          // prior chunk's reads done
        {
            const uint4* src = (const uint4*)((const char*)g_B + c * 36864);
            uint4* dst = (uint4*)(smem + OFF_B);
            for (int i = tid; i < 2304; i += NTHR) dst[i] = src[i];
        }
        __syncthreads();

        #pragma unroll
        for (int ks = 0; ks < 4; ks++) {
            const int kg = c * 64 + ks * 16;      // global k for A
            uint32_t bf[4][4];
            #pragma unroll
            for (int t = 0; t < 4; t++)
                ldsm4(bB + ((uint32_t)t * 16 * BH + ks * 16) * 2,
                      bf[t][0], bf[t][1], bf[t][2], bf[t][3]);
            #pragma unroll
            for (int h = 0; h < 2; h++) {
                uint32_t ah0, ah1, ah2, ah3, al0, al1, al2, al3;
                uint32_t off = ((uint32_t)h * 16 * AH + kg) * 2;
                ldsm4(aHiB + off, ah0, ah1, ah2, ah3);
                ldsm4(aLoB + off, al0, al1, al2, al3);
                #pragma unroll
                for (int nt = 0; nt < 8; nt++) {
                    uint32_t b0 = bf[nt >> 1][(nt & 1) * 2];
                    uint32_t b1 = bf[nt >> 1][(nt & 1) * 2 + 1];
                    mma16816(acc[h][nt], ah0, ah1, ah2, ah3, b0, b1);
                    mma16816(acc[h][nt], al0, al1, al2, al3, b0, b1);
                }
            }
        }
    }
    __syncthreads();                              // all A reads done; C overlays A

    // write C to smem
    {
        const int rw = m0 + (lane >> 2);
        const int cw = n0 + 2 * (lane & 3);
        #pragma unroll
        for (int h = 0; h < 2; h++)
            #pragma unroll
            for (int nt = 0; nt < 8; nt++) {
                int r0 = rw + h * 16, cc = cw + nt * 8;
                s_C[(size_t)r0 * CS + cc]           = acc[h][nt][0];
                s_C[(size_t)r0 * CS + cc + 1]       = acc[h][nt][1];
                s_C[(size_t)(r0 + 8) * CS + cc]     = acc[h][nt][2];
                s_C[(size_t)(r0 + 8) * CS + cc + 1] = acc[h][nt][3];
            }
    }
    __syncthreads();

    // ---- logits (K half: cols 0..127) + LeakyReLU ----
    if (tid < ROWS) {
        int r = tid, n = r >> 3;
        float p0 = 0.f, p1 = 0.f;
        #pragma unroll 8
        for (int cc = 0; cc < 64; cc++)
            p0 = fmaf(s_C[(size_t)r * CS + cc] + s_bk[cc], s_q[n * 132 + cc], p0);
        #pragma unroll 8
        for (int cc = 64; cc < 128; cc++)
            p1 = fmaf(s_C[(size_t)r * CS + cc] + s_bk[cc], s_q[n * 132 + cc], p1);
        s_att[r * 2 + 0] = (p0 >= 0.f) ? p0 : 0.2f * p0;
        s_att[r * 2 + 1] = (p1 >= 0.f) ? p1 : 0.2f * p1;
    }
    __syncthreads();

    if (tid < NPB * 2) {                          // softmax over slots
        int n = tid >> 1, h = tid & 1;
        float mx = -1e30f;
        #pragma unroll
        for (int s = 0; s < MAIL; s++) mx = fmaxf(mx, s_att[(n * 8 + s) * 2 + h]);
        float e[MAIL], sum = 0.f;
        #pragma unroll
        for (int s = 0; s < MAIL; s++) { e[s] = expf(s_att[(n * 8 + s) * 2 + h] - mx); sum += e[s]; }
        float inv = 1.f / sum;
        #pragma unroll
        for (int s = 0; s < MAIL; s++) s_att[(n * 8 + s) * 2 + h] = e[s] * inv;
    }
    __syncthreads();

    // ---- weighted V (cols 128..255) + residual ----
    {
        int n = tid >> 5, c0 = (tid & 31) * 4;    // 4 channels per thread
        #pragma unroll
        for (int u = 0; u < 4; u++) {
            int cc = c0 + u, h = cc >> 6;
            float o = s_memf[n * 128 + cc];
            #pragma unroll
            for (int s = 0; s < MAIL; s++)
                o = fmaf(s_att[(n * 8 + s) * 2 + h],
                         s_C[(size_t)(n * 8 + s) * CS + 128 + cc] + s_bv[cc], o);
            s_out[n * 128 + cc] = o;
        }
    }
    __syncthreads();

    // ---- LayerNorm: warp n -> node n ----
    {
        int n = warp;
        float4 x4 = ((float4*)(s_out + n * 128))[lane];
        float sum = x4.x + x4.y + x4.z + x4.w;
        float sq  = fmaf(x4.x, x4.x, fmaf(x4.y, x4.y, fmaf(x4.z, x4.z, x4.w * x4.w)));
        #pragma unroll
        for (int off = 16; off; off >>= 1) {
            sum += __shfl_xor_sync(0xffffffffu, sum, off);
            sq  += __shfl_xor_sync(0xffffffffu, sq, off);
        }
        float mu = sum * (1.f / 128.f);
        float rstd = rsqrtf(sq * (1.f / 128.f) - mu * mu + 1e-5f);
        float o[4] = {x4.x, x4.y, x4.z, x4.w};
        #pragma unroll
        for (int u = 0; u < 4; u++) {
            int cc = lane * 4 + u;
            s_out[n * 128 + cc] = (o[u] - mu) * rstd * __ldg(ln_g + cc) + __ldg(ln_b + cc);
        }
    }
    __syncthreads();

    // ---- MLP + ReLU ----
    {
        int ch = tid & 127, ng = tid >> 7;
        #pragma unroll
        for (int nn = 0; nn < 4; nn++) {
            int n = ng * 4 + nn, g = base + n;
            float a = __ldg(mlp_b + ch);
            #pragma unroll 8
            for (int k = 0; k < 128; k++)
                a = fmaf(__ldg(g_mlpT + k * 128 + ch), s_out[n * 128 + k], a);
            if (g < size) out[(size_t)g * 128 + ch] = fmaxf(a, 0.f);
        }
    }
}

extern "C" void kernel_launch(void* const* d_in, const int* in_sizes, int n_in,
                              void* d_out, int out_size) {
    const int*   nodes     = (const int*)  d_in[0];
    const float* times     = (const float*)d_in[1];
    const float* mem       = (const float*)d_in[2];
    const float* mail      = (const float*)d_in[3];
    const float* mail_time = (const float*)d_in[4];
    const float* time_w    = (const float*)d_in[5];
    const float* time_b    = (const float*)d_in[6];
    const float* wq_w      = (const float*)d_in[7];
    const float* wq_b      = (const float*)d_in[8];
    const float* wk_w      = (const float*)d_in[9];
    const float* wk_b      = (const float*)d_in[10];
    const float* wv_w      = (const float*)d_in[11];
    const float* wv_b      = (const float*)d_in[12];
    const float* mlp_w     = (const float*)d_in[13];
    const float* mlp_b     = (const float*)d_in[14];
    const float* ln_g      = (const float*)d_in[15];
    const float* ln_b      = (const float*)d_in[16];
    int size = in_sizes[0];

    cudaFuncSetAttribute(attn_mma_kernel,
                         cudaFuncAttributeMaxDynamicSharedMemorySize, SMEM_TOTAL);

    prep_weights<<<256, 256>>>(wq_w, wk_w, wv_w, mlp_w);

    int nblk = (size + NPB - 1) / NPB;
    attn_mma_kernel<<<nblk, NTHR, SMEM_TOTAL>>>(
        nodes, times, mem, mail, mail_time, time_w, time_b,
        wq_b, wk_b, wv_b, mlp_b, ln_g, ln_b,
        (float*)d_out, size);
}

// round 4
// speedup vs baseline: 2.8890x; 1.8198x over previous
#include <cuda_runtime.h>
#include <cuda_fp16.h>
#include <cstdint>
#include <math.h>

#define MAIL   8
#define DMEM   128
#define DCAT   256
#define NPB    8
#define ROWS   64          // node-slot rows per CTA
#define NTHR   256

#define AH 264             // A row stride in halves (256 + 8)
#define BH 40              // B chunk row stride in halves (32 + 8)

// ---- smem byte offsets ----
#define OFF_NODE 0
#define OFF_TIME 32
#define OFF_BK   64
#define OFF_BV   576
#define OFF_ATT  1088                      // 64 rows x 2 heads floats
#define OFF_MEM  1600                      // 8 x 128 f32
#define OFF_Q    5696                      // 8 x 132 f32 (OUT overlays this)
#define OFF_OUT  5696
#define OFF_A    9920                      // 64 x 264 halves = 33792 B
#define OFF_B    43712                     // 256 x 40 halves = 20480 B
#define SMEM_TOTAL 64192

__device__ float g_wqT[DMEM * DMEM];                 // [k][ch]
__device__ float g_mlpT[DMEM * DMEM];                // [k][ch]
__device__ __align__(16) __half g_B[8 * 256 * BH];   // [kchunk32][out][BH]

__device__ __forceinline__ uint32_t smem_u32(const void* p) {
    uint32_t a;
    asm("{ .reg .u64 t; cvta.to.shared.u64 t, %1; cvt.u32.u64 %0, t; }"
        : "=r"(a) : "l"(p));
    return a;
}
__device__ __forceinline__ void ldsm4(uint32_t addr, uint32_t& r0, uint32_t& r1,
                                      uint32_t& r2, uint32_t& r3) {
    asm volatile("ldmatrix.sync.aligned.m8n8.x4.shared.b16 {%0,%1,%2,%3}, [%4];"
                 : "=r"(r0), "=r"(r1), "=r"(r2), "=r"(r3) : "r"(addr));
}
__device__ __forceinline__ void mma16816(float* c, uint32_t a0, uint32_t a1,
                                         uint32_t a2, uint32_t a3,
                                         uint32_t b0, uint32_t b1) {
    asm volatile("mma.sync.aligned.m16n8k16.row.col.f32.f16.f16.f32 "
                 "{%0,%1,%2,%3},{%4,%5,%6,%7},{%8,%9},{%0,%1,%2,%3};"
                 : "+f"(c[0]), "+f"(c[1]), "+f"(c[2]), "+f"(c[3])
                 : "r"(a0), "r"(a1), "r"(a2), "r"(a3), "r"(b0), "r"(b1));
}

__global__ void prep_weights(const float* __restrict__ wq,
                             const float* __restrict__ wk,
                             const float* __restrict__ wv,
                             const float* __restrict__ mlp) {
    int i = blockIdx.x * 256 + threadIdx.x;          // 0..65535
    if (i < DMEM * DMEM) {
        int ch = i >> 7, k = i & 127;
        g_wqT[k * 128 + ch]  = wq[i];
        g_mlpT[k * 128 + ch] = mlp[i];
    }
    int o = i >> 8, k = i & 255;
    float w = (o < 128) ? wk[o * 256 + k] : wv[(o - 128) * 256 + k];
    int c = k >> 5, kk = k & 31;
    g_B[(c * 256 + o) * BH + kk] = __float2half_rn(w);
}

__global__ __launch_bounds__(NTHR, 2)
void attn_mma_kernel(
    const int*   __restrict__ nodes,
    const float* __restrict__ times,
    const float* __restrict__ mem,
    const float* __restrict__ mail,
    const float* __restrict__ mail_time,
    const float* __restrict__ time_w,
    const float* __restrict__ time_b,
    const float* __restrict__ wq_b,
    const float* __restrict__ wk_b,
    const float* __restrict__ wv_b,
    const float* __restrict__ mlp_b,
    const float* __restrict__ ln_g,
    const float* __restrict__ ln_b,
    float*       __restrict__ out,
    int size)
{
    extern __shared__ __align__(1024) char smem[];
    const uint32_t sb = smem_u32(smem);
    const int tid = threadIdx.x, warp = tid >> 5, lane = tid & 31;
    const int base = blockIdx.x * NPB;

    int*   s_node = (int*)(smem + OFF_NODE);
    float* s_time = (float*)(smem + OFF_TIME);
    float* s_bk   = (float*)(smem + OFF_BK);
    float* s_bv   = (float*)(smem + OFF_BV);
    float* s_att  = (float*)(smem + OFF_ATT);
    float* s_memf = (float*)(smem + OFF_MEM);
    float* s_q    = (float*)(smem + OFF_Q);        // stride 132
    float* s_out  = (float*)(smem + OFF_OUT);      // overlays s_q

    if (tid < NPB) {
        int g = base + tid; if (g >= size) g = size - 1;
        s_node[tid] = nodes[g];
        s_time[tid] = times[g];
    }
    if (tid >= 128) { int c = tid - 128; s_bk[c] = wk_b[c]; s_bv[c] = wv_b[c]; }
    __syncthreads();

    // gather mem rows [8][128]
    {
        float4* d4 = (float4*)s_memf;
        for (int i = tid; i < NPB * DMEM / 4; i += NTHR) {
            int n = i >> 5, c4 = i & 31;
            d4[i] = *(const float4*)(mem + (size_t)s_node[n] * DMEM + c4 * 4);
        }
    }

    // build A = Mcat as single fp16 (cos via MUFU)
    for (int i = tid * 2; i < ROWS * DCAT; i += NTHR * 2) {
        int r = i >> 8, k = i & 255;
        int n = r >> 3, slot = r & 7;
        long nm = (long)s_node[n] * MAIL + slot;
        float v0, v1;
        if (k < 128) {
            float2 mv = *(const float2*)(mail + nm * 128 + k);
            v0 = mv.x; v1 = mv.y;
        } else {
            float dt = s_time[n] - __ldg(mail_time + nm);
            int j = k - 128;
            v0 = __cosf(fmaf(dt, __ldg(time_w + j),     __ldg(time_b + j)));
            v1 = __cosf(fmaf(dt, __ldg(time_w + j + 1), __ldg(time_b + j + 1)));
        }
        *(__half2*)(smem + OFF_A + ((size_t)r * AH + k) * 2) =
            __halves2half2(__float2half_rn(v0), __float2half_rn(v1));
    }
    __syncthreads();

    // Q = mem @ wqT + b (fp32 exact); 4 nodes per thread in registers
    {
        int ch = tid & 127, ng = tid >> 7;          // ng 0..1
        float a0 = __ldg(wq_b + ch), a1 = a0, a2 = a0, a3 = a0;
        const float* m0p = s_memf + (ng * 4 + 0) * 128;
        const float* m1p = s_memf + (ng * 4 + 1) * 128;
        const float* m2p = s_memf + (ng * 4 + 2) * 128;
        const float* m3p = s_memf + (ng * 4 + 3) * 128;
        #pragma unroll 4
        for (int kk = 0; kk < 128; kk += 4) {
            float w0 = __ldg(g_wqT + (kk + 0) * 128 + ch);
            float w1 = __ldg(g_wqT + (kk + 1) * 128 + ch);
            float w2 = __ldg(g_wqT + (kk + 2) * 128 + ch);
            float w3 = __ldg(g_wqT + (kk + 3) * 128 + ch);
            float4 x0 = *(const float4*)(m0p + kk);
            float4 x1 = *(const float4*)(m1p + kk);
            float4 x2 = *(const float4*)(m2p + kk);
            float4 x3 = *(const float4*)(m3p + kk);
            a0 = fmaf(x0.x, w0, fmaf(x0.y, w1, fmaf(x0.z, w2, fmaf(x0.w, w3, a0))));
            a1 = fmaf(x1.x, w0, fmaf(x1.y, w1, fmaf(x1.z, w2, fmaf(x1.w, w3, a1))));
            a2 = fmaf(x2.x, w0, fmaf(x2.y, w1, fmaf(x2.z, w2, fmaf(x2.w, w3, a2))));
            a3 = fmaf(x3.x, w0, fmaf(x3.y, w1, fmaf(x3.z, w2, fmaf(x3.w, w3, a3))));
        }
        s_q[(ng * 4 + 0) * 132 + ch] = a0;
        s_q[(ng * 4 + 1) * 132 + ch] = a1;
        s_q[(ng * 4 + 2) * 132 + ch] = a2;
        s_q[(ng * 4 + 3) * 132 + ch] = a3;
    }

    // ---- GEMM: C[64x256] = A[64x256] x B^T in registers ----
    const int rb = warp >> 2, cb = warp & 3;        // 32-row block, 64-col block
    const int m0 = rb * 32;
    const int g8 = lane >> 3, lr = lane & 7;
    const int a_row = m0 + lr + ((g8 & 1) << 3);
    const int a_koff = (g8 >> 1) << 3;
    const uint32_t aB = sb + OFF_A + ((uint32_t)a_row * AH + a_koff) * 2;
    const int b_out = lr + ((g8 >> 1) << 3);
    const int b_koff = (g8 & 1) << 3;
    const uint32_t bB = sb + OFF_B + (((uint32_t)cb * 64 + b_out) * BH + b_koff) * 2;

    float acc[2][8][4];
    #pragma unroll
    for (int rh = 0; rh < 2; rh++)
        #pragma unroll
        for (int t = 0; t < 8; t++)
            #pragma unroll
            for (int u = 0; u < 4; u++) acc[rh][t][u] = 0.f;

    #pragma unroll 1
    for (int c = 0; c < 8; c++) {
        __syncthreads();
        {
            const uint4* src = (const uint4*)((const char*)g_B + c * 20480);
            uint4* dst = (uint4*)(smem + OFF_B);
            #pragma unroll
            for (int i = 0; i < 5; i++) dst[tid + i * NTHR] = src[tid + i * NTHR];
        }
        __syncthreads();
        #pragma unroll
        for (int ks = 0; ks < 2; ks++) {
            uint32_t bf[4][4];
            #pragma unroll
            for (int t = 0; t < 4; t++)
                ldsm4(bB + ((uint32_t)t * 16 * BH + ks * 16) * 2,
                      bf[t][0], bf[t][1], bf[t][2], bf[t][3]);
            #pragma unroll
            for (int rh = 0; rh < 2; rh++) {
                uint32_t a0, a1, a2, a3;
                ldsm4(aB + ((uint32_t)rh * 16 * AH + c * 32 + ks * 16) * 2,
                      a0, a1, a2, a3);
                #pragma unroll
                for (int nt = 0; nt < 8; nt++)
                    mma16816(acc[rh][nt], a0, a1, a2, a3,
                             bf[nt >> 1][(nt & 1) * 2], bf[nt >> 1][(nt & 1) * 2 + 1]);
            }
        }
    }

    const int cw = 2 * (lane & 3);
    const int e  = lane >> 2;

    // ---- logits in registers (K warps: cb 0,1), head = cb ----
    if (cb < 2) {
        float p[4] = {0.f, 0.f, 0.f, 0.f};          // node 4rb+{0..3}, slot e
        #pragma unroll
        for (int rh = 0; rh < 2; rh++)
            #pragma unroll
            for (int nt = 0; nt < 8; nt++)
                #pragma unroll
                for (int u = 0; u < 4; u++) {
                    int cl = cw + nt * 8 + (u & 1);          // 0..63
                    int col = cb * 64 + cl;
                    int ni = rh * 2 + (u >> 1);
                    int node = 4 * rb + ni;
                    p[ni] = fmaf(acc[rh][nt][u] + s_bk[col],
                                 s_q[node * 132 + col], p[ni]);
                }
        #pragma unroll
        for (int ni = 0; ni < 4; ni++) {
            p[ni] += __shfl_xor_sync(0xffffffffu, p[ni], 1);
            p[ni] += __shfl_xor_sync(0xffffffffu, p[ni], 2);
        }
        if ((lane & 3) == 0) {
            #pragma unroll
            for (int ni = 0; ni < 4; ni++) {
                float v = p[ni];
                v = (v >= 0.f) ? v : 0.2f * v;
                s_att[((4 * rb + ni) * 8 + e) * 2 + cb] = v;
            }
        }
    }
    __syncthreads();

    if (tid < NPB * 2) {                             // softmax over slots
        int n = tid >> 1, h = tid & 1;
        float mx = -1e30f;
        #pragma unroll
        for (int s = 0; s < MAIL; s++) mx = fmaxf(mx, s_att[(n * 8 + s) * 2 + h]);
        float ex[MAIL], sum = 0.f;
        #pragma unroll
        for (int s = 0; s < MAIL; s++) { ex[s] = __expf(s_att[(n * 8 + s) * 2 + h] - mx); sum += ex[s]; }
        float inv = 1.f / sum;
        #pragma unroll
        for (int s = 0; s < MAIL; s++) s_att[(n * 8 + s) * 2 + h] = ex[s] * inv;
    }
    __syncthreads();

    // ---- V slot-sum in registers (V warps: cb 2,3), head = cb-2 ----
    if (cb >= 2) {
        const int head = cb - 2;
        float v[2][8][4];
        #pragma unroll
        for (int rh = 0; rh < 2; rh++) {
            float attA = s_att[((4 * rb + 2 * rh + 0) * 8 + e) * 2 + head];
            float attB = s_att[((4 * rb + 2 * rh + 1) * 8 + e) * 2 + head];
            #pragma unroll
            for (int nt = 0; nt < 8; nt++) {
                v[rh][nt][0] = acc[rh][nt][0] * attA;
                v[rh][nt][1] = acc[rh][nt][1] * attA;
                v[rh][nt][2] = acc[rh][nt][2] * attB;
                v[rh][nt][3] = acc[rh][nt][3] * attB;
            }
        }
        #pragma unroll
        for (int rh = 0; rh < 2; rh++)
            #pragma unroll
            for (int nt = 0; nt < 8; nt++)
                #pragma unroll
                for (int u = 0; u < 4; u++) {
                    float x = v[rh][nt][u];
                    x += __shfl_xor_sync(0xffffffffu, x, 4);
                    x += __shfl_xor_sync(0xffffffffu, x, 8);
                    x += __shfl_xor_sync(0xffffffffu, x, 16);
                    v[rh][nt][u] = x;
                }
        if (e == 0) {
            #pragma unroll
            for (int rh = 0; rh < 2; rh++)
                #pragma unroll
                for (int nt = 0; nt < 8; nt++)
                    #pragma unroll
                    for (int u = 0; u < 4; u++) {
                        int node = 4 * rb + 2 * rh + (u >> 1);
                        int ch = head * 64 + cw + nt * 8 + (u & 1);
                        s_out[node * 128 + ch] =
                            v[rh][nt][u] + s_bv[ch] + s_memf[node * 128 + ch];
                    }
        }
    }
    __syncthreads();

    // ---- LayerNorm: warp n -> node n ----
    {
        int n = warp;
        float4 x4 = ((float4*)(s_out + n * 128))[lane];
        float sum = x4.x + x4.y + x4.z + x4.w;
        float sq  = fmaf(x4.x, x4.x, fmaf(x4.y, x4.y, fmaf(x4.z, x4.z, x4.w * x4.w)));
        #pragma unroll
        for (int off = 16; off; off >>= 1) {
            sum += __shfl_xor_sync(0xffffffffu, sum, off);
            sq  += __shfl_xor_sync(0xffffffffu, sq, off);
        }
        float mu = sum * (1.f / 128.f);
        float rstd = rsqrtf(sq * (1.f / 128.f) - mu * mu + 1e-5f);
        float o[4] = {x4.x, x4.y, x4.z, x4.w};
        #pragma unroll
        for (int u = 0; u < 4; u++) {
            int cc = lane * 4 + u;
            s_out[n * 128 + cc] = (o[u] - mu) * rstd * __ldg(ln_g + cc) + __ldg(ln_b + cc);
        }
    }
    __syncthreads();

    // ---- MLP + ReLU: 4 nodes per thread in registers ----
    {
        int ch = tid & 127, ng = tid >> 7;
        float a0 = __ldg(mlp_b + ch), a1 = a0, a2 = a0, a3 = a0;
        const float* o0 = s_out + (ng * 4 + 0) * 128;
        const float* o1 = s_out + (ng * 4 + 1) * 128;
        const float* o2 = s_out + (ng * 4 + 2) * 128;
        const float* o3 = s_out + (ng * 4 + 3) * 128;
        #pragma unroll 4
        for (int kk = 0; kk < 128; kk += 4) {
            float w0 = __ldg(g_mlpT + (kk + 0) * 128 + ch);
            float w1 = __ldg(g_mlpT + (kk + 1) * 128 + ch);
            float w2 = __ldg(g_mlpT + (kk + 2) * 128 + ch);
            float w3 = __ldg(g_mlpT + (kk + 3) * 128 + ch);
            float4 x0 = *(const float4*)(o0 + kk);
            float4 x1 = *(const float4*)(o1 + kk);
            float4 x2 = *(const float4*)(o2 + kk);
            float4 x3 = *(const float4*)(o3 + kk);
            a0 = fmaf(x0.x, w0, fmaf(x0.y, w1, fmaf(x0.z, w2, fmaf(x0.w, w3, a0))));
            a1 = fmaf(x1.x, w0, fmaf(x1.y, w1, fmaf(x1.z, w2, fmaf(x1.w, w3, a1))));
            a2 = fmaf(x2.x, w0, fmaf(x2.y, w1, fmaf(x2.z, w2, fmaf(x2.w, w3, a2))));
            a3 = fmaf(x3.x, w0, fmaf(x3.y, w1, fmaf(x3.z, w2, fmaf(x3.w, w3, a3))));
        }
        float r[4] = {a0, a1, a2, a3};
        #pragma unroll
        for (int nn = 0; nn < 4; nn++) {
            int g = base + ng * 4 + nn;
            if (g < size) out[(size_t)g * 128 + ch] = fmaxf(r[nn], 0.f);
        }
    }
}

extern "C" void kernel_launch(void* const* d_in, const int* in_sizes, int n_in,
                              void* d_out, int out_size) {
    const int*   nodes     = (const int*)  d_in[0];
    const float* times     = (const float*)d_in[1];
    const float* mem       = (const float*)d_in[2];
    const float* mail      = (const float*)d_in[3];
    const float* mail_time = (const float*)d_in[4];
    const float* time_w    = (const float*)d_in[5];
    const float* time_b    = (const float*)d_in[6];
    const float* wq_w      = (const float*)d_in[7];
    const float* wq_b      = (const float*)d_in[8];
    const float* wk_w      = (const float*)d_in[9];
    const float* wk_b      = (const float*)d_in[10];
    const float* wv_w      = (const float*)d_in[11];
    const float* wv_b      = (const float*)d_in[12];
    const float* mlp_w     = (const float*)d_in[13];
    const float* mlp_b     = (const float*)d_in[14];
    const float* ln_g      = (const float*)d_in[15];
    const float* ln_b      = (const float*)d_in[16];
    int size = in_sizes[0];

    cudaFuncSetAttribute(attn_mma_kernel,
                         cudaFuncAttributeMaxDynamicSharedMemorySize, SMEM_TOTAL);

    prep_weights<<<256, 256>>>(wq_w, wk_w, wv_w, mlp_w);

    int nblk = (size + NPB - 1) / NPB;
    attn_mma_kernel<<<nblk, NTHR, SMEM_TOTAL>>>(
        nodes, times, mem, mail, mail_time, time_w, time_b,
        wq_b, wk_b, wv_b, mlp_b, ln_g, ln_b,
        (float*)d_out, size);
}

// round 5
// speedup vs baseline: 4.0649x; 1.4070x over previous
#include <cuda_runtime.h>
#include <cuda_fp16.h>
#include <cstdint>
#include <math.h>

#define MAIL   8
#define DMEM   128
#define DCAT   256
#define NPB    8
#define ROWS   64
#define NTHR   256

#define AH 264             // A row stride in halves (256 + 8)

// ---- smem byte offsets ----
#define OFF_NODE 0
#define OFF_TIME 32
#define OFF_BK   64
#define OFF_BV   576
#define OFF_ATT  1088                      // 64 rows x 2 heads
#define OFF_DT   1600                      // 64 floats
#define OFF_MEM  1856                      // 8 x 128 f32
#define OFF_Q    5952                      // 8 x 132 f32 (OUT overlays)
#define OFF_OUT  5952
#define OFF_A    10176                     // 64 x 264 halves = 33792 B
#define SMEM_TOTAL 43968

__device__ float g_wqT[DMEM * DMEM];                  // [k][ch]
__device__ float g_mlpT[DMEM * DMEM];                 // [k][ch]
// B = [Wk;Wv] pre-arranged in mma-fragment order:
// idx = ((cb*16+ks)*32 + lane)*16 + nt*2 + b   (uint32 = 2 halves)
__device__ __align__(16) uint32_t g_Bf[32768];

__device__ __forceinline__ uint32_t smem_u32(const void* p) {
    uint32_t a;
    asm("{ .reg .u64 t; cvta.to.shared.u64 t, %1; cvt.u32.u64 %0, t; }"
        : "=r"(a) : "l"(p));
    return a;
}
__device__ __forceinline__ void ldsm4(uint32_t addr, uint32_t& r0, uint32_t& r1,
                                      uint32_t& r2, uint32_t& r3) {
    asm volatile("ldmatrix.sync.aligned.m8n8.x4.shared.b16 {%0,%1,%2,%3}, [%4];"
                 : "=r"(r0), "=r"(r1), "=r"(r2), "=r"(r3) : "r"(addr));
}
__device__ __forceinline__ void mma16816(float* c, uint32_t a0, uint32_t a1,
                                         uint32_t a2, uint32_t a3,
                                         uint32_t b0, uint32_t b1) {
    asm volatile("mma.sync.aligned.m16n8k16.row.col.f32.f16.f16.f32 "
                 "{%0,%1,%2,%3},{%4,%5,%6,%7},{%8,%9},{%0,%1,%2,%3};"
                 : "+f"(c[0]), "+f"(c[1]), "+f"(c[2]), "+f"(c[3])
                 : "r"(a0), "r"(a1), "r"(a2), "r"(a3), "r"(b0), "r"(b1));
}

__global__ void prep_weights(const float* __restrict__ wq,
                             const float* __restrict__ wk,
                             const float* __restrict__ wv,
                             const float* __restrict__ mlp) {
    int i = blockIdx.x * 256 + threadIdx.x;           // 0..65535
    if (i < DMEM * DMEM) {
        int ch = i >> 7, k = i & 127;
        g_wqT[k * 128 + ch]  = wq[i];
        g_mlpT[k * 128 + ch] = mlp[i];
    }
    if (i < 32768) {
        int b  = i & 1;
        int nt = (i >> 1) & 7;
        int l  = (i >> 4) & 31;
        int ks = (i >> 9) & 15;
        int cb = (i >> 13) & 3;
        int o  = cb * 64 + nt * 8 + (l >> 2);
        int k0 = ks * 16 + b * 8 + (l & 3) * 2;
        float w0 = (o < 128) ? wk[o * 256 + k0]     : wv[(o - 128) * 256 + k0];
        float w1 = (o < 128) ? wk[o * 256 + k0 + 1] : wv[(o - 128) * 256 + k0 + 1];
        __half2 h = __halves2half2(__float2half_rn(w0), __float2half_rn(w1));
        g_Bf[i] = *(uint32_t*)&h;
    }
}

__global__ __launch_bounds__(NTHR, 2)
void attn_mma_kernel(
    const int*   __restrict__ nodes,
    const float* __restrict__ times,
    const float* __restrict__ mem,
    const float* __restrict__ mail,
    const float* __restrict__ mail_time,
    const float* __restrict__ time_w,
    const float* __restrict__ time_b,
    const float* __restrict__ wq_b,
    const float* __restrict__ wk_b,
    const float* __restrict__ wv_b,
    const float* __restrict__ mlp_b,
    const float* __restrict__ ln_g,
    const float* __restrict__ ln_b,
    float*       __restrict__ out,
    int size)
{
    extern __shared__ __align__(1024) char smem[];
    const uint32_t sb = smem_u32(smem);
    const int tid = threadIdx.x, warp = tid >> 5, lane = tid & 31;
    const int base = blockIdx.x * NPB;

    int*   s_node = (int*)(smem + OFF_NODE);
    float* s_time = (float*)(smem + OFF_TIME);
    float* s_bk   = (float*)(smem + OFF_BK);
    float* s_bv   = (float*)(smem + OFF_BV);
    float* s_att  = (float*)(smem + OFF_ATT);
    float* s_dt   = (float*)(smem + OFF_DT);
    float* s_memf = (float*)(smem + OFF_MEM);
    float* s_q    = (float*)(smem + OFF_Q);        // stride 132
    float* s_out  = (float*)(smem + OFF_OUT);

    if (tid < NPB) {
        int g = base + tid; if (g >= size) g = size - 1;
        s_node[tid] = nodes[g];
        s_time[tid] = times[g];
    }
    if (tid >= 128) { int c = tid - 128; s_bk[c] = wk_b[c]; s_bv[c] = wv_b[c]; }
    __syncthreads();

    // dt per row (64 gathered scalars)
    if (tid < ROWS) {
        int n = tid >> 3, slot = tid & 7;
        s_dt[tid] = s_time[n] - __ldg(mail_time + (size_t)s_node[n] * MAIL + slot);
    }

    // gather mem rows [8][128]
    {
        float4* d4 = (float4*)s_memf;
        #pragma unroll
        for (int t = 0; t < 1; t++) {
            int i = tid;                            // 256 float4 = exactly NTHR
            int n = i >> 5, c4 = i & 31;
            d4[i] = *(const float4*)(mem + (size_t)s_node[n] * DMEM + c4 * 4);
        }
    }

    // mail half of A: batched float4 loads (8 per thread)
    #pragma unroll
    for (int t = 0; t < 8; t++) {
        int i = tid + t * NTHR;                     // 0..2047
        int r = i >> 5, c4 = (i & 31) * 4;
        int n = r >> 3, slot = r & 7;
        float4 mv = *(const float4*)(mail + ((size_t)s_node[n] * MAIL + slot) * 128 + c4);
        __half2* dst = (__half2*)(smem + OFF_A + ((size_t)r * AH + c4) * 2);
        dst[0] = __halves2half2(__float2half_rn(mv.x), __float2half_rn(mv.y));
        dst[1] = __halves2half2(__float2half_rn(mv.z), __float2half_rn(mv.w));
    }
    __syncthreads();                                // s_dt ready

    // time-encode half of A (MUFU cos), 16 per thread
    #pragma unroll
    for (int t = 0; t < 16; t++) {
        int i = tid + t * NTHR;                     // 0..4095
        int r = i >> 6, j = (i & 63) * 2;
        float dt = s_dt[r];
        float v0 = __cosf(fmaf(dt, __ldg(time_w + j),     __ldg(time_b + j)));
        float v1 = __cosf(fmaf(dt, __ldg(time_w + j + 1), __ldg(time_b + j + 1)));
        *(__half2*)(smem + OFF_A + ((size_t)r * AH + 128 + j) * 2) =
            __halves2half2(__float2half_rn(v0), __float2half_rn(v1));
    }
    __syncthreads();                                // A + mem ready

    // Q = mem @ wqT + b (fp32); 4 nodes per thread
    {
        int ch = tid & 127, ng = tid >> 7;
        float a0 = __ldg(wq_b + ch), a1 = a0, a2 = a0, a3 = a0;
        const float* m0p = s_memf + (ng * 4 + 0) * 128;
        const float* m1p = s_memf + (ng * 4 + 1) * 128;
        const float* m2p = s_memf + (ng * 4 + 2) * 128;
        const float* m3p = s_memf + (ng * 4 + 3) * 128;
        #pragma unroll 4
        for (int kk = 0; kk < 128; kk += 4) {
            float w0 = __ldg(g_wqT + (kk + 0) * 128 + ch);
            float w1 = __ldg(g_wqT + (kk + 1) * 128 + ch);
            float w2 = __ldg(g_wqT + (kk + 2) * 128 + ch);
            float w3 = __ldg(g_wqT + (kk + 3) * 128 + ch);
            float4 x0 = *(const float4*)(m0p + kk);
            float4 x1 = *(const float4*)(m1p + kk);
            float4 x2 = *(const float4*)(m2p + kk);
            float4 x3 = *(const float4*)(m3p + kk);
            a0 = fmaf(x0.x, w0, fmaf(x0.y, w1, fmaf(x0.z, w2, fmaf(x0.w, w3, a0))));
            a1 = fmaf(x1.x, w0, fmaf(x1.y, w1, fmaf(x1.z, w2, fmaf(x1.w, w3, a1))));
            a2 = fmaf(x2.x, w0, fmaf(x2.y, w1, fmaf(x2.z, w2, fmaf(x2.w, w3, a2))));
            a3 = fmaf(x3.x, w0, fmaf(x3.y, w1, fmaf(x3.z, w2, fmaf(x3.w, w3, a3))));
        }
        s_q[(ng * 4 + 0) * 132 + ch] = a0;
        s_q[(ng * 4 + 1) * 132 + ch] = a1;
        s_q[(ng * 4 + 2) * 132 + ch] = a2;
        s_q[(ng * 4 + 3) * 132 + ch] = a3;
    }
    __syncthreads();                                // s_q ready

    // ---- GEMM: C[64x256] = A x B^T, B fragments streamed from global ----
    const int rb = warp >> 2, cb = warp & 3;
    const int m0 = rb * 32;
    const int g8 = lane >> 3, lr = lane & 7;
    const int a_row = m0 + lr + ((g8 & 1) << 3);
    const int a_koff = (g8 >> 1) << 3;
    const uint32_t aB = sb + OFF_A + ((uint32_t)a_row * AH + a_koff) * 2;
    const uint4* bfp = (const uint4*)g_Bf + ((uint32_t)(cb * 16) * 32 + lane) * 4;

    float acc[2][8][4];
    #pragma unroll
    for (int rh = 0; rh < 2; rh++)
        #pragma unroll
        for (int t = 0; t < 8; t++)
            #pragma unroll
            for (int u = 0; u < 4; u++) acc[rh][t][u] = 0.f;

    #pragma unroll 4
    for (int ks = 0; ks < 16; ks++) {
        uint4 q0 = __ldg(bfp + 0);
        uint4 q1 = __ldg(bfp + 1);
        uint4 q2 = __ldg(bfp + 2);
        uint4 q3 = __ldg(bfp + 3);
        bfp += 128;                                 // 32 lanes * 4 uint4
        uint32_t a0, a1, a2, a3, a4, a5, a6, a7;
        ldsm4(aB + ((uint32_t)ks * 16) * 2,            a0, a1, a2, a3);
        ldsm4(aB + ((uint32_t)(16 * AH + ks * 16)) * 2, a4, a5, a6, a7);
        mma16816(acc[0][0], a0, a1, a2, a3, q0.x, q0.y);
        mma16816(acc[0][1], a0, a1, a2, a3, q0.z, q0.w);
        mma16816(acc[0][2], a0, a1, a2, a3, q1.x, q1.y);
        mma16816(acc[0][3], a0, a1, a2, a3, q1.z, q1.w);
        mma16816(acc[0][4], a0, a1, a2, a3, q2.x, q2.y);
        mma16816(acc[0][5], a0, a1, a2, a3, q2.z, q2.w);
        mma16816(acc[0][6], a0, a1, a2, a3, q3.x, q3.y);
        mma16816(acc[0][7], a0, a1, a2, a3, q3.z, q3.w);
        mma16816(acc[1][0], a4, a5, a6, a7, q0.x, q0.y);
        mma16816(acc[1][1], a4, a5, a6, a7, q0.z, q0.w);
        mma16816(acc[1][2], a4, a5, a6, a7, q1.x, q1.y);
        mma16816(acc[1][3], a4, a5, a6, a7, q1.z, q1.w);
        mma16816(acc[1][4], a4, a5, a6, a7, q2.x, q2.y);
        mma16816(acc[1][5], a4, a5, a6, a7, q2.z, q2.w);
        mma16816(acc[1][6], a4, a5, a6, a7, q3.x, q3.y);
        mma16816(acc[1][7], a4, a5, a6, a7, q3.z, q3.w);
    }

    const int cw = 2 * (lane & 3);
    const int e  = lane >> 2;

    // ---- logits (K warps: cb 0,1), head = cb ----
    if (cb < 2) {
        float p[4] = {0.f, 0.f, 0.f, 0.f};
        #pragma unroll
        for (int rh = 0; rh < 2; rh++)
            #pragma unroll
            for (int nt = 0; nt < 8; nt++)
                #pragma unroll
                for (int u = 0; u < 4; u++) {
                    int col = cb * 64 + cw + nt * 8 + (u & 1);
                    int ni = rh * 2 + (u >> 1);
                    p[ni] = fmaf(acc[rh][nt][u] + s_bk[col],
                                 s_q[(4 * rb + ni) * 132 + col], p[ni]);
                }
        #pragma unroll
        for (int ni = 0; ni < 4; ni++) {
            p[ni] += __shfl_xor_sync(0xffffffffu, p[ni], 1);
            p[ni] += __shfl_xor_sync(0xffffffffu, p[ni], 2);
        }
        if ((lane & 3) == 0) {
            #pragma unroll
            for (int ni = 0; ni < 4; ni++) {
                float v = p[ni];
                v = (v >= 0.f) ? v : 0.2f * v;
                s_att[((4 * rb + ni) * 8 + e) * 2 + cb] = v;
            }
        }
    }
    __syncthreads();

    if (tid < NPB * 2) {                            // softmax over slots
        int n = tid >> 1, h = tid & 1;
        float mx = -1e30f;
        #pragma unroll
        for (int s = 0; s < MAIL; s++) mx = fmaxf(mx, s_att[(n * 8 + s) * 2 + h]);
        float ex[MAIL], sum = 0.f;
        #pragma unroll
        for (int s = 0; s < MAIL; s++) { ex[s] = __expf(s_att[(n * 8 + s) * 2 + h] - mx); sum += ex[s]; }
        float inv = 1.f / sum;
        #pragma unroll
        for (int s = 0; s < MAIL; s++) s_att[(n * 8 + s) * 2 + h] = ex[s] * inv;
    }
    __syncthreads();

    // ---- V slot-sum (V warps: cb 2,3), head = cb-2 ----
    if (cb >= 2) {
        const int head = cb - 2;
        float v[2][8][4];
        #pragma unroll
        for (int rh = 0; rh < 2; rh++) {
            float attA = s_att[((4 * rb + 2 * rh + 0) * 8 + e) * 2 + head];
            float attB = s_att[((4 * rb + 2 * rh + 1) * 8 + e) * 2 + head];
            #pragma unroll
            for (int nt = 0; nt < 8; nt++) {
                v[rh][nt][0] = acc[rh][nt][0] * attA;
                v[rh][nt][1] = acc[rh][nt][1] * attA;
                v[rh][nt][2] = acc[rh][nt][2] * attB;
                v[rh][nt][3] = acc[rh][nt][3] * attB;
            }
        }
        #pragma unroll
        for (int rh = 0; rh < 2; rh++)
            #pragma unroll
            for (int nt = 0; nt < 8; nt++)
                #pragma unroll
                for (int u = 0; u < 4; u++) {
                    float x = v[rh][nt][u];
                    x += __shfl_xor_sync(0xffffffffu, x, 4);
                    x += __shfl_xor_sync(0xffffffffu, x, 8);
                    x += __shfl_xor_sync(0xffffffffu, x, 16);
                    v[rh][nt][u] = x;
                }
        if (e == 0) {
            #pragma unroll
            for (int rh = 0; rh < 2; rh++)
                #pragma unroll
                for (int nt = 0; nt < 8; nt++)
                    #pragma unroll
                    for (int u = 0; u < 4; u++) {
                        int node = 4 * rb + 2 * rh + (u >> 1);
                        int ch = head * 64 + cw + nt * 8 + (u & 1);
                        s_out[node * 128 + ch] =
                            v[rh][nt][u] + s_bv[ch] + s_memf[node * 128 + ch];
                    }
        }
    }
    __syncthreads();

    // ---- LayerNorm: warp n -> node n ----
    {
        int n = warp;
        float4 x4 = ((float4*)(s_out + n * 128))[lane];
        float sum = x4.x + x4.y + x4.z + x4.w;
        float sq  = fmaf(x4.x, x4.x, fmaf(x4.y, x4.y, fmaf(x4.z, x4.z, x4.w * x4.w)));
        #pragma unroll
        for (int off = 16; off; off >>= 1) {
            sum += __shfl_xor_sync(0xffffffffu, sum, off);
            sq  += __shfl_xor_sync(0xffffffffu, sq, off);
        }
        float mu = sum * (1.f / 128.f);
        float rstd = rsqrtf(sq * (1.f / 128.f) - mu * mu + 1e-5f);
        float o[4] = {x4.x, x4.y, x4.z, x4.w};
        #pragma unroll
        for (int u = 0; u < 4; u++) {
            int cc = lane * 4 + u;
            s_out[n * 128 + cc] = (o[u] - mu) * rstd * __ldg(ln_g + cc) + __ldg(ln_b + cc);
        }
    }
    __syncthreads();

    // ---- MLP + ReLU: 4 nodes per thread ----
    {
        int ch = tid & 127, ng = tid >> 7;
        float a0 = __ldg(mlp_b + ch), a1 = a0, a2 = a0, a3 = a0;
        const float* o0 = s_out + (ng * 4 + 0) * 128;
        const float* o1 = s_out + (ng * 4 + 1) * 128;
        const float* o2 = s_out + (ng * 4 + 2) * 128;
        const float* o3 = s_out + (ng * 4 + 3) * 128;
        #pragma unroll 4
        for (int kk = 0; kk < 128; kk += 4) {
            float w0 = __ldg(g_mlpT + (kk + 0) * 128 + ch);
            float w1 = __ldg(g_mlpT + (kk + 1) * 128 + ch);
            float w2 = __ldg(g_mlpT + (kk + 2) * 128 + ch);
            float w3 = __ldg(g_mlpT + (kk + 3) * 128 + ch);
            float4 x0 = *(const float4*)(o0 + kk);
            float4 x1 = *(const float4*)(o1 + kk);
            float4 x2 = *(const float4*)(o2 + kk);
            float4 x3 = *(const float4*)(o3 + kk);
            a0 = fmaf(x0.x, w0, fmaf(x0.y, w1, fmaf(x0.z, w2, fmaf(x0.w, w3, a0))));
            a1 = fmaf(x1.x, w0, fmaf(x1.y, w1, fmaf(x1.z, w2, fmaf(x1.w, w3, a1))));
            a2 = fmaf(x2.x, w0, fmaf(x2.y, w1, fmaf(x2.z, w2, fmaf(x2.w, w3, a2))));
            a3 = fmaf(x3.x, w0, fmaf(x3.y, w1, fmaf(x3.z, w2, fmaf(x3.w, w3, a3))));
        }
        float r[4] = {a0, a1, a2, a3};
        #pragma unroll
        for (int nn = 0; nn < 4; nn++) {
            int g = base + ng * 4 + nn;
            if (g < size) out[(size_t)g * 128 + ch] = fmaxf(r[nn], 0.f);
        }
    }
}

extern "C" void kernel_launch(void* const* d_in, const int* in_sizes, int n_in,
                              void* d_out, int out_size) {
    const int*   nodes     = (const int*)  d_in[0];
    const float* times     = (const float*)d_in[1];
    const float* mem       = (const float*)d_in[2];
    const float* mail      = (const float*)d_in[3];
    const float* mail_time = (const float*)d_in[4];
    const float* time_w    = (const float*)d_in[5];
    const float* time_b    = (const float*)d_in[6];
    const float* wq_w      = (const float*)d_in[7];
    const float* wq_b      = (const float*)d_in[8];
    const float* wk_w      = (const float*)d_in[9];
    const float* wk_b      = (const float*)d_in[10];
    const float* wv_w      = (const float*)d_in[11];
    const float* wv_b      = (const float*)d_in[12];
    const float* mlp_w     = (const float*)d_in[13];
    const float* mlp_b     = (const float*)d_in[14];
    const float* ln_g      = (const float*)d_in[15];
    const float* ln_b      = (const float*)d_in[16];
    int size = in_sizes[0];

    cudaFuncSetAttribute(attn_mma_kernel,
                         cudaFuncAttributeMaxDynamicSharedMemorySize, SMEM_TOTAL);

    prep_weights<<<256, 256>>>(wq_w, wk_w, wv_w, mlp_w);

    int nblk = (size + NPB - 1) / NPB;
    attn_mma_kernel<<<nblk, NTHR, SMEM_TOTAL>>>(
        nodes, times, mem, mail, mail_time, time_w, time_b,
        wq_b, wk_b, wv_b, mlp_b, ln_g, ln_b,
        (float*)d_out, size);
}

// round 6
// speedup vs baseline: 4.9514x; 1.2181x over previous
#include <cuda_runtime.h>
#include <cuda_fp16.h>
#include <cstdint>
#include <math.h>

#define MAIL   8
#define DMEM   128
#define DCAT   256
#define NPB    8
#define ROWS   64
#define NTHR   256

#define AH 264             // A row stride in halves (256 + 8)
#define QH 132             // mem/mlp-in hi/lo row stride in halves

// ---- smem byte offsets ----
#define OFF_NODE 0
#define OFF_TIME 32
#define OFF_BK   64
#define OFF_BV   576
#define OFF_ATT  1088
#define OFF_DT   1600
#define OFF_MEM  1856                      // 8 x 128 f32 -> ends 5952
#define OFF_Q    5952                      // 8 x 132 f32 (s_out overlays)
#define OFF_OUT  5952
#define OFF_MH   10176                     // 16 x 132 halves (hi)
#define OFF_ML   14400                     // 16 x 132 halves (lo)
#define OFF_A    18624                     // 64 x 264 halves = 33792
#define SMEM_TOTAL 52416

// K/V weights in mma B-frag order (R5 layout), padded for prefetch safety
__device__ __align__(16) uint32_t g_Bf[32768 + 2048];
// Wq / mlp_w as hi/lo B-frags: idx=((((w*8+ks)*2+nt)*2+p)*32+lane)*2+breg
__device__ __align__(16) uint32_t g_WqF[16384];
__device__ __align__(16) uint32_t g_MlF[16384];

__device__ __forceinline__ uint32_t smem_u32(const void* p) {
    uint32_t a;
    asm("{ .reg .u64 t; cvta.to.shared.u64 t, %1; cvt.u32.u64 %0, t; }"
        : "=r"(a) : "l"(p));
    return a;
}
__device__ __forceinline__ void ldsm4(uint32_t addr, uint32_t& r0, uint32_t& r1,
                                      uint32_t& r2, uint32_t& r3) {
    asm volatile("ldmatrix.sync.aligned.m8n8.x4.shared.b16 {%0,%1,%2,%3}, [%4];"
                 : "=r"(r0), "=r"(r1), "=r"(r2), "=r"(r3) : "r"(addr));
}
__device__ __forceinline__ void mma16816(float* c, uint32_t a0, uint32_t a1,
                                         uint32_t a2, uint32_t a3,
                                         uint32_t b0, uint32_t b1) {
    asm volatile("mma.sync.aligned.m16n8k16.row.col.f32.f16.f16.f32 "
                 "{%0,%1,%2,%3},{%4,%5,%6,%7},{%8,%9},{%0,%1,%2,%3};"
                 : "+f"(c[0]), "+f"(c[1]), "+f"(c[2]), "+f"(c[3])
                 : "r"(a0), "r"(a1), "r"(a2), "r"(a3), "r"(b0), "r"(b1));
}
__device__ __forceinline__ uint32_t pack_h2(float x, float y) {
    __half2 h = __halves2half2(__float2half_rn(x), __float2half_rn(y));
    return *(uint32_t*)&h;
}

__global__ void prep_weights(const float* __restrict__ wq,
                             const float* __restrict__ wk,
                             const float* __restrict__ wv,
                             const float* __restrict__ mlp) {
    int i = blockIdx.x * 256 + threadIdx.x;           // 0..65535
    if (i < 32768) {
        int b  = i & 1;
        int nt = (i >> 1) & 7;
        int l  = (i >> 4) & 31;
        int ks = (i >> 9) & 15;
        int cb = (i >> 13) & 3;
        int o  = cb * 64 + nt * 8 + (l >> 2);
        int k0 = ks * 16 + b * 8 + (l & 3) * 2;
        float w0 = (o < 128) ? wk[o * 256 + k0]     : wv[(o - 128) * 256 + k0];
        float w1 = (o < 128) ? wk[o * 256 + k0 + 1] : wv[(o - 128) * 256 + k0 + 1];
        g_Bf[i] = pack_h2(w0, w1);
    } else {
        int j = i - 32768;
        const float* W = (j < 16384) ? wq : mlp;
        int jj = j & 16383;
        int breg = jj & 1, l = (jj >> 1) & 31, p = (jj >> 6) & 1;
        int nt = (jj >> 7) & 1, ks = (jj >> 8) & 7, w = (jj >> 11) & 7;
        int col = w * 16 + nt * 8 + (l >> 2);
        int k0  = ks * 16 + breg * 8 + (l & 3) * 2;
        float w0 = W[col * 128 + k0], w1 = W[col * 128 + k0 + 1];
        uint32_t v;
        if (p == 0) v = pack_h2(w0, w1);
        else {
            float l0 = w0 - __half2float(__float2half_rn(w0));
            float l1 = w1 - __half2float(__float2half_rn(w1));
            v = pack_h2(l0, l1);
        }
        if (j < 16384) g_WqF[jj] = v; else g_MlF[jj] = v;
    }
}

__global__ __launch_bounds__(NTHR, 2)
void attn_mma_kernel(
    const int*   __restrict__ nodes,
    const float* __restrict__ times,
    const float* __restrict__ mem,
    const float* __restrict__ mail,
    const float* __restrict__ mail_time,
    const float* __restrict__ time_w,
    const float* __restrict__ time_b,
    const float* __restrict__ wq_b,
    const float* __restrict__ wk_b,
    const float* __restrict__ wv_b,
    const float* __restrict__ mlp_b,
    const float* __restrict__ ln_g,
    const float* __restrict__ ln_b,
    float*       __restrict__ out,
    int size)
{
    extern __shared__ __align__(1024) char smem[];
    const uint32_t sb = smem_u32(smem);
    const int tid = threadIdx.x, warp = tid >> 5, lane = tid & 31;
    const int base = blockIdx.x * NPB;

    int*   s_node = (int*)(smem + OFF_NODE);
    float* s_time = (float*)(smem + OFF_TIME);
    float* s_bk   = (float*)(smem + OFF_BK);
    float* s_bv   = (float*)(smem + OFF_BV);
    float* s_att  = (float*)(smem + OFF_ATT);
    float* s_dt   = (float*)(smem + OFF_DT);
    float* s_memf = (float*)(smem + OFF_MEM);
    float* s_q    = (float*)(smem + OFF_Q);        // stride 132
    float* s_out  = (float*)(smem + OFF_OUT);

    if (tid < NPB) {
        int g = base + tid; if (g >= size) g = size - 1;
        s_node[tid] = nodes[g];
        s_time[tid] = times[g];
    }
    if (tid >= 128) { int c = tid - 128; s_bk[c] = wk_b[c]; s_bv[c] = wv_b[c]; }
    __syncthreads();

    if (tid < ROWS) {
        int n = tid >> 3, slot = tid & 7;
        s_dt[tid] = s_time[n] - __ldg(mail_time + (size_t)s_node[n] * MAIL + slot);
    }

    // gather mem rows + build hi/lo fp16 copy (rows 0-7)
    {
        int n = tid >> 5, c4 = (tid & 31) * 4;
        float4 v = *(const float4*)(mem + (size_t)s_node[n] * DMEM + c4);
        ((float4*)s_memf)[tid] = v;
        uint32_t h0 = pack_h2(v.x, v.y), h1 = pack_h2(v.z, v.w);
        float lx = v.x - __half2float(__float2half_rn(v.x));
        float ly = v.y - __half2float(__float2half_rn(v.y));
        float lz = v.z - __half2float(__float2half_rn(v.z));
        float lw = v.w - __half2float(__float2half_rn(v.w));
        uint32_t l0 = pack_h2(lx, ly), l1 = pack_h2(lz, lw);
        uint32_t off = (uint32_t)(n * QH + c4) * 2;
        *(uint32_t*)(smem + OFF_MH + off)     = h0;
        *(uint32_t*)(smem + OFF_MH + off + 4) = h1;
        *(uint32_t*)(smem + OFF_ML + off)     = l0;
        *(uint32_t*)(smem + OFF_ML + off + 4) = l1;
    }
    // zero pad rows 8-15 of hi/lo buffers
    for (int i = tid; i < 8 * QH / 2; i += NTHR) {
        int r = 8 + i / (QH / 2), c = (i % (QH / 2)) * 2;
        *(uint32_t*)(smem + OFF_MH + (uint32_t)(r * QH + c) * 2) = 0u;
        *(uint32_t*)(smem + OFF_ML + (uint32_t)(r * QH + c) * 2) = 0u;
    }

    // mail half of A (fp16)
    #pragma unroll
    for (int t = 0; t < 8; t++) {
        int i = tid + t * NTHR;
        int r = i >> 5, c4 = (i & 31) * 4;
        int n = r >> 3, slot = r & 7;
        float4 mv = *(const float4*)(mail + ((size_t)s_node[n] * MAIL + slot) * 128 + c4);
        uint32_t* dst = (uint32_t*)(smem + OFF_A + ((size_t)r * AH + c4) * 2);
        dst[0] = pack_h2(mv.x, mv.y);
        dst[1] = pack_h2(mv.z, mv.w);
    }
    __syncthreads();                                // s_dt, mem_hl ready

    // time-encode half of A
    #pragma unroll
    for (int t = 0; t < 16; t++) {
        int i = tid + t * NTHR;
        int r = i >> 6, j = (i & 63) * 2;
        float dt = s_dt[r];
        float v0 = __cosf(fmaf(dt, __ldg(time_w + j),     __ldg(time_b + j)));
        float v1 = __cosf(fmaf(dt, __ldg(time_w + j + 1), __ldg(time_b + j + 1)));
        *(uint32_t*)(smem + OFF_A + ((size_t)r * AH + 128 + j) * 2) = pack_h2(v0, v1);
    }

    // ---- Q via MMA (hi/lo exact): warp w -> cols [w*16, w*16+16) ----
    {
        const int r = lane >> 2, cpos = 2 * (lane & 3);
        float qa0[4] = {0.f, 0.f, 0.f, 0.f}, qa1[4] = {0.f, 0.f, 0.f, 0.f};
        const uint2* wf = (const uint2*)g_WqF + (uint32_t)(warp * 8) * 128 + lane;
        #pragma unroll
        for (int ks = 0; ks < 8; ks++) {
            uint32_t abase = sb + OFF_MH + (uint32_t)(r * QH + ks * 16 + cpos) * 2;
            uint32_t lbase = abase + (OFF_ML - OFF_MH);
            uint32_t ah0 = *(uint32_t*)(smem + (abase - sb));
            uint32_t ah1 = *(uint32_t*)(smem + (abase - sb) + 8 * QH * 2);
            uint32_t ah2 = *(uint32_t*)(smem + (abase - sb) + 16);
            uint32_t ah3 = *(uint32_t*)(smem + (abase - sb) + 8 * QH * 2 + 16);
            uint32_t al0 = *(uint32_t*)(smem + (lbase - sb));
            uint32_t al1 = *(uint32_t*)(smem + (lbase - sb) + 8 * QH * 2);
            uint32_t al2 = *(uint32_t*)(smem + (lbase - sb) + 16);
            uint32_t al3 = *(uint32_t*)(smem + (lbase - sb) + 8 * QH * 2 + 16);
            uint2 bh0 = __ldg(wf + ks * 128);
            uint2 bl0 = __ldg(wf + ks * 128 + 32);
            uint2 bh1 = __ldg(wf + ks * 128 + 64);
            uint2 bl1 = __ldg(wf + ks * 128 + 96);
            mma16816(qa0, ah0, ah1, ah2, ah3, bh0.x, bh0.y);
            mma16816(qa0, al0, al1, al2, al3, bh0.x, bh0.y);
            mma16816(qa0, ah0, ah1, ah2, ah3, bl0.x, bl0.y);
            mma16816(qa1, ah0, ah1, ah2, ah3, bh1.x, bh1.y);
            mma16816(qa1, al0, al1, al2, al3, bh1.x, bh1.y);
            mma16816(qa1, ah0, ah1, ah2, ah3, bl1.x, bl1.y);
        }
        int col = warp * 16 + cpos;
        s_q[r * QH + col]     = qa0[0] + __ldg(wq_b + col);
        s_q[r * QH + col + 1] = qa0[1] + __ldg(wq_b + col + 1);
        s_q[r * QH + col + 8] = qa1[0] + __ldg(wq_b + col + 8);
        s_q[r * QH + col + 9] = qa1[1] + __ldg(wq_b + col + 9);
    }
    __syncthreads();                                // A + s_q ready

    // ---- big GEMM: C[64x256] = A x [Wk|Wv]^T, B fragments from global ----
    const int rb = warp >> 2, cb = warp & 3;
    const int m0 = rb * 32;
    const int g8 = lane >> 3, lr = lane & 7;
    const int a_row = m0 + lr + ((g8 & 1) << 3);
    const int a_koff = (g8 >> 1) << 3;
    const uint32_t aB = sb + OFF_A + ((uint32_t)a_row * AH + a_koff) * 2;
    const uint4* bfp = (const uint4*)g_Bf + ((uint32_t)(cb * 16) * 32 + lane) * 4;

    float acc[2][8][4];
    #pragma unroll
    for (int rh = 0; rh < 2; rh++)
        #pragma unroll
        for (int t = 0; t < 8; t++)
            #pragma unroll
            for (int u = 0; u < 4; u++) acc[rh][t][u] = 0.f;

    #pragma unroll 4
    for (int ks = 0; ks < 16; ks++) {
        uint4 q0 = __ldg(bfp + 0);
        uint4 q1 = __ldg(bfp + 1);
        uint4 q2 = __ldg(bfp + 2);
        uint4 q3 = __ldg(bfp + 3);
        bfp += 128;
        uint32_t a0, a1, a2, a3, a4, a5, a6, a7;
        ldsm4(aB + ((uint32_t)ks * 16) * 2,             a0, a1, a2, a3);
        ldsm4(aB + ((uint32_t)(16 * AH + ks * 16)) * 2, a4, a5, a6, a7);
        mma16816(acc[0][0], a0, a1, a2, a3, q0.x, q0.y);
        mma16816(acc[0][1], a0, a1, a2, a3, q0.z, q0.w);
        mma16816(acc[0][2], a0, a1, a2, a3, q1.x, q1.y);
        mma16816(acc[0][3], a0, a1, a2, a3, q1.z, q1.w);
        mma16816(acc[0][4], a0, a1, a2, a3, q2.x, q2.y);
        mma16816(acc[0][5], a0, a1, a2, a3, q2.z, q2.w);
        mma16816(acc[0][6], a0, a1, a2, a3, q3.x, q3.y);
        mma16816(acc[0][7], a0, a1, a2, a3, q3.z, q3.w);
        mma16816(acc[1][0], a4, a5, a6, a7, q0.x, q0.y);
        mma16816(acc[1][1], a4, a5, a6, a7, q0.z, q0.w);
        mma16816(acc[1][2], a4, a5, a6, a7, q1.x, q1.y);
        mma16816(acc[1][3], a4, a5, a6, a7, q1.z, q1.w);
        mma16816(acc[1][4], a4, a5, a6, a7, q2.x, q2.y);
        mma16816(acc[1][5], a4, a5, a6, a7, q2.z, q2.w);
        mma16816(acc[1][6], a4, a5, a6, a7, q3.x, q3.y);
        mma16816(acc[1][7], a4, a5, a6, a7, q3.z, q3.w);
    }

    const int cw = 2 * (lane & 3);
    const int e  = lane >> 2;

    // ---- logits (K warps: cb 0,1), head = cb ----
    if (cb < 2) {
        float p[4] = {0.f, 0.f, 0.f, 0.f};
        #pragma unroll
        for (int rh = 0; rh < 2; rh++)
            #pragma unroll
            for (int nt = 0; nt < 8; nt++)
                #pragma unroll
                for (int u = 0; u < 4; u++) {
                    int col = cb * 64 + cw + nt * 8 + (u & 1);
                    int ni = rh * 2 + (u >> 1);
                    p[ni] = fmaf(acc[rh][nt][u] + s_bk[col],
                                 s_q[(4 * rb + ni) * QH + col], p[ni]);
                }
        #pragma unroll
        for (int ni = 0; ni < 4; ni++) {
            p[ni] += __shfl_xor_sync(0xffffffffu, p[ni], 1);
            p[ni] += __shfl_xor_sync(0xffffffffu, p[ni], 2);
        }
        if ((lane & 3) == 0) {
            #pragma unroll
            for (int ni = 0; ni < 4; ni++) {
                float v = p[ni];
                v = (v >= 0.f) ? v : 0.2f * v;
                s_att[((4 * rb + ni) * 8 + e) * 2 + cb] = v;
            }
        }
    }
    __syncthreads();

    if (tid < NPB * 2) {
        int n = tid >> 1, h = tid & 1;
        float mx = -1e30f;
        #pragma unroll
        for (int s = 0; s < MAIL; s++) mx = fmaxf(mx, s_att[(n * 8 + s) * 2 + h]);
        float ex[MAIL], sum = 0.f;
        #pragma unroll
        for (int s = 0; s < MAIL; s++) { ex[s] = __expf(s_att[(n * 8 + s) * 2 + h] - mx); sum += ex[s]; }
        float inv = 1.f / sum;
        #pragma unroll
        for (int s = 0; s < MAIL; s++) s_att[(n * 8 + s) * 2 + h] = ex[s] * inv;
    }
    __syncthreads();

    // ---- V slot-sum (V warps: cb 2,3), head = cb-2 ----
    if (cb >= 2) {
        const int head = cb - 2;
        float v[2][8][4];
        #pragma unroll
        for (int rh = 0; rh < 2; rh++) {
            float attA = s_att[((4 * rb + 2 * rh + 0) * 8 + e) * 2 + head];
            float attB = s_att[((4 * rb + 2 * rh + 1) * 8 + e) * 2 + head];
            #pragma unroll
            for (int nt = 0; nt < 8; nt++) {
                v[rh][nt][0] = acc[rh][nt][0] * attA;
                v[rh][nt][1] = acc[rh][nt][1] * attA;
                v[rh][nt][2] = acc[rh][nt][2] * attB;
                v[rh][nt][3] = acc[rh][nt][3] * attB;
            }
        }
        #pragma unroll
        for (int rh = 0; rh < 2; rh++)
            #pragma unroll
            for (int nt = 0; nt < 8; nt++)
                #pragma unroll
                for (int u = 0; u < 4; u++) {
                    float x = v[rh][nt][u];
                    x += __shfl_xor_sync(0xffffffffu, x, 4);
                    x += __shfl_xor_sync(0xffffffffu, x, 8);
                    x += __shfl_xor_sync(0xffffffffu, x, 16);
                    v[rh][nt][u] = x;
                }
        if (e == 0) {
            #pragma unroll
            for (int rh = 0; rh < 2; rh++)
                #pragma unroll
                for (int nt = 0; nt < 8; nt++)
                    #pragma unroll
                    for (int u = 0; u < 4; u++) {
                        int node = 4 * rb + 2 * rh + (u >> 1);
                        int ch = head * 64 + cw + nt * 8 + (u & 1);
                        s_out[node * 128 + ch] =
                            v[rh][nt][u] + s_bv[ch] + s_memf[node * 128 + ch];
                    }
        }
    }
    __syncthreads();

    // ---- LayerNorm: warp n -> node n; writes hi/lo fp16 for MLP-MMA ----
    {
        int n = warp;
        float4 x4 = ((float4*)(s_out + n * 128))[lane];
        float sum = x4.x + x4.y + x4.z + x4.w;
        float sq  = fmaf(x4.x, x4.x, fmaf(x4.y, x4.y, fmaf(x4.z, x4.z, x4.w * x4.w)));
        #pragma unroll
        for (int off = 16; off; off >>= 1) {
            sum += __shfl_xor_sync(0xffffffffu, sum, off);
            sq  += __shfl_xor_sync(0xffffffffu, sq, off);
        }
        float mu = sum * (1.f / 128.f);
        float rstd = rsqrtf(sq * (1.f / 128.f) - mu * mu + 1e-5f);
        float o[4] = {x4.x, x4.y, x4.z, x4.w};
        float y[4];
        #pragma unroll
        for (int u = 0; u < 4; u++) {
            int cc = lane * 4 + u;
            y[u] = (o[u] - mu) * rstd * __ldg(ln_g + cc) + __ldg(ln_b + cc);
        }
        uint32_t off0 = (uint32_t)(n * QH + lane * 4) * 2;
        *(uint32_t*)(smem + OFF_MH + off0)     = pack_h2(y[0], y[1]);
        *(uint32_t*)(smem + OFF_MH + off0 + 4) = pack_h2(y[2], y[3]);
        float l0 = y[0] - __half2float(__float2half_rn(y[0]));
        float l1 = y[1] - __half2float(__float2half_rn(y[1]));
        float l2 = y[2] - __half2float(__float2half_rn(y[2]));
        float l3 = y[3] - __half2float(__float2half_rn(y[3]));
        *(uint32_t*)(smem + OFF_ML + off0)     = pack_h2(l0, l1);
        *(uint32_t*)(smem + OFF_ML + off0 + 4) = pack_h2(l2, l3);
    }
    __syncthreads();

    // ---- MLP via MMA (hi/lo exact) + ReLU + store ----
    {
        const int r = lane >> 2, cpos = 2 * (lane & 3);
        float qa0[4] = {0.f, 0.f, 0.f, 0.f}, qa1[4] = {0.f, 0.f, 0.f, 0.f};
        const uint2* wf = (const uint2*)g_MlF + (uint32_t)(warp * 8) * 128 + lane;
        #pragma unroll
        for (int ks = 0; ks < 8; ks++) {
            uint32_t ab = (uint32_t)OFF_MH + (uint32_t)(r * QH + ks * 16 + cpos) * 2;
            uint32_t lb = ab + (OFF_ML - OFF_MH);
            uint32_t ah0 = *(uint32_t*)(smem + ab);
            uint32_t ah1 = *(uint32_t*)(smem + ab + 8 * QH * 2);
            uint32_t ah2 = *(uint32_t*)(smem + ab + 16);
            uint32_t ah3 = *(uint32_t*)(smem + ab + 8 * QH * 2 + 16);
            uint32_t al0 = *(uint32_t*)(smem + lb);
            uint32_t al1 = *(uint32_t*)(smem + lb + 8 * QH * 2);
            uint32_t al2 = *(uint32_t*)(smem + lb + 16);
            uint32_t al3 = *(uint32_t*)(smem + lb + 8 * QH * 2 + 16);
            uint2 bh0 = __ldg(wf + ks * 128);
            uint2 bl0 = __ldg(wf + ks * 128 + 32);
            uint2 bh1 = __ldg(wf + ks * 128 + 64);
            uint2 bl1 = __ldg(wf + ks * 128 + 96);
            mma16816(qa0, ah0, ah1, ah2, ah3, bh0.x, bh0.y);
            mma16816(qa0, al0, al1, al2, al3, bh0.x, bh0.y);
            mma16816(qa0, ah0, ah1, ah2, ah3, bl0.x, bl0.y);
            mma16816(qa1, ah0, ah1, ah2, ah3, bh1.x, bh1.y);
            mma16816(qa1, al0, al1, al2, al3, bh1.x, bh1.y);
            mma16816(qa1, ah0, ah1, ah2, ah3, bl1.x, bl1.y);
        }
        int col = warp * 16 + cpos;
        int g = base + r;
        if (g < size) {
            float2 v0, v1;
            v0.x = fmaxf(qa0[0] + __ldg(mlp_b + col),     0.f);
            v0.y = fmaxf(qa0[1] + __ldg(mlp_b + col + 1), 0.f);
            v1.x = fmaxf(qa1[0] + __ldg(mlp_b + col + 8), 0.f);
            v1.y = fmaxf(qa1[1] + __ldg(mlp_b + col + 9), 0.f);
            *(float2*)(out + (size_t)g * 128 + col)     = v0;
            *(float2*)(out + (size_t)g * 128 + col + 8) = v1;
        }
    }
}

extern "C" void kernel_launch(void* const* d_in, const int* in_sizes, int n_in,
                              void* d_out, int out_size) {
    const int*   nodes     = (const int*)  d_in[0];
    const float* times     = (const float*)d_in[1];
    const float* mem       = (const float*)d_in[2];
    const float* mail      = (const float*)d_in[3];
    const float* mail_time = (const float*)d_in[4];
    const float* time_w    = (const float*)d_in[5];
    const float* time_b    = (const float*)d_in[6];
    const float* wq_w      = (const float*)d_in[7];
    const float* wq_b      = (const float*)d_in[8];
    const float* wk_w      = (const float*)d_in[9];
    const float* wk_b      = (const float*)d_in[10];
    const float* wv_w      = (const float*)d_in[11];
    const float* wv_b      = (const float*)d_in[12];
    const float* mlp_w     = (const float*)d_in[13];
    const float* mlp_b     = (const float*)d_in[14];
    const float* ln_g      = (const float*)d_in[15];
    const float* ln_b      = (const float*)d_in[16];
    int size = in_sizes[0];

    cudaFuncSetAttribute(attn_mma_kernel,
                         cudaFuncAttributeMaxDynamicSharedMemorySize, SMEM_TOTAL);

    prep_weights<<<256, 256>>>(wq_w, wk_w, wv_w, mlp_w);

    int nblk = (size + NPB - 1) / NPB;
    attn_mma_kernel<<<nblk, NTHR, SMEM_TOTAL>>>(
        nodes, times, mem, mail, mail_time, time_w, time_b,
        wq_b, wk_b, wv_b, mlp_b, ln_g, ln_b,
        (float*)d_out, size);
}

// round 7
// speedup vs baseline: 5.1395x; 1.0380x over previous
#include <cuda_runtime.h>
#include <cuda_fp16.h>
#include <cstdint>
#include <math.h>

#define MAIL   8
#define DMEM   128
#define DCAT   256
#define NPB    8
#define ROWS   64
#define NTHR   256

#define AH 264             // A row stride in halves (132 words == 4 mod 32)
#define MHH 136            // MH/ML row stride in halves (68 words == 4 mod 32)
#define QF 132             // s_q float row stride

// ---- smem byte offsets ----
#define OFF_NODE 0
#define OFF_TIME 32
#define OFF_BK   64
#define OFF_BV   576
#define OFF_ATT  1088
#define OFF_DT   1600
#define OFF_MEM  1856                      // 8 x 128 f32 -> 5952
#define OFF_Q    5952                      // 8 x 132 f32 (s_out overlays) -> 10176
#define OFF_OUT  5952
#define OFF_MH   10176                     // 16 x 136 halves = 4352 -> 14528
#define OFF_ML   14528                     // 4352 -> 18880
#define OFF_A    18880                     // 64 x 264 halves = 33792
#define SMEM_TOTAL 52672

// K/V weights in mma B-frag order
__device__ __align__(16) uint32_t g_Bf[32768 + 2048];
// Wq / mlp_w as hi/lo B-frags: idx=((((w*8+ks)*2+nt)*2+p)*32+lane)*2+breg
__device__ __align__(16) uint32_t g_WqF[16384];
__device__ __align__(16) uint32_t g_MlF[16384];

__device__ __forceinline__ uint32_t smem_u32(const void* p) {
    uint32_t a;
    asm("{ .reg .u64 t; cvta.to.shared.u64 t, %1; cvt.u32.u64 %0, t; }"
        : "=r"(a) : "l"(p));
    return a;
}
__device__ __forceinline__ void ldsm4(uint32_t addr, uint32_t& r0, uint32_t& r1,
                                      uint32_t& r2, uint32_t& r3) {
    asm volatile("ldmatrix.sync.aligned.m8n8.x4.shared.b16 {%0,%1,%2,%3}, [%4];"
                 : "=r"(r0), "=r"(r1), "=r"(r2), "=r"(r3) : "r"(addr));
}
__device__ __forceinline__ void mma16816(float* c, uint32_t a0, uint32_t a1,
                                         uint32_t a2, uint32_t a3,
                                         uint32_t b0, uint32_t b1) {
    asm volatile("mma.sync.aligned.m16n8k16.row.col.f32.f16.f16.f32 "
                 "{%0,%1,%2,%3},{%4,%5,%6,%7},{%8,%9},{%0,%1,%2,%3};"
                 : "+f"(c[0]), "+f"(c[1]), "+f"(c[2]), "+f"(c[3])
                 : "r"(a0), "r"(a1), "r"(a2), "r"(a3), "r"(b0), "r"(b1));
}
__device__ __forceinline__ uint32_t pack_h2(float x, float y) {
    __half2 h = __halves2half2(__float2half_rn(x), __float2half_rn(y));
    return *(uint32_t*)&h;
}

__global__ void prep_weights(const float* __restrict__ wq,
                             const float* __restrict__ wk,
                             const float* __restrict__ wv,
                             const float* __restrict__ mlp) {
    int i = blockIdx.x * 256 + threadIdx.x;           // 0..65535
    if (i < 32768) {
        int b  = i & 1;
        int nt = (i >> 1) & 7;
        int l  = (i >> 4) & 31;
        int ks = (i >> 9) & 15;
        int cb = (i >> 13) & 3;
        int o  = cb * 64 + nt * 8 + (l >> 2);
        int k0 = ks * 16 + b * 8 + (l & 3) * 2;
        float w0 = (o < 128) ? wk[o * 256 + k0]     : wv[(o - 128) * 256 + k0];
        float w1 = (o < 128) ? wk[o * 256 + k0 + 1] : wv[(o - 128) * 256 + k0 + 1];
        g_Bf[i] = pack_h2(w0, w1);
    } else {
        int j = i - 32768;
        const float* W = (j < 16384) ? wq : mlp;
        int jj = j & 16383;
        int breg = jj & 1, l = (jj >> 1) & 31, p = (jj >> 6) & 1;
        int nt = (jj >> 7) & 1, ks = (jj >> 8) & 7, w = (jj >> 11) & 7;
        int col = w * 16 + nt * 8 + (l >> 2);
        int k0  = ks * 16 + breg * 8 + (l & 3) * 2;
        float w0 = W[col * 128 + k0], w1 = W[col * 128 + k0 + 1];
        uint32_t v;
        if (p == 0) v = pack_h2(w0, w1);
        else {
            float l0 = w0 - __half2float(__float2half_rn(w0));
            float l1 = w1 - __half2float(__float2half_rn(w1));
            v = pack_h2(l0, l1);
        }
        if (j < 16384) g_WqF[jj] = v; else g_MlF[jj] = v;
    }
}

__global__ __launch_bounds__(NTHR, 2)
void attn_mma_kernel(
    const int*   __restrict__ nodes,
    const float* __restrict__ times,
    const float* __restrict__ mem,
    const float* __restrict__ mail,
    const float* __restrict__ mail_time,
    const float* __restrict__ time_w,
    const float* __restrict__ time_b,
    const float* __restrict__ wq_b,
    const float* __restrict__ wk_b,
    const float* __restrict__ wv_b,
    const float* __restrict__ mlp_b,
    const float* __restrict__ ln_g,
    const float* __restrict__ ln_b,
    float*       __restrict__ out,
    int size)
{
    extern __shared__ __align__(1024) char smem[];
    const uint32_t sb = smem_u32(smem);
    const int tid = threadIdx.x, warp = tid >> 5, lane = tid & 31;
    const int base = blockIdx.x * NPB;

    int*   s_node = (int*)(smem + OFF_NODE);
    float* s_time = (float*)(smem + OFF_TIME);
    float* s_bk   = (float*)(smem + OFF_BK);
    float* s_bv   = (float*)(smem + OFF_BV);
    float* s_att  = (float*)(smem + OFF_ATT);
    float* s_dt   = (float*)(smem + OFF_DT);
    float* s_memf = (float*)(smem + OFF_MEM);
    float* s_q    = (float*)(smem + OFF_Q);
    float* s_out  = (float*)(smem + OFF_OUT);

    if (tid < NPB) {
        int g = base + tid; if (g >= size) g = size - 1;
        s_node[tid] = nodes[g];
        s_time[tid] = times[g];
    }
    if (tid >= 128) { int c = tid - 128; s_bk[c] = wk_b[c]; s_bv[c] = wv_b[c]; }
    __syncthreads();

    if (tid < ROWS) {
        int n = tid >> 3, slot = tid & 7;
        s_dt[tid] = s_time[n] - __ldg(mail_time + (size_t)s_node[n] * MAIL + slot);
    }

    // gather mem rows + hi/lo fp16 copy (rows 0-7 of MH/ML)
    {
        int n = tid >> 5, c4 = (tid & 31) * 4;
        float4 v = *(const float4*)(mem + (size_t)s_node[n] * DMEM + c4);
        ((float4*)s_memf)[tid] = v;
        float lx = v.x - __half2float(__float2half_rn(v.x));
        float ly = v.y - __half2float(__float2half_rn(v.y));
        float lz = v.z - __half2float(__float2half_rn(v.z));
        float lw = v.w - __half2float(__float2half_rn(v.w));
        uint32_t off = (uint32_t)(n * MHH + c4) * 2;
        *(uint32_t*)(smem + OFF_MH + off)     = pack_h2(v.x, v.y);
        *(uint32_t*)(smem + OFF_MH + off + 4) = pack_h2(v.z, v.w);
        *(uint32_t*)(smem + OFF_ML + off)     = pack_h2(lx, ly);
        *(uint32_t*)(smem + OFF_ML + off + 4) = pack_h2(lz, lw);
    }
    // zero rows 8-15 of MH/ML (valid data region only: 64 halves used of 136)
    for (int i = tid; i < 8 * 68; i += NTHR) {
        int r = 8 + i / 68, c = (i % 68) * 2;
        *(uint32_t*)(smem + OFF_MH + (uint32_t)(r * MHH + c) * 2) = 0u;
        *(uint32_t*)(smem + OFF_ML + (uint32_t)(r * MHH + c) * 2) = 0u;
    }

    // mail half of A (fp16); c4 constant per thread
    {
        const int c4 = (tid & 31) * 4;
        #pragma unroll
        for (int t = 0; t < 8; t++) {
            int r = (tid >> 5) + t * 8;
            int n = r >> 3, slot = r & 7;
            float4 mv = *(const float4*)(mail + ((size_t)s_node[n] * MAIL + slot) * 128 + c4);
            uint32_t* dst = (uint32_t*)(smem + OFF_A + ((size_t)r * AH + c4) * 2);
            dst[0] = pack_h2(mv.x, mv.y);
            dst[1] = pack_h2(mv.z, mv.w);
        }
    }
    __syncthreads();                                // s_dt, MH/ML ready

    // time-encode half of A: time_w/time_b hoisted (j constant per thread)
    {
        const int j = (tid & 63) * 2;
        const float tw0 = __ldg(time_w + j), tw1 = __ldg(time_w + j + 1);
        const float tb0 = __ldg(time_b + j), tb1 = __ldg(time_b + j + 1);
        #pragma unroll
        for (int t = 0; t < 16; t++) {
            int r = (tid >> 6) + t * 4;
            float dt = s_dt[r];
            float v0 = __cosf(fmaf(dt, tw0, tb0));
            float v1 = __cosf(fmaf(dt, tw1, tb1));
            *(uint32_t*)(smem + OFF_A + ((size_t)r * AH + 128 + j) * 2) = pack_h2(v0, v1);
        }
    }

    const int g8 = lane >> 3, lr = lane & 7;

    // ---- Q via MMA (hi/lo exact): warp w -> cols [w*16, w*16+16) ----
    {
        const int r = lane >> 2, cpos = 2 * (lane & 3);
        const uint32_t mrow = lr + ((g8 & 1) << 3);
        const uint32_t mko  = (uint32_t)((g8 >> 1) << 3);
        const uint32_t mHa = sb + OFF_MH + (mrow * MHH + mko) * 2;
        const uint32_t mLa = sb + OFF_ML + (mrow * MHH + mko) * 2;
        float qa0[4] = {0.f, 0.f, 0.f, 0.f}, qa1[4] = {0.f, 0.f, 0.f, 0.f};
        const uint2* wf = (const uint2*)g_WqF + (uint32_t)(warp * 8) * 128 + lane;
        #pragma unroll
        for (int ks = 0; ks < 8; ks++) {
            uint32_t ah0, ah1, ah2, ah3, al0, al1, al2, al3;
            ldsm4(mHa + (uint32_t)ks * 32, ah0, ah1, ah2, ah3);
            ldsm4(mLa + (uint32_t)ks * 32, al0, al1, al2, al3);
            uint2 bh0 = __ldg(wf + ks * 128);
            uint2 bl0 = __ldg(wf + ks * 128 + 32);
            uint2 bh1 = __ldg(wf + ks * 128 + 64);
            uint2 bl1 = __ldg(wf + ks * 128 + 96);
            mma16816(qa0, ah0, ah1, ah2, ah3, bh0.x, bh0.y);
            mma16816(qa0, al0, al1, al2, al3, bh0.x, bh0.y);
            mma16816(qa0, ah0, ah1, ah2, ah3, bl0.x, bl0.y);
            mma16816(qa1, ah0, ah1, ah2, ah3, bh1.x, bh1.y);
            mma16816(qa1, al0, al1, al2, al3, bh1.x, bh1.y);
            mma16816(qa1, ah0, ah1, ah2, ah3, bl1.x, bl1.y);
        }
        int col = warp * 16 + cpos;
        s_q[r * QF + col]     = qa0[0] + __ldg(wq_b + col);
        s_q[r * QF + col + 1] = qa0[1] + __ldg(wq_b + col + 1);
        s_q[r * QF + col + 8] = qa1[0] + __ldg(wq_b + col + 8);
        s_q[r * QF + col + 9] = qa1[1] + __ldg(wq_b + col + 9);
    }
    __syncthreads();                                // A + s_q ready

    // ---- big GEMM: C[64x256] = A x [Wk|Wv]^T ----
    const int rb = warp >> 2, cb = warp & 3;
    const int m0 = rb * 32;
    const int a_row = m0 + lr + ((g8 & 1) << 3);
    const int a_koff = (g8 >> 1) << 3;
    const uint32_t aB = sb + OFF_A + ((uint32_t)a_row * AH + a_koff) * 2;
    const uint4* bfp = (const uint4*)g_Bf + ((uint32_t)(cb * 16) * 32 + lane) * 4;

    float acc[2][8][4];
    #pragma unroll
    for (int rh = 0; rh < 2; rh++)
        #pragma unroll
        for (int t = 0; t < 8; t++)
            #pragma unroll
            for (int u = 0; u < 4; u++) acc[rh][t][u] = 0.f;

    #pragma unroll 4
    for (int ks = 0; ks < 16; ks++) {
        uint4 q0 = __ldg(bfp + 0);
        uint4 q1 = __ldg(bfp + 1);
        uint4 q2 = __ldg(bfp + 2);
        uint4 q3 = __ldg(bfp + 3);
        bfp += 128;
        uint32_t a0, a1, a2, a3, a4, a5, a6, a7;
        ldsm4(aB + ((uint32_t)ks * 16) * 2,             a0, a1, a2, a3);
        ldsm4(aB + ((uint32_t)(16 * AH + ks * 16)) * 2, a4, a5, a6, a7);
        mma16816(acc[0][0], a0, a1, a2, a3, q0.x, q0.y);
        mma16816(acc[0][1], a0, a1, a2, a3, q0.z, q0.w);
        mma16816(acc[0][2], a0, a1, a2, a3, q1.x, q1.y);
        mma16816(acc[0][3], a0, a1, a2, a3, q1.z, q1.w);
        mma16816(acc[0][4], a0, a1, a2, a3, q2.x, q2.y);
        mma16816(acc[0][5], a0, a1, a2, a3, q2.z, q2.w);
        mma16816(acc[0][6], a0, a1, a2, a3, q3.x, q3.y);
        mma16816(acc[0][7], a0, a1, a2, a3, q3.z, q3.w);
        mma16816(acc[1][0], a4, a5, a6, a7, q0.x, q0.y);
        mma16816(acc[1][1], a4, a5, a6, a7, q0.z, q0.w);
        mma16816(acc[1][2], a4, a5, a6, a7, q1.x, q1.y);
        mma16816(acc[1][3], a4, a5, a6, a7, q1.z, q1.w);
        mma16816(acc[1][4], a4, a5, a6, a7, q2.x, q2.y);
        mma16816(acc[1][5], a4, a5, a6, a7, q2.z, q2.w);
        mma16816(acc[1][6], a4, a5, a6, a7, q3.x, q3.y);
        mma16816(acc[1][7], a4, a5, a6, a7, q3.z, q3.w);
    }

    const int cw = 2 * (lane & 3);
    const int e  = lane >> 2;

    // ---- logits (K warps: cb 0,1), head = cb ----
    if (cb < 2) {
        float p[4] = {0.f, 0.f, 0.f, 0.f};
        #pragma unroll
        for (int rh = 0; rh < 2; rh++)
            #pragma unroll
            for (int nt = 0; nt < 8; nt++)
                #pragma unroll
                for (int u = 0; u < 4; u++) {
                    int col = cb * 64 + cw + nt * 8 + (u & 1);
                    int ni = rh * 2 + (u >> 1);
                    p[ni] = fmaf(acc[rh][nt][u] + s_bk[col],
                                 s_q[(4 * rb + ni) * QF + col], p[ni]);
                }
        #pragma unroll
        for (int ni = 0; ni < 4; ni++) {
            p[ni] += __shfl_xor_sync(0xffffffffu, p[ni], 1);
            p[ni] += __shfl_xor_sync(0xffffffffu, p[ni], 2);
        }
        if ((lane & 3) == 0) {
            #pragma unroll
            for (int ni = 0; ni < 4; ni++) {
                float v = p[ni];
                v = (v >= 0.f) ? v : 0.2f * v;
                s_att[((4 * rb + ni) * 8 + e) * 2 + cb] = v;
            }
        }
    }
    __syncthreads();

    if (tid < NPB * 2) {
        int n = tid >> 1, h = tid & 1;
        float mx = -1e30f;
        #pragma unroll
        for (int s = 0; s < MAIL; s++) mx = fmaxf(mx, s_att[(n * 8 + s) * 2 + h]);
        float ex[MAIL], sum = 0.f;
        #pragma unroll
        for (int s = 0; s < MAIL; s++) { ex[s] = __expf(s_att[(n * 8 + s) * 2 + h] - mx); sum += ex[s]; }
        float inv = 1.f / sum;
        #pragma unroll
        for (int s = 0; s < MAIL; s++) s_att[(n * 8 + s) * 2 + h] = ex[s] * inv;
    }
    __syncthreads();

    // ---- V slot-sum (V warps: cb 2,3), head = cb-2 ----
    if (cb >= 2) {
        const int head = cb - 2;
        float v[2][8][4];
        #pragma unroll
        for (int rh = 0; rh < 2; rh++) {
            float attA = s_att[((4 * rb + 2 * rh + 0) * 8 + e) * 2 + head];
            float attB = s_att[((4 * rb + 2 * rh + 1) * 8 + e) * 2 + head];
            #pragma unroll
            for (int nt = 0; nt < 8; nt++) {
                v[rh][nt][0] = acc[rh][nt][0] * attA;
                v[rh][nt][1] = acc[rh][nt][1] * attA;
                v[rh][nt][2] = acc[rh][nt][2] * attB;
                v[rh][nt][3] = acc[rh][nt][3] * attB;
            }
        }
        #pragma unroll
        for (int rh = 0; rh < 2; rh++)
            #pragma unroll
            for (int nt = 0; nt < 8; nt++)
                #pragma unroll
                for (int u = 0; u < 4; u++) {
                    float x = v[rh][nt][u];
                    x += __shfl_xor_sync(0xffffffffu, x, 4);
                    x += __shfl_xor_sync(0xffffffffu, x, 8);
                    x += __shfl_xor_sync(0xffffffffu, x, 16);
                    v[rh][nt][u] = x;
                }
        if (e == 0) {
            #pragma unroll
            for (int rh = 0; rh < 2; rh++)
                #pragma unroll
                for (int nt = 0; nt < 8; nt++)
                    #pragma unroll
                    for (int u = 0; u < 4; u++) {
                        int node = 4 * rb + 2 * rh + (u >> 1);
                        int ch = head * 64 + cw + nt * 8 + (u & 1);
                        s_out[node * 128 + ch] =
                            v[rh][nt][u] + s_bv[ch] + s_memf[node * 128 + ch];
                    }
        }
    }
    __syncthreads();

    // ---- LayerNorm: warp n -> node n; writes hi/lo fp16 into MH/ML ----
    {
        int n = warp;
        float4 x4 = ((float4*)(s_out + n * 128))[lane];
        float sum = x4.x + x4.y + x4.z + x4.w;
        float sq  = fmaf(x4.x, x4.x, fmaf(x4.y, x4.y, fmaf(x4.z, x4.z, x4.w * x4.w)));
        #pragma unroll
        for (int off = 16; off; off >>= 1) {
            sum += __shfl_xor_sync(0xffffffffu, sum, off);
            sq  += __shfl_xor_sync(0xffffffffu, sq, off);
        }
        float mu = sum * (1.f / 128.f);
        float rstd = rsqrtf(sq * (1.f / 128.f) - mu * mu + 1e-5f);
        float o[4] = {x4.x, x4.y, x4.z, x4.w};
        float y[4];
        #pragma unroll
        for (int u = 0; u < 4; u++) {
            int cc = lane * 4 + u;
            y[u] = (o[u] - mu) * rstd * __ldg(ln_g + cc) + __ldg(ln_b + cc);
        }
        uint32_t off0 = (uint32_t)(n * MHH + lane * 4) * 2;
        *(uint32_t*)(smem + OFF_MH + off0)     = pack_h2(y[0], y[1]);
        *(uint32_t*)(smem + OFF_MH + off0 + 4) = pack_h2(y[2], y[3]);
        float l0 = y[0] - __half2float(__float2half_rn(y[0]));
        float l1 = y[1] - __half2float(__float2half_rn(y[1]));
        float l2 = y[2] - __half2float(__float2half_rn(y[2]));
        float l3 = y[3] - __half2float(__float2half_rn(y[3]));
        *(uint32_t*)(smem + OFF_ML + off0)     = pack_h2(l0, l1);
        *(uint32_t*)(smem + OFF_ML + off0 + 4) = pack_h2(l2, l3);
    }
    __syncthreads();

    // ---- MLP via MMA (hi/lo exact) + ReLU + store ----
    {
        const int r = lane >> 2, cpos = 2 * (lane & 3);
        const uint32_t mrow = lr + ((g8 & 1) << 3);
        const uint32_t mko  = (uint32_t)((g8 >> 1) << 3);
        const uint32_t mHa = sb + OFF_MH + (mrow * MHH + mko) * 2;
        const uint32_t mLa = sb + OFF_ML + (mrow * MHH + mko) * 2;
        float qa0[4] = {0.f, 0.f, 0.f, 0.f}, qa1[4] = {0.f, 0.f, 0.f, 0.f};
        const uint2* wf = (const uint2*)g_MlF + (uint32_t)(warp * 8) * 128 + lane;
        #pragma unroll
        for (int ks = 0; ks < 8; ks++) {
            uint32_t ah0, ah1, ah2, ah3, al0, al1, al2, al3;
            ldsm4(mHa + (uint32_t)ks * 32, ah0, ah1, ah2, ah3);
            ldsm4(mLa + (uint32_t)ks * 32, al0, al1, al2, al3);
            uint2 bh0 = __ldg(wf + ks * 128);
            uint2 bl0 = __ldg(wf + ks * 128 + 32);
            uint2 bh1 = __ldg(wf + ks * 128 + 64);
            uint2 bl1 = __ldg(wf + ks * 128 + 96);
            mma16816(qa0, ah0, ah1, ah2, ah3, bh0.x, bh0.y);
            mma16816(qa0, al0, al1, al2, al3, bh0.x, bh0.y);
            mma16816(qa0, ah0, ah1, ah2, ah3, bl0.x, bl0.y);
            mma16816(qa1, ah0, ah1, ah2, ah3, bh1.x, bh1.y);
            mma16816(qa1, al0, al1, al2, al3, bh1.x, bh1.y);
            mma16816(qa1, ah0, ah1, ah2, ah3, bl1.x, bl1.y);
        }
        int col = warp * 16 + cpos;
        int g = base + r;
        if (g < size) {
            float2 v0, v1;
            v0.x = fmaxf(qa0[0] + __ldg(mlp_b + col),     0.f);
            v0.y = fmaxf(qa0[1] + __ldg(mlp_b + col + 1), 0.f);
            v1.x = fmaxf(qa1[0] + __ldg(mlp_b + col + 8), 0.f);
            v1.y = fmaxf(qa1[1] + __ldg(mlp_b + col + 9), 0.f);
            *(float2*)(out + (size_t)g * 128 + col)     = v0;
            *(float2*)(out + (size_t)g * 128 + col + 8) = v1;
        }
    }
}

extern "C" void kernel_launch(void* const* d_in, const int* in_sizes, int n_in,
                              void* d_out, int out_size) {
    const int*   nodes     = (const int*)  d_in[0];
    const float* times     = (const float*)d_in[1];
    const float* mem       = (const float*)d_in[2];
    const float* mail      = (const float*)d_in[3];
    const float* mail_time = (const float*)d_in[4];
    const float* time_w    = (const float*)d_in[5];
    const float* time_b    = (const float*)d_in[6];
    const float* wq_w      = (const float*)d_in[7];
    const float* wq_b      = (const float*)d_in[8];
    const float* wk_w      = (const float*)d_in[9];
    const float* wk_b      = (const float*)d_in[10];
    const float* wv_w      = (const float*)d_in[11];
    const float* wv_b      = (const float*)d_in[12];
    const float* mlp_w     = (const float*)d_in[13];
    const float* mlp_b     = (const float*)d_in[14];
    const float* ln_g      = (const float*)d_in[15];
    const float* ln_b      = (const float*)d_in[16];
    int size = in_sizes[0];

    cudaFuncSetAttribute(attn_mma_kernel,
                         cudaFuncAttributeMaxDynamicSharedMemorySize, SMEM_TOTAL);

    prep_weights<<<256, 256>>>(wq_w, wk_w, wv_w, mlp_w);

    int nblk = (size + NPB - 1) / NPB;
    attn_mma_kernel<<<nblk, NTHR, SMEM_TOTAL>>>(
        nodes, times, mem, mail, mail_time, time_w, time_b,
        wq_b, wk_b, wv_b, mlp_b, ln_g, ln_b,
        (float*)d_out, size);
}

// round 8
// speedup vs baseline: 5.9977x; 1.1670x over previous
#include <cuda_runtime.h>
#include <cuda_fp16.h>
#include <cstdint>
#include <math.h>

#define MAIL   8
#define DMEM   128
#define DCAT   256
#define NPB    16
#define ROWS   128
#define NTHR   256

#define AH 264             // A row stride in halves (132 words == 4 mod 32)
#define MHH 136            // MH row stride in halves (68 words == 4 mod 32)
#define QF 132             // s_q float row stride

// ---- smem byte offsets ----
#define OFF_NODE 0
#define OFF_TIME 64
#define OFF_BK   128
#define OFF_BV   640
#define OFF_ATT  1152                     // 8 local nodes x 8 slots x 2 heads
#define OFF_DT   1664                     // 128 floats
#define OFF_MEM  2176                     // 16 x 128 f32 -> 10368
#define OFF_Q    10368                    // 16 x 132 f32 (s_out overlays) -> 18816
#define OFF_OUT  10368
#define OFF_MH   18816                    // 16 x 136 halves -> 23168
#define OFF_A    23168                    // 128 x 264 halves -> 90752
#define SMEM_TOTAL 90752

// K/V weights in mma B-frag order
__device__ __align__(16) uint32_t g_Bf[32768 + 2048];
// Wq / mlp_w hi-only B-frags: idx = ((w*8+ks)*2+nt)*64 + lane*2 + breg
__device__ __align__(16) uint32_t g_WqF[8192];
__device__ __align__(16) uint32_t g_MlF[8192];

__device__ __forceinline__ uint32_t smem_u32(const void* p) {
    uint32_t a;
    asm("{ .reg .u64 t; cvta.to.shared.u64 t, %1; cvt.u32.u64 %0, t; }"
        : "=r"(a) : "l"(p));
    return a;
}
__device__ __forceinline__ void ldsm4(uint32_t addr, uint32_t& r0, uint32_t& r1,
                                      uint32_t& r2, uint32_t& r3) {
    asm volatile("ldmatrix.sync.aligned.m8n8.x4.shared.b16 {%0,%1,%2,%3}, [%4];"
                 : "=r"(r0), "=r"(r1), "=r"(r2), "=r"(r3) : "r"(addr));
}
__device__ __forceinline__ void mma16816(float* c, uint32_t a0, uint32_t a1,
                                         uint32_t a2, uint32_t a3,
                                         uint32_t b0, uint32_t b1) {
    asm volatile("mma.sync.aligned.m16n8k16.row.col.f32.f16.f16.f32 "
                 "{%0,%1,%2,%3},{%4,%5,%6,%7},{%8,%9},{%0,%1,%2,%3};"
                 : "+f"(c[0]), "+f"(c[1]), "+f"(c[2]), "+f"(c[3])
                 : "r"(a0), "r"(a1), "r"(a2), "r"(a3), "r"(b0), "r"(b1));
}
__device__ __forceinline__ uint32_t pack_h2(float x, float y) {
    __half2 h = __halves2half2(__float2half_rn(x), __float2half_rn(y));
    return *(uint32_t*)&h;
}

__global__ void prep_weights(const float* __restrict__ wq,
                             const float* __restrict__ wk,
                             const float* __restrict__ wv,
                             const float* __restrict__ mlp) {
    int i = blockIdx.x * 256 + threadIdx.x;           // 0..65535
    if (i < 32768) {
        int b  = i & 1;
        int nt = (i >> 1) & 7;
        int l  = (i >> 4) & 31;
        int ks = (i >> 9) & 15;
        int cb = (i >> 13) & 3;
        int o  = cb * 64 + nt * 8 + (l >> 2);
        int k0 = ks * 16 + b * 8 + (l & 3) * 2;
        float w0 = (o < 128) ? wk[o * 256 + k0]     : wv[(o - 128) * 256 + k0];
        float w1 = (o < 128) ? wk[o * 256 + k0 + 1] : wv[(o - 128) * 256 + k0 + 1];
        g_Bf[i] = pack_h2(w0, w1);
    } else if (i < 49152) {
        int j = i - 32768;
        const float* W = (j < 8192) ? wq : mlp;
        int jj = j & 8191;
        int breg = jj & 1, l = (jj >> 1) & 31;
        int nt = (jj >> 6) & 1, ks = (jj >> 7) & 7, w = (jj >> 10) & 7;
        int col = w * 16 + nt * 8 + (l >> 2);
        int k0  = ks * 16 + breg * 8 + (l & 3) * 2;
        uint32_t v = pack_h2(W[col * 128 + k0], W[col * 128 + k0 + 1]);
        if (j < 8192) g_WqF[jj] = v; else g_MlF[jj] = v;
    }
}

__global__ __launch_bounds__(NTHR, 2)
void attn_mma_kernel(
    const int*   __restrict__ nodes,
    const float* __restrict__ times,
    const float* __restrict__ mem,
    const float* __restrict__ mail,
    const float* __restrict__ mail_time,
    const float* __restrict__ time_w,
    const float* __restrict__ time_b,
    const float* __restrict__ wq_b,
    const float* __restrict__ wk_b,
    const float* __restrict__ wv_b,
    const float* __restrict__ mlp_b,
    const float* __restrict__ ln_g,
    const float* __restrict__ ln_b,
    float*       __restrict__ out,
    int size)
{
    extern __shared__ __align__(1024) char smem[];
    const uint32_t sb = smem_u32(smem);
    const int tid = threadIdx.x, warp = tid >> 5, lane = tid & 31;
    const int base = blockIdx.x * NPB;

    int*   s_node = (int*)(smem + OFF_NODE);
    float* s_time = (float*)(smem + OFF_TIME);
    float* s_bk   = (float*)(smem + OFF_BK);
    float* s_bv   = (float*)(smem + OFF_BV);
    float* s_att  = (float*)(smem + OFF_ATT);
    float* s_dt   = (float*)(smem + OFF_DT);
    float* s_memf = (float*)(smem + OFF_MEM);
    float* s_q    = (float*)(smem + OFF_Q);
    float* s_out  = (float*)(smem + OFF_OUT);

    if (tid < NPB) {
        int g = base + tid; if (g >= size) g = size - 1;
        s_node[tid] = nodes[g];
        s_time[tid] = times[g];
    }
    if (tid >= 128) { int c = tid - 128; s_bk[c] = wk_b[c]; s_bv[c] = wv_b[c]; }
    __syncthreads();

    if (tid < ROWS) {
        int n = tid >> 3, slot = tid & 7;
        s_dt[tid] = s_time[n] - __ldg(mail_time + (size_t)s_node[n] * MAIL + slot);
    }

    // gather mem rows (fp32) + hi fp16 copy into MH (16 rows)
    #pragma unroll
    for (int t = 0; t < 2; t++) {
        int idx = tid + t * NTHR;                    // 0..511
        int n = idx >> 5, c4 = (idx & 31) * 4;
        float4 v = *(const float4*)(mem + (size_t)s_node[n] * DMEM + c4);
        ((float4*)s_memf)[idx] = v;
        uint32_t off = (uint32_t)(n * MHH + c4) * 2;
        *(uint32_t*)(smem + OFF_MH + off)     = pack_h2(v.x, v.y);
        *(uint32_t*)(smem + OFF_MH + off + 4) = pack_h2(v.z, v.w);
    }

    // mail half of A (fp16); c4 constant per thread
    {
        const int c4 = (tid & 31) * 4;
        #pragma unroll
        for (int t = 0; t < 16; t++) {
            int r = (tid >> 5) + t * 8;
            int n = r >> 3, slot = r & 7;
            float4 mv = *(const float4*)(mail + ((size_t)s_node[n] * MAIL + slot) * 128 + c4);
            uint32_t* dst = (uint32_t*)(smem + OFF_A + ((size_t)r * AH + c4) * 2);
            dst[0] = pack_h2(mv.x, mv.y);
            dst[1] = pack_h2(mv.z, mv.w);
        }
    }
    __syncthreads();                                 // s_dt, MH ready

    // time-encode half of A: j constant per thread
    {
        const int j = (tid & 63) * 2;
        const float tw0 = __ldg(time_w + j), tw1 = __ldg(time_w + j + 1);
        const float tb0 = __ldg(time_b + j), tb1 = __ldg(time_b + j + 1);
        #pragma unroll
        for (int t = 0; t < 32; t++) {
            int r = (tid >> 6) + t * 4;
            float dt = s_dt[r];
            float v0 = __cosf(fmaf(dt, tw0, tb0));
            float v1 = __cosf(fmaf(dt, tw1, tb1));
            *(uint32_t*)(smem + OFF_A + ((size_t)r * AH + 128 + j) * 2) = pack_h2(v0, v1);
        }
    }

    const int g8 = lane >> 3, lr = lane & 7;
    const uint32_t mrow = lr + ((g8 & 1) << 3);
    const uint32_t mko  = (uint32_t)((g8 >> 1) << 3);
    const uint32_t mHa  = sb + OFF_MH + (mrow * MHH + mko) * 2;

    // ---- Q via MMA (16 real rows): warp w -> cols [w*16, w*16+16) ----
    {
        const int r = lane >> 2, cpos = 2 * (lane & 3);
        float qa0[4] = {0.f, 0.f, 0.f, 0.f}, qa1[4] = {0.f, 0.f, 0.f, 0.f};
        const uint2* wfq = (const uint2*)g_WqF + (uint32_t)warp * 512 + lane;
        #pragma unroll
        for (int ks = 0; ks < 8; ks++) {
            uint32_t ah0, ah1, ah2, ah3;
            ldsm4(mHa + (uint32_t)ks * 32, ah0, ah1, ah2, ah3);
            uint2 bh0 = __ldg(wfq + ks * 64);
            uint2 bh1 = __ldg(wfq + ks * 64 + 32);
            mma16816(qa0, ah0, ah1, ah2, ah3, bh0.x, bh0.y);
            mma16816(qa1, ah0, ah1, ah2, ah3, bh1.x, bh1.y);
        }
        int col = warp * 16 + cpos;
        float b0 = __ldg(wq_b + col),     b1 = __ldg(wq_b + col + 1);
        float b8 = __ldg(wq_b + col + 8), b9 = __ldg(wq_b + col + 9);
        s_q[r * QF + col]           = qa0[0] + b0;
        s_q[r * QF + col + 1]       = qa0[1] + b1;
        s_q[(r + 8) * QF + col]     = qa0[2] + b0;
        s_q[(r + 8) * QF + col + 1] = qa0[3] + b1;
        s_q[r * QF + col + 8]       = qa1[0] + b8;
        s_q[r * QF + col + 9]       = qa1[1] + b9;
        s_q[(r + 8) * QF + col + 8] = qa1[2] + b8;
        s_q[(r + 8) * QF + col + 9] = qa1[3] + b9;
    }
    __syncthreads();                                 // A + s_q ready

    // ---- two-pass GEMM + attention epilogue ----
    const int rb = warp >> 2, cb = warp & 3;
    const int m0 = rb * 32;
    const int a_row = m0 + lr + ((g8 & 1) << 3);
    const int a_koff = (g8 >> 1) << 3;
    const int cw = 2 * (lane & 3);
    const int e  = lane >> 2;

    #pragma unroll 1
    for (int p = 0; p < 2; p++) {
        const uint32_t aB = sb + OFF_A +
            (((uint32_t)(p * 64 + a_row)) * AH + a_koff) * 2;
        const uint4* bfp = (const uint4*)g_Bf + ((uint32_t)(cb * 16) * 32 + lane) * 4;

        float acc[2][8][4];
        #pragma unroll
        for (int rh = 0; rh < 2; rh++)
            #pragma unroll
            for (int t = 0; t < 8; t++)
                #pragma unroll
                for (int u = 0; u < 4; u++) acc[rh][t][u] = 0.f;

        #pragma unroll 4
        for (int ks = 0; ks < 16; ks++) {
            uint4 q0 = __ldg(bfp + 0);
            uint4 q1 = __ldg(bfp + 1);
            uint4 q2 = __ldg(bfp + 2);
            uint4 q3 = __ldg(bfp + 3);
            bfp += 128;
            uint32_t a0, a1, a2, a3, a4, a5, a6, a7;
            ldsm4(aB + ((uint32_t)ks * 16) * 2,             a0, a1, a2, a3);
            ldsm4(aB + ((uint32_t)(16 * AH + ks * 16)) * 2, a4, a5, a6, a7);
            mma16816(acc[0][0], a0, a1, a2, a3, q0.x, q0.y);
            mma16816(acc[0][1], a0, a1, a2, a3, q0.z, q0.w);
            mma16816(acc[0][2], a0, a1, a2, a3, q1.x, q1.y);
            mma16816(acc[0][3], a0, a1, a2, a3, q1.z, q1.w);
            mma16816(acc[0][4], a0, a1, a2, a3, q2.x, q2.y);
            mma16816(acc[0][5], a0, a1, a2, a3, q2.z, q2.w);
            mma16816(acc[0][6], a0, a1, a2, a3, q3.x, q3.y);
            mma16816(acc[0][7], a0, a1, a2, a3, q3.z, q3.w);
            mma16816(acc[1][0], a4, a5, a6, a7, q0.x, q0.y);
            mma16816(acc[1][1], a4, a5, a6, a7, q0.z, q0.w);
            mma16816(acc[1][2], a4, a5, a6, a7, q1.x, q1.y);
            mma16816(acc[1][3], a4, a5, a6, a7, q1.z, q1.w);
            mma16816(acc[1][4], a4, a5, a6, a7, q2.x, q2.y);
            mma16816(acc[1][5], a4, a5, a6, a7, q2.z, q2.w);
            mma16816(acc[1][6], a4, a5, a6, a7, q3.x, q3.y);
            mma16816(acc[1][7], a4, a5, a6, a7, q3.z, q3.w);
        }

        // logits (K warps: cb 0,1), head = cb; local node = 4rb+ni
        if (cb < 2) {
            float pr[4] = {0.f, 0.f, 0.f, 0.f};
            #pragma unroll
            for (int rh = 0; rh < 2; rh++)
                #pragma unroll
                for (int nt = 0; nt < 8; nt++)
                    #pragma unroll
                    for (int u = 0; u < 4; u++) {
                        int col = cb * 64 + cw + nt * 8 + (u & 1);
                        int ni = rh * 2 + (u >> 1);
                        pr[ni] = fmaf(acc[rh][nt][u] + s_bk[col],
                                      s_q[(p * 8 + 4 * rb + ni) * QF + col], pr[ni]);
                    }
            #pragma unroll
            for (int ni = 0; ni < 4; ni++) {
                pr[ni] += __shfl_xor_sync(0xffffffffu, pr[ni], 1);
                pr[ni] += __shfl_xor_sync(0xffffffffu, pr[ni], 2);
            }
            if ((lane & 3) == 0) {
                #pragma unroll
                for (int ni = 0; ni < 4; ni++) {
                    float v = pr[ni];
                    v = (v >= 0.f) ? v : 0.2f * v;
                    s_att[((4 * rb + ni) * 8 + e) * 2 + cb] = v;
                }
            }
        }
        __syncthreads();

        if (tid < 16) {                              // softmax over slots (8 local nodes)
            int n = tid >> 1, h = tid & 1;
            float mx = -1e30f;
            #pragma unroll
            for (int s = 0; s < MAIL; s++) mx = fmaxf(mx, s_att[(n * 8 + s) * 2 + h]);
            float ex[MAIL], sum = 0.f;
            #pragma unroll
            for (int s = 0; s < MAIL; s++) { ex[s] = __expf(s_att[(n * 8 + s) * 2 + h] - mx); sum += ex[s]; }
            float inv = 1.f / sum;
            #pragma unroll
            for (int s = 0; s < MAIL; s++) s_att[(n * 8 + s) * 2 + h] = ex[s] * inv;
        }
        __syncthreads();

        // V slot-sum (V warps: cb 2,3), head = cb-2
        if (cb >= 2) {
            const int head = cb - 2;
            float v[2][8][4];
            #pragma unroll
            for (int rh = 0; rh < 2; rh++) {
                float attA = s_att[((4 * rb + 2 * rh + 0) * 8 + e) * 2 + head];
                float attB = s_att[((4 * rb + 2 * rh + 1) * 8 + e) * 2 + head];
                #pragma unroll
                for (int nt = 0; nt < 8; nt++) {
                    v[rh][nt][0] = acc[rh][nt][0] * attA;
                    v[rh][nt][1] = acc[rh][nt][1] * attA;
                    v[rh][nt][2] = acc[rh][nt][2] * attB;
                    v[rh][nt][3] = acc[rh][nt][3] * attB;
                }
            }
            #pragma unroll
            for (int rh = 0; rh < 2; rh++)
                #pragma unroll
                for (int nt = 0; nt < 8; nt++)
                    #pragma unroll
                    for (int u = 0; u < 4; u++) {
                        float x = v[rh][nt][u];
                        x += __shfl_xor_sync(0xffffffffu, x, 4);
                        x += __shfl_xor_sync(0xffffffffu, x, 8);
                        x += __shfl_xor_sync(0xffffffffu, x, 16);
                        v[rh][nt][u] = x;
                    }
            if (e == 0) {
                #pragma unroll
                for (int rh = 0; rh < 2; rh++)
                    #pragma unroll
                    for (int nt = 0; nt < 8; nt++)
                        #pragma unroll
                        for (int u = 0; u < 4; u++) {
                            int node = p * 8 + 4 * rb + 2 * rh + (u >> 1);
                            int ch = head * 64 + cw + nt * 8 + (u & 1);
                            s_out[node * 128 + ch] =
                                v[rh][nt][u] + s_bv[ch] + s_memf[node * 128 + ch];
                        }
            }
        }
        __syncthreads();
    }

    // ---- LayerNorm: warp handles 2 nodes; writes hi fp16 into MH ----
    #pragma unroll
    for (int t = 0; t < 2; t++) {
        int n = warp * 2 + t;
        float4 x4 = ((float4*)(s_out + n * 128))[lane];
        float sum = x4.x + x4.y + x4.z + x4.w;
        float sq  = fmaf(x4.x, x4.x, fmaf(x4.y, x4.y, fmaf(x4.z, x4.z, x4.w * x4.w)));
        #pragma unroll
        for (int off = 16; off; off >>= 1) {
            sum += __shfl_xor_sync(0xffffffffu, sum, off);
            sq  += __shfl_xor_sync(0xffffffffu, sq, off);
        }
        float mu = sum * (1.f / 128.f);
        float rstd = rsqrtf(sq * (1.f / 128.f) - mu * mu + 1e-5f);
        float o[4] = {x4.x, x4.y, x4.z, x4.w};
        float y[4];
        #pragma unroll
        for (int u = 0; u < 4; u++) {
            int cc = lane * 4 + u;
            y[u] = (o[u] - mu) * rstd * __ldg(ln_g + cc) + __ldg(ln_b + cc);
        }
        uint32_t off0 = (uint32_t)(n * MHH + lane * 4) * 2;
        *(uint32_t*)(smem + OFF_MH + off0)     = pack_h2(y[0], y[1]);
        *(uint32_t*)(smem + OFF_MH + off0 + 4) = pack_h2(y[2], y[3]);
    }
    __syncthreads();

    // ---- MLP via MMA (16 real rows) + ReLU + store ----
    {
        const int r = lane >> 2, cpos = 2 * (lane & 3);
        float qa0[4] = {0.f, 0.f, 0.f, 0.f}, qa1[4] = {0.f, 0.f, 0.f, 0.f};
        const uint2* wfm = (const uint2*)g_MlF + (uint32_t)warp * 512 + lane;
        #pragma unroll
        for (int ks = 0; ks < 8; ks++) {
            uint32_t ah0, ah1, ah2, ah3;
            ldsm4(mHa + (uint32_t)ks * 32, ah0, ah1, ah2, ah3);
            uint2 bh0 = __ldg(wfm + ks * 64);
            uint2 bh1 = __ldg(wfm + ks * 64 + 32);
            mma16816(qa0, ah0, ah1, ah2, ah3, bh0.x, bh0.y);
            mma16816(qa1, ah0, ah1, ah2, ah3, bh1.x, bh1.y);
        }
        int col = warp * 16 + cpos;
        float b0 = __ldg(mlp_b + col),     b1 = __ldg(mlp_b + col + 1);
        float b8 = __ldg(mlp_b + col + 8), b9 = __ldg(mlp_b + col + 9);
        int g0 = base + r, g1 = base + r + 8;
        if (g0 < size) {
            float2 v0 = { fmaxf(qa0[0] + b0, 0.f), fmaxf(qa0[1] + b1, 0.f) };
            float2 v1 = { fmaxf(qa1[0] + b8, 0.f), fmaxf(qa1[1] + b9, 0.f) };
            *(float2*)(out + (size_t)g0 * 128 + col)     = v0;
            *(float2*)(out + (size_t)g0 * 128 + col + 8) = v1;
        }
        if (g1 < size) {
            float2 v0 = { fmaxf(qa0[2] + b0, 0.f), fmaxf(qa0[3] + b1, 0.f) };
            float2 v1 = { fmaxf(qa1[2] + b8, 0.f), fmaxf(qa1[3] + b9, 0.f) };
            *(float2*)(out + (size_t)g1 * 128 + col)     = v0;
            *(float2*)(out + (size_t)g1 * 128 + col + 8) = v1;
        }
    }
}

extern "C" void kernel_launch(void* const* d_in, const int* in_sizes, int n_in,
                              void* d_out, int out_size) {
    const int*   nodes     = (const int*)  d_in[0];
    const float* times     = (const float*)d_in[1];
    const float* mem       = (const float*)d_in[2];
    const float* mail      = (const float*)d_in[3];
    const float* mail_time = (const float*)d_in[4];
    const float* time_w    = (const float*)d_in[5];
    const float* time_b    = (const float*)d_in[6];
    const float* wq_w      = (const float*)d_in[7];
    const float* wq_b      = (const float*)d_in[8];
    const float* wk_w      = (const float*)d_in[9];
    const float* wk_b      = (const float*)d_in[10];
    const float* wv_w      = (const float*)d_in[11];
    const float* wv_b      = (const float*)d_in[12];
    const float* mlp_w     = (const float*)d_in[13];
    const float* mlp_b     = (const float*)d_in[14];
    const float* ln_g      = (const float*)d_in[15];
    const float* ln_b      = (const float*)d_in[16];
    int size = in_sizes[0];

    cudaFuncSetAttribute(attn_mma_kernel,
                         cudaFuncAttributeMaxDynamicSharedMemorySize, SMEM_TOTAL);

    prep_weights<<<256, 256>>>(wq_w, wk_w, wv_w, mlp_w);

    int nblk = (size + NPB - 1) / NPB;
    attn_mma_kernel<<<nblk, NTHR, SMEM_TOTAL>>>(
        nodes, times, mem, mail, mail_time, time_w, time_b,
        wq_b, wk_b, wv_b, mlp_b, ln_g, ln_b,
        (float*)d_out, size);
}

// round 9
// speedup vs baseline: 8.9221x; 1.4876x over previous
#include <cuda_runtime.h>
#include <cuda_fp16.h>
#include <cstdint>
#include <math.h>

#define MAIL   8
#define DMEM   128
#define DCAT   256
#define NPB    16
#define ROWS   128
#define NTHR   256

#define AH 264             // A row stride in halves (132 words == 4 mod 32)
#define MHH 136            // MH row stride in halves (68 words == 4 mod 32)
#define QF 132             // s_q float row stride

// ---- smem byte offsets ----
#define OFF_NODE 0
#define OFF_TIME 64
#define OFF_BK   128
#define OFF_BV   640
#define OFF_ATT  1152
#define OFF_DT   1664
#define OFF_MEM  2176                     // 16 x 128 f32 -> 10368
#define OFF_Q    10368                    // 16 x 132 f32 (s_out overlays) -> 18816
#define OFF_OUT  10368
#define OFF_MH   18816                    // 16 x 136 halves -> 23168
#define OFF_A    23168                    // 128 x 264 halves -> 90752
#define SMEM_TOTAL 90752

// K/V weights in COALESCED mma B-frag order:
// uint4 index = ((cb*16+ks)*4 + j)*32 + lane  (j = register pair 0..3)
__device__ __align__(16) uint32_t g_Bf[32768 + 2048];
// Wq / mlp_w hi-only B-frags: idx = ((w*8+ks)*2+nt)*64 + lane*2 + breg
__device__ __align__(16) uint32_t g_WqF[8192];
__device__ __align__(16) uint32_t g_MlF[8192];

__device__ __forceinline__ uint32_t smem_u32(const void* p) {
    uint32_t a;
    asm("{ .reg .u64 t; cvta.to.shared.u64 t, %1; cvt.u32.u64 %0, t; }"
        : "=r"(a) : "l"(p));
    return a;
}
__device__ __forceinline__ void ldsm4(uint32_t addr, uint32_t& r0, uint32_t& r1,
                                      uint32_t& r2, uint32_t& r3) {
    asm volatile("ldmatrix.sync.aligned.m8n8.x4.shared.b16 {%0,%1,%2,%3}, [%4];"
                 : "=r"(r0), "=r"(r1), "=r"(r2), "=r"(r3) : "r"(addr));
}
__device__ __forceinline__ void mma16816(float* c, uint32_t a0, uint32_t a1,
                                         uint32_t a2, uint32_t a3,
                                         uint32_t b0, uint32_t b1) {
    asm volatile("mma.sync.aligned.m16n8k16.row.col.f32.f16.f16.f32 "
                 "{%0,%1,%2,%3},{%4,%5,%6,%7},{%8,%9},{%0,%1,%2,%3};"
                 : "+f"(c[0]), "+f"(c[1]), "+f"(c[2]), "+f"(c[3])
                 : "r"(a0), "r"(a1), "r"(a2), "r"(a3), "r"(b0), "r"(b1));
}
__device__ __forceinline__ uint32_t pack_h2(float x, float y) {
    __half2 h = __halves2half2(__float2half_rn(x), __float2half_rn(y));
    return *(uint32_t*)&h;
}

__global__ void prep_weights(const float* __restrict__ wq,
                             const float* __restrict__ wk,
                             const float* __restrict__ wv,
                             const float* __restrict__ mlp) {
    int i = blockIdx.x * 256 + threadIdx.x;           // 0..65535
    if (i < 32768) {
        // coalesced frag layout: i = (((cb*16+ks)*4 + j)*32 + lane)*4 + c
        int c    = i & 3;
        int lane = (i >> 2) & 31;
        int j    = (i >> 7) & 3;
        int ks   = (i >> 9) & 15;
        int cb   = (i >> 13) & 3;
        int nt   = j * 2 + (c >> 1);
        int b    = c & 1;
        int o  = cb * 64 + nt * 8 + (lane >> 2);
        int k0 = ks * 16 + b * 8 + (lane & 3) * 2;
        float w0 = (o < 128) ? wk[o * 256 + k0]     : wv[(o - 128) * 256 + k0];
        float w1 = (o < 128) ? wk[o * 256 + k0 + 1] : wv[(o - 128) * 256 + k0 + 1];
        g_Bf[i] = pack_h2(w0, w1);
    } else if (i < 49152) {
        int j = i - 32768;
        const float* W = (j < 8192) ? wq : mlp;
        int jj = j & 8191;
        int breg = jj & 1, l = (jj >> 1) & 31;
        int nt = (jj >> 6) & 1, ks = (jj >> 7) & 7, w = (jj >> 10) & 7;
        int col = w * 16 + nt * 8 + (l >> 2);
        int k0  = ks * 16 + breg * 8 + (l & 3) * 2;
        uint32_t v = pack_h2(W[col * 128 + k0], W[col * 128 + k0 + 1]);
        if (j < 8192) g_WqF[jj] = v; else g_MlF[jj] = v;
    }
}

__global__ __launch_bounds__(NTHR, 2)
void attn_mma_kernel(
    const int*   __restrict__ nodes,
    const float* __restrict__ times,
    const float* __restrict__ mem,
    const float* __restrict__ mail,
    const float* __restrict__ mail_time,
    const float* __restrict__ time_w,
    const float* __restrict__ time_b,
    const float* __restrict__ wq_b,
    const float* __restrict__ wk_b,
    const float* __restrict__ wv_b,
    const float* __restrict__ mlp_b,
    const float* __restrict__ ln_g,
    const float* __restrict__ ln_b,
    float*       __restrict__ out,
    int size)
{
    extern __shared__ __align__(1024) char smem[];
    const uint32_t sb = smem_u32(smem);
    const int tid = threadIdx.x, warp = tid >> 5, lane = tid & 31;
    const int base = blockIdx.x * NPB;

    int*   s_node = (int*)(smem + OFF_NODE);
    float* s_time = (float*)(smem + OFF_TIME);
    float* s_bk   = (float*)(smem + OFF_BK);
    float* s_bv   = (float*)(smem + OFF_BV);
    float* s_att  = (float*)(smem + OFF_ATT);
    float* s_dt   = (float*)(smem + OFF_DT);
    float* s_memf = (float*)(smem + OFF_MEM);
    float* s_q    = (float*)(smem + OFF_Q);
    float* s_out  = (float*)(smem + OFF_OUT);

    if (tid < NPB) {
        int g = base + tid; if (g >= size) g = size - 1;
        s_node[tid] = nodes[g];
        s_time[tid] = times[g];
    }
    if (tid >= 128) { int c = tid - 128; s_bk[c] = wk_b[c]; s_bv[c] = wv_b[c]; }
    __syncthreads();

    if (tid < ROWS) {
        int n = tid >> 3, slot = tid & 7;
        s_dt[tid] = s_time[n] - __ldg(mail_time + (size_t)s_node[n] * MAIL + slot);
    }

    // gather mem rows (fp32) + hi fp16 copy into MH (16 rows)
    #pragma unroll
    for (int t = 0; t < 2; t++) {
        int idx = tid + t * NTHR;
        int n = idx >> 5, c4 = (idx & 31) * 4;
        float4 v = *(const float4*)(mem + (size_t)s_node[n] * DMEM + c4);
        ((float4*)s_memf)[idx] = v;
        uint32_t off = (uint32_t)(n * MHH + c4) * 2;
        *(uint32_t*)(smem + OFF_MH + off)     = pack_h2(v.x, v.y);
        *(uint32_t*)(smem + OFF_MH + off + 4) = pack_h2(v.z, v.w);
    }

    // mail half of A (fp16); c4 constant per thread
    {
        const int c4 = (tid & 31) * 4;
        #pragma unroll
        for (int t = 0; t < 16; t++) {
            int r = (tid >> 5) + t * 8;
            int n = r >> 3, slot = r & 7;
            float4 mv = *(const float4*)(mail + ((size_t)s_node[n] * MAIL + slot) * 128 + c4);
            uint32_t* dst = (uint32_t*)(smem + OFF_A + ((size_t)r * AH + c4) * 2);
            dst[0] = pack_h2(mv.x, mv.y);
            dst[1] = pack_h2(mv.z, mv.w);
        }
    }
    __syncthreads();

    // time-encode half of A
    {
        const int j = (tid & 63) * 2;
        const float tw0 = __ldg(time_w + j), tw1 = __ldg(time_w + j + 1);
        const float tb0 = __ldg(time_b + j), tb1 = __ldg(time_b + j + 1);
        #pragma unroll
        for (int t = 0; t < 32; t++) {
            int r = (tid >> 6) + t * 4;
            float dt = s_dt[r];
            float v0 = __cosf(fmaf(dt, tw0, tb0));
            float v1 = __cosf(fmaf(dt, tw1, tb1));
            *(uint32_t*)(smem + OFF_A + ((size_t)r * AH + 128 + j) * 2) = pack_h2(v0, v1);
        }
    }

    const int g8 = lane >> 3, lr = lane & 7;
    const uint32_t mrow = lr + ((g8 & 1) << 3);
    const uint32_t mko  = (uint32_t)((g8 >> 1) << 3);
    const uint32_t mHa  = sb + OFF_MH + (mrow * MHH + mko) * 2;

    // ---- Q via MMA: warp w -> cols [w*16, w*16+16) ----
    {
        const int r = lane >> 2, cpos = 2 * (lane & 3);
        float qa0[4] = {0.f, 0.f, 0.f, 0.f}, qa1[4] = {0.f, 0.f, 0.f, 0.f};
        const uint2* wfq = (const uint2*)g_WqF + (uint32_t)warp * 512 + lane;
        #pragma unroll
        for (int ks = 0; ks < 8; ks++) {
            uint32_t ah0, ah1, ah2, ah3;
            ldsm4(mHa + (uint32_t)ks * 32, ah0, ah1, ah2, ah3);
            uint2 bh0 = __ldg(wfq + ks * 64);
            uint2 bh1 = __ldg(wfq + ks * 64 + 32);
            mma16816(qa0, ah0, ah1, ah2, ah3, bh0.x, bh0.y);
            mma16816(qa1, ah0, ah1, ah2, ah3, bh1.x, bh1.y);
        }
        int col = warp * 16 + cpos;
        float b0 = __ldg(wq_b + col),     b1 = __ldg(wq_b + col + 1);
        float b8 = __ldg(wq_b + col + 8), b9 = __ldg(wq_b + col + 9);
        s_q[r * QF + col]           = qa0[0] + b0;
        s_q[r * QF + col + 1]       = qa0[1] + b1;
        s_q[(r + 8) * QF + col]     = qa0[2] + b0;
        s_q[(r + 8) * QF + col + 1] = qa0[3] + b1;
        s_q[r * QF + col + 8]       = qa1[0] + b8;
        s_q[r * QF + col + 9]       = qa1[1] + b9;
        s_q[(r + 8) * QF + col + 8] = qa1[2] + b8;
        s_q[(r + 8) * QF + col + 9] = qa1[3] + b9;
    }
    __syncthreads();

    // ---- two-pass GEMM + attention epilogue ----
    const int rb = warp >> 2, cb = warp & 3;
    const int m0 = rb * 32;
    const int a_row = m0 + lr + ((g8 & 1) << 3);
    const int a_koff = (g8 >> 1) << 3;
    const int cw = 2 * (lane & 3);
    const int e  = lane >> 2;

    #pragma unroll 1
    for (int p = 0; p < 2; p++) {
        const uint32_t aB = sb + OFF_A +
            (((uint32_t)(p * 64 + a_row)) * AH + a_koff) * 2;
        const uint4* bfp = (const uint4*)g_Bf + (uint32_t)(cb * 16) * 128 + lane;

        float acc[2][8][4];
        #pragma unroll
        for (int rh = 0; rh < 2; rh++)
            #pragma unroll
            for (int t = 0; t < 8; t++)
                #pragma unroll
                for (int u = 0; u < 4; u++) acc[rh][t][u] = 0.f;

        #pragma unroll 4
        for (int ks = 0; ks < 16; ks++) {
            uint4 q0 = __ldg(bfp + 0);     // 32 lanes x 16B contiguous
            uint4 q1 = __ldg(bfp + 32);
            uint4 q2 = __ldg(bfp + 64);
            uint4 q3 = __ldg(bfp + 96);
            bfp += 128;
            uint32_t a0, a1, a2, a3, a4, a5, a6, a7;
            ldsm4(aB + ((uint32_t)ks * 16) * 2,             a0, a1, a2, a3);
            ldsm4(aB + ((uint32_t)(16 * AH + ks * 16)) * 2, a4, a5, a6, a7);
            mma16816(acc[0][0], a0, a1, a2, a3, q0.x, q0.y);
            mma16816(acc[0][1], a0, a1, a2, a3, q0.z, q0.w);
            mma16816(acc[0][2], a0, a1, a2, a3, q1.x, q1.y);
            mma16816(acc[0][3], a0, a1, a2, a3, q1.z, q1.w);
            mma16816(acc[0][4], a0, a1, a2, a3, q2.x, q2.y);
            mma16816(acc[0][5], a0, a1, a2, a3, q2.z, q2.w);
            mma16816(acc[0][6], a0, a1, a2, a3, q3.x, q3.y);
            mma16816(acc[0][7], a0, a1, a2, a3, q3.z, q3.w);
            mma16816(acc[1][0], a4, a5, a6, a7, q0.x, q0.y);
            mma16816(acc[1][1], a4, a5, a6, a7, q0.z, q0.w);
            mma16816(acc[1][2], a4, a5, a6, a7, q1.x, q1.y);
            mma16816(acc[1][3], a4, a5, a6, a7, q1.z, q1.w);
            mma16816(acc[1][4], a4, a5, a6, a7, q2.x, q2.y);
            mma16816(acc[1][5], a4, a5, a6, a7, q2.z, q2.w);
            mma16816(acc[1][6], a4, a5, a6, a7, q3.x, q3.y);
            mma16816(acc[1][7], a4, a5, a6, a7, q3.z, q3.w);
        }

        if (cb < 2) {
            float pr[4] = {0.f, 0.f, 0.f, 0.f};
            #pragma unroll
            for (int rh = 0; rh < 2; rh++)
                #pragma unroll
                for (int nt = 0; nt < 8; nt++)
                    #pragma unroll
                    for (int u = 0; u < 4; u++) {
                        int col = cb * 64 + cw + nt * 8 + (u & 1);
                        int ni = rh * 2 + (u >> 1);
                        pr[ni] = fmaf(acc[rh][nt][u] + s_bk[col],
                                      s_q[(p * 8 + 4 * rb + ni) * QF + col], pr[ni]);
                    }
            #pragma unroll
            for (int ni = 0; ni < 4; ni++) {
                pr[ni] += __shfl_xor_sync(0xffffffffu, pr[ni], 1);
                pr[ni] += __shfl_xor_sync(0xffffffffu, pr[ni], 2);
            }
            if ((lane & 3) == 0) {
                #pragma unroll
                for (int ni = 0; ni < 4; ni++) {
                    float v = pr[ni];
                    v = (v >= 0.f) ? v : 0.2f * v;
                    s_att[((4 * rb + ni) * 8 + e) * 2 + cb] = v;
                }
            }
        }
        __syncthreads();

        if (tid < 16) {
            int n = tid >> 1, h = tid & 1;
            float mx = -1e30f;
            #pragma unroll
            for (int s = 0; s < MAIL; s++) mx = fmaxf(mx, s_att[(n * 8 + s) * 2 + h]);
            float ex[MAIL], sum = 0.f;
            #pragma unroll
            for (int s = 0; s < MAIL; s++) { ex[s] = __expf(s_att[(n * 8 + s) * 2 + h] - mx); sum += ex[s]; }
            float inv = 1.f / sum;
            #pragma unroll
            for (int s = 0; s < MAIL; s++) s_att[(n * 8 + s) * 2 + h] = ex[s] * inv;
        }
        __syncthreads();

        if (cb >= 2) {
            const int head = cb - 2;
            float v[2][8][4];
            #pragma unroll
            for (int rh = 0; rh < 2; rh++) {
                float attA = s_att[((4 * rb + 2 * rh + 0) * 8 + e) * 2 + head];
                float attB = s_att[((4 * rb + 2 * rh + 1) * 8 + e) * 2 + head];
                #pragma unroll
                for (int nt = 0; nt < 8; nt++) {
                    v[rh][nt][0] = acc[rh][nt][0] * attA;
                    v[rh][nt][1] = acc[rh][nt][1] * attA;
                    v[rh][nt][2] = acc[rh][nt][2] * attB;
                    v[rh][nt][3] = acc[rh][nt][3] * attB;
                }
            }
            #pragma unroll
            for (int rh = 0; rh < 2; rh++)
                #pragma unroll
                for (int nt = 0; nt < 8; nt++)
                    #pragma unroll
                    for (int u = 0; u < 4; u++) {
                        float x = v[rh][nt][u];
                        x += __shfl_xor_sync(0xffffffffu, x, 4);
                        x += __shfl_xor_sync(0xffffffffu, x, 8);
                        x += __shfl_xor_sync(0xffffffffu, x, 16);
                        v[rh][nt][u] = x;
                    }
            if (e == 0) {
                #pragma unroll
                for (int rh = 0; rh < 2; rh++)
                    #pragma unroll
                    for (int nt = 0; nt < 8; nt++)
                        #pragma unroll
                        for (int u = 0; u < 4; u++) {
                            int node = p * 8 + 4 * rb + 2 * rh + (u >> 1);
                            int ch = head * 64 + cw + nt * 8 + (u & 1);
                            s_out[node * 128 + ch] =
                                v[rh][nt][u] + s_bv[ch] + s_memf[node * 128 + ch];
                        }
            }
        }
        __syncthreads();
    }

    // ---- LayerNorm ----
    #pragma unroll
    for (int t = 0; t < 2; t++) {
        int n = warp * 2 + t;
        float4 x4 = ((float4*)(s_out + n * 128))[lane];
        float sum = x4.x + x4.y + x4.z + x4.w;
        float sq  = fmaf(x4.x, x4.x, fmaf(x4.y, x4.y, fmaf(x4.z, x4.z, x4.w * x4.w)));
        #pragma unroll
        for (int off = 16; off; off >>= 1) {
            sum += __shfl_xor_sync(0xffffffffu, sum, off);
            sq  += __shfl_xor_sync(0xffffffffu, sq, off);
        }
        float mu = sum * (1.f / 128.f);
        float rstd = rsqrtf(sq * (1.f / 128.f) - mu * mu + 1e-5f);
        float o[4] = {x4.x, x4.y, x4.z, x4.w};
        float y[4];
        #pragma unroll
        for (int u = 0; u < 4; u++) {
            int cc = lane * 4 + u;
            y[u] = (o[u] - mu) * rstd * __ldg(ln_g + cc) + __ldg(ln_b + cc);
        }
        uint32_t off0 = (uint32_t)(n * MHH + lane * 4) * 2;
        *(uint32_t*)(smem + OFF_MH + off0)     = pack_h2(y[0], y[1]);
        *(uint32_t*)(smem + OFF_MH + off0 + 4) = pack_h2(y[2], y[3]);
    }
    __syncthreads();

    // ---- MLP via MMA + ReLU + store ----
    {
        const int r = lane >> 2, cpos = 2 * (lane & 3);
        float qa0[4] = {0.f, 0.f, 0.f, 0.f}, qa1[4] = {0.f, 0.f, 0.f, 0.f};
        const uint2* wfm = (const uint2*)g_MlF + (uint32_t)warp * 512 + lane;
        #pragma unroll
        for (int ks = 0; ks < 8; ks++) {
            uint32_t ah0, ah1, ah2, ah3;
            ldsm4(mHa + (uint32_t)ks * 32, ah0, ah1, ah2, ah3);
            uint2 bh0 = __ldg(wfm + ks * 64);
            uint2 bh1 = __ldg(wfm + ks * 64 + 32);
            mma16816(qa0, ah0, ah1, ah2, ah3, bh0.x, bh0.y);
            mma16816(qa1, ah0, ah1, ah2, ah3, bh1.x, bh1.y);
        }
        int col = warp * 16 + cpos;
        float b0 = __ldg(mlp_b + col),     b1 = __ldg(mlp_b + col + 1);
        float b8 = __ldg(mlp_b + col + 8), b9 = __ldg(mlp_b + col + 9);
        int g0 = base + r, g1 = base + r + 8;
        if (g0 < size) {
            float2 v0 = { fmaxf(qa0[0] + b0, 0.f), fmaxf(qa0[1] + b1, 0.f) };
            float2 v1 = { fmaxf(qa1[0] + b8, 0.f), fmaxf(qa1[1] + b9, 0.f) };
            *(float2*)(out + (size_t)g0 * 128 + col)     = v0;
            *(float2*)(out + (size_t)g0 * 128 + col + 8) = v1;
        }
        if (g1 < size) {
            float2 v0 = { fmaxf(qa0[2] + b0, 0.f), fmaxf(qa0[3] + b1, 0.f) };
            float2 v1 = { fmaxf(qa1[2] + b8, 0.f), fmaxf(qa1[3] + b9, 0.f) };
            *(float2*)(out + (size_t)g1 * 128 + col)     = v0;
            *(float2*)(out + (size_t)g1 * 128 + col + 8) = v1;
        }
    }
}

extern "C" void kernel_launch(void* const* d_in, const int* in_sizes, int n_in,
                              void* d_out, int out_size) {
    const int*   nodes     = (const int*)  d_in[0];
    const float* times     = (const float*)d_in[1];
    const float* mem       = (const float*)d_in[2];
    const float* mail      = (const float*)d_in[3];
    const float* mail_time = (const float*)d_in[4];
    const float* time_w    = (const float*)d_in[5];
    const float* time_b    = (const float*)d_in[6];
    const float* wq_w      = (const float*)d_in[7];
    const float* wq_b      = (const float*)d_in[8];
    const float* wk_w      = (const float*)d_in[9];
    const float* wk_b      = (const float*)d_in[10];
    const float* wv_w      = (const float*)d_in[11];
    const float* wv_b      = (const float*)d_in[12];
    const float* mlp_w     = (const float*)d_in[13];
    const float* mlp_b     = (const float*)d_in[14];
    const float* ln_g      = (const float*)d_in[15];
    const float* ln_b      = (const float*)d_in[16];
    int size = in_sizes[0];

    cudaFuncSetAttribute(attn_mma_kernel,
                         cudaFuncAttributeMaxDynamicSharedMemorySize, SMEM_TOTAL);

    prep_weights<<<256, 256>>>(wq_w, wk_w, wv_w, mlp_w);

    int nblk = (size + NPB - 1) / NPB;
    attn_mma_kernel<<<nblk, NTHR, SMEM_TOTAL>>>(
        nodes, times, mem, mail, mail_time, time_w, time_b,
        wq_b, wk_b, wv_b, mlp_b, ln_g, ln_b,
        (float*)d_out, size);
}

// round 10
// speedup vs baseline: 11.0083x; 1.2338x over previous
#include <cuda_runtime.h>
#include <cuda_fp16.h>
#include <cstdint>
#include <math.h>

#define MAIL   8
#define DMEM   128
#define DCAT   256
#define NPB    16
#define ROWS   128
#define NTHR   256

#define AH 264             // A row stride in halves (132 words == 4 mod 32)
#define MHH 136            // MH row stride in halves
#define QF 132             // s_q float row stride

// ---- smem byte offsets ----
#define OFF_NODE 0
#define OFF_TIME 64
#define OFF_BK   128
#define OFF_BV   640
#define OFF_ATT  1152
#define OFF_DT   1664
#define OFF_MEM  2176                     // 16 x 128 f32 -> 10368
#define OFF_Q    10368                    // 16 x 132 f32 (s_out overlays) -> 18816
#define OFF_OUT  10368
#define OFF_MH   18816                    // 16 x 136 halves -> 23168
#define OFF_A    23168                    // 128 x 264 halves -> 90752
#define SMEM_TOTAL 90752

// Wk in coalesced mma B-frag order: uint4 idx = ((cb*16+ks)*4+j)*32+lane, cb 0..1
__device__ __align__(16) uint32_t g_BKf[16384 + 2048];
// Wv frags for the contracted V GEMM: uint32 idx = ((w*16+ks)*2+nt)*64+lane*2+breg
__device__ __align__(16) uint32_t g_VF[16384];
// Wq / mlp_w hi-only B-frags: idx = ((w*8+ks)*2+nt)*64 + lane*2 + breg
__device__ __align__(16) uint32_t g_WqF[8192];
__device__ __align__(16) uint32_t g_MlF[8192];

__device__ __forceinline__ uint32_t smem_u32(const void* p) {
    uint32_t a;
    asm("{ .reg .u64 t; cvta.to.shared.u64 t, %1; cvt.u32.u64 %0, t; }"
        : "=r"(a) : "l"(p));
    return a;
}
__device__ __forceinline__ void ldsm4(uint32_t addr, uint32_t& r0, uint32_t& r1,
                                      uint32_t& r2, uint32_t& r3) {
    asm volatile("ldmatrix.sync.aligned.m8n8.x4.shared.b16 {%0,%1,%2,%3}, [%4];"
                 : "=r"(r0), "=r"(r1), "=r"(r2), "=r"(r3) : "r"(addr));
}
__device__ __forceinline__ void mma16816(float* c, uint32_t a0, uint32_t a1,
                                         uint32_t a2, uint32_t a3,
                                         uint32_t b0, uint32_t b1) {
    asm volatile("mma.sync.aligned.m16n8k16.row.col.f32.f16.f16.f32 "
                 "{%0,%1,%2,%3},{%4,%5,%6,%7},{%8,%9},{%0,%1,%2,%3};"
                 : "+f"(c[0]), "+f"(c[1]), "+f"(c[2]), "+f"(c[3])
                 : "r"(a0), "r"(a1), "r"(a2), "r"(a3), "r"(b0), "r"(b1));
}
__device__ __forceinline__ uint32_t pack_h2(float x, float y) {
    __half2 h = __halves2half2(__float2half_rn(x), __float2half_rn(y));
    return *(uint32_t*)&h;
}

__global__ void prep_weights(const float* __restrict__ wq,
                             const float* __restrict__ wk,
                             const float* __restrict__ wv,
                             const float* __restrict__ mlp) {
    int i = blockIdx.x * 256 + threadIdx.x;           // 0..65535
    if (i < 16384) {
        // Wk coalesced frags
        int c    = i & 3;
        int lane = (i >> 2) & 31;
        int j    = (i >> 7) & 3;
        int ks   = (i >> 9) & 15;
        int cb   = (i >> 13) & 1;
        int nt   = j * 2 + (c >> 1);
        int b    = c & 1;
        int o  = cb * 64 + nt * 8 + (lane >> 2);      // Wk out channel 0..127
        int k0 = ks * 16 + b * 8 + (lane & 3) * 2;
        g_BKf[i] = pack_h2(wk[o * 256 + k0], wk[o * 256 + k0 + 1]);
    } else if (i < 32768) {
        // Wv frags (warp w = h*4+j owns 16 out cols)
        int jj = i - 16384;
        int breg = jj & 1, l = (jj >> 1) & 31;
        int nt = (jj >> 6) & 1, ks = (jj >> 7) & 15, w = (jj >> 11) & 7;
        int h = w >> 2, j = w & 3;
        int col = h * 64 + j * 16 + nt * 8 + (l >> 2);   // 0..127
        int k0  = ks * 16 + breg * 8 + (l & 3) * 2;
        g_VF[jj] = pack_h2(wv[col * 256 + k0], wv[col * 256 + k0 + 1]);
    } else if (i < 49152) {
        int j = i - 32768;
        const float* W = (j < 8192) ? wq : mlp;
        int jj = j & 8191;
        int breg = jj & 1, l = (jj >> 1) & 31;
        int nt = (jj >> 6) & 1, ks = (jj >> 7) & 7, w = (jj >> 10) & 7;
        int col = w * 16 + nt * 8 + (l >> 2);
        int k0  = ks * 16 + breg * 8 + (l & 3) * 2;
        uint32_t v = pack_h2(W[col * 128 + k0], W[col * 128 + k0 + 1]);
        if (j < 8192) g_WqF[jj] = v; else g_MlF[jj] = v;
    }
}

__global__ __launch_bounds__(NTHR, 2)
void attn_mma_kernel(
    const int*   __restrict__ nodes,
    const float* __restrict__ times,
    const float* __restrict__ mem,
    const float* __restrict__ mail,
    const float* __restrict__ mail_time,
    const float* __restrict__ time_w,
    const float* __restrict__ time_b,
    const float* __restrict__ wq_b,
    const float* __restrict__ wk_b,
    const float* __restrict__ wv_b,
    const float* __restrict__ mlp_b,
    const float* __restrict__ ln_g,
    const float* __restrict__ ln_b,
    float*       __restrict__ out,
    int size)
{
    extern __shared__ __align__(1024) char smem[];
    const uint32_t sb = smem_u32(smem);
    const int tid = threadIdx.x, warp = tid >> 5, lane = tid & 31;
    const int base = blockIdx.x * NPB;

    int*   s_node = (int*)(smem + OFF_NODE);
    float* s_time = (float*)(smem + OFF_TIME);
    float* s_bk   = (float*)(smem + OFF_BK);
    float* s_bv   = (float*)(smem + OFF_BV);
    float* s_att  = (float*)(smem + OFF_ATT);
    float* s_dt   = (float*)(smem + OFF_DT);
    float* s_memf = (float*)(smem + OFF_MEM);
    float* s_q    = (float*)(smem + OFF_Q);
    float* s_out  = (float*)(smem + OFF_OUT);

    if (tid < NPB) {
        int g = base + tid; if (g >= size) g = size - 1;
        s_node[tid] = nodes[g];
        s_time[tid] = times[g];
    }
    if (tid >= 128) { int c = tid - 128; s_bk[c] = wk_b[c]; s_bv[c] = wv_b[c]; }
    __syncthreads();

    if (tid < ROWS) {
        int n = tid >> 3, slot = tid & 7;
        s_dt[tid] = s_time[n] - __ldg(mail_time + (size_t)s_node[n] * MAIL + slot);
    }

    // gather mem rows (fp32) + hi fp16 copy into MH (16 rows)
    #pragma unroll
    for (int t = 0; t < 2; t++) {
        int idx = tid + t * NTHR;
        int n = idx >> 5, c4 = (idx & 31) * 4;
        float4 v = *(const float4*)(mem + (size_t)s_node[n] * DMEM + c4);
        ((float4*)s_memf)[idx] = v;
        uint32_t off = (uint32_t)(n * MHH + c4) * 2;
        *(uint32_t*)(smem + OFF_MH + off)     = pack_h2(v.x, v.y);
        *(uint32_t*)(smem + OFF_MH + off + 4) = pack_h2(v.z, v.w);
    }

    // mail half of A (fp16)
    {
        const int c4 = (tid & 31) * 4;
        #pragma unroll
        for (int t = 0; t < 16; t++) {
            int r = (tid >> 5) + t * 8;
            int n = r >> 3, slot = r & 7;
            float4 mv = *(const float4*)(mail + ((size_t)s_node[n] * MAIL + slot) * 128 + c4);
            uint32_t* dst = (uint32_t*)(smem + OFF_A + ((size_t)r * AH + c4) * 2);
            dst[0] = pack_h2(mv.x, mv.y);
            dst[1] = pack_h2(mv.z, mv.w);
        }
    }
    __syncthreads();

    // time-encode half of A
    {
        const int j = (tid & 63) * 2;
        const float tw0 = __ldg(time_w + j), tw1 = __ldg(time_w + j + 1);
        const float tb0 = __ldg(time_b + j), tb1 = __ldg(time_b + j + 1);
        #pragma unroll
        for (int t = 0; t < 32; t++) {
            int r = (tid >> 6) + t * 4;
            float dt = s_dt[r];
            float v0 = __cosf(fmaf(dt, tw0, tb0));
            float v1 = __cosf(fmaf(dt, tw1, tb1));
            *(uint32_t*)(smem + OFF_A + ((size_t)r * AH + 128 + j) * 2) = pack_h2(v0, v1);
        }
    }

    const int g8 = lane >> 3, lr = lane & 7;
    const uint32_t mrow = lr + ((g8 & 1) << 3);
    const uint32_t mko  = (uint32_t)((g8 >> 1) << 3);
    const uint32_t mHa  = sb + OFF_MH + (mrow * MHH + mko) * 2;

    // ---- Q via MMA: warp w -> cols [w*16, w*16+16) ----
    {
        const int r = lane >> 2, cpos = 2 * (lane & 3);
        float qa0[4] = {0.f, 0.f, 0.f, 0.f}, qa1[4] = {0.f, 0.f, 0.f, 0.f};
        const uint2* wfq = (const uint2*)g_WqF + (uint32_t)warp * 512 + lane;
        #pragma unroll
        for (int ks = 0; ks < 8; ks++) {
            uint32_t ah0, ah1, ah2, ah3;
            ldsm4(mHa + (uint32_t)ks * 32, ah0, ah1, ah2, ah3);
            uint2 bh0 = __ldg(wfq + ks * 64);
            uint2 bh1 = __ldg(wfq + ks * 64 + 32);
            mma16816(qa0, ah0, ah1, ah2, ah3, bh0.x, bh0.y);
            mma16816(qa1, ah0, ah1, ah2, ah3, bh1.x, bh1.y);
        }
        int col = warp * 16 + cpos;
        float b0 = __ldg(wq_b + col),     b1 = __ldg(wq_b + col + 1);
        float b8 = __ldg(wq_b + col + 8), b9 = __ldg(wq_b + col + 9);
        s_q[r * QF + col]           = qa0[0] + b0;
        s_q[r * QF + col + 1]       = qa0[1] + b1;
        s_q[(r + 8) * QF + col]     = qa0[2] + b0;
        s_q[(r + 8) * QF + col + 1] = qa0[3] + b1;
        s_q[r * QF + col + 8]       = qa1[0] + b8;
        s_q[r * QF + col + 9]       = qa1[1] + b9;
        s_q[(r + 8) * QF + col + 8] = qa1[2] + b8;
        s_q[(r + 8) * QF + col + 9] = qa1[3] + b9;
    }
    __syncthreads();

    // ---- K GEMM, single pass: warp (rb=warp>>1: 32-row block, cb=warp&1: head) ----
    const int rb = warp >> 1, cb = warp & 1;
    const int m0 = rb * 32;
    const int a_row = m0 + lr + ((g8 & 1) << 3);
    const int a_koff = (g8 >> 1) << 3;
    const int cw = 2 * (lane & 3);
    const int e  = lane >> 2;

    {
        const uint32_t aB = sb + OFF_A + ((uint32_t)a_row * AH + a_koff) * 2;
        const uint4* bfp = (const uint4*)g_BKf + (uint32_t)(cb * 16) * 128 + lane;

        float acc[2][8][4];
        #pragma unroll
        for (int rh = 0; rh < 2; rh++)
            #pragma unroll
            for (int t = 0; t < 8; t++)
                #pragma unroll
                for (int u = 0; u < 4; u++) acc[rh][t][u] = 0.f;

        #pragma unroll 4
        for (int ks = 0; ks < 16; ks++) {
            uint4 q0 = __ldg(bfp + 0);
            uint4 q1 = __ldg(bfp + 32);
            uint4 q2 = __ldg(bfp + 64);
            uint4 q3 = __ldg(bfp + 96);
            bfp += 128;
            uint32_t a0, a1, a2, a3, a4, a5, a6, a7;
            ldsm4(aB + ((uint32_t)ks * 16) * 2,             a0, a1, a2, a3);
            ldsm4(aB + ((uint32_t)(16 * AH + ks * 16)) * 2, a4, a5, a6, a7);
            mma16816(acc[0][0], a0, a1, a2, a3, q0.x, q0.y);
            mma16816(acc[0][1], a0, a1, a2, a3, q0.z, q0.w);
            mma16816(acc[0][2], a0, a1, a2, a3, q1.x, q1.y);
            mma16816(acc[0][3], a0, a1, a2, a3, q1.z, q1.w);
            mma16816(acc[0][4], a0, a1, a2, a3, q2.x, q2.y);
            mma16816(acc[0][5], a0, a1, a2, a3, q2.z, q2.w);
            mma16816(acc[0][6], a0, a1, a2, a3, q3.x, q3.y);
            mma16816(acc[0][7], a0, a1, a2, a3, q3.z, q3.w);
            mma16816(acc[1][0], a4, a5, a6, a7, q0.x, q0.y);
            mma16816(acc[1][1], a4, a5, a6, a7, q0.z, q0.w);
            mma16816(acc[1][2], a4, a5, a6, a7, q1.x, q1.y);
            mma16816(acc[1][3], a4, a5, a6, a7, q1.z, q1.w);
            mma16816(acc[1][4], a4, a5, a6, a7, q2.x, q2.y);
            mma16816(acc[1][5], a4, a5, a6, a7, q2.z, q2.w);
            mma16816(acc[1][6], a4, a5, a6, a7, q3.x, q3.y);
            mma16816(acc[1][7], a4, a5, a6, a7, q3.z, q3.w);
        }

        // logits: all 8 warps; head = cb, nodes 4rb..4rb+4, slot = e
        float pr[4] = {0.f, 0.f, 0.f, 0.f};
        #pragma unroll
        for (int rh = 0; rh < 2; rh++)
            #pragma unroll
            for (int nt = 0; nt < 8; nt++)
                #pragma unroll
                for (int u = 0; u < 4; u++) {
                    int col = cb * 64 + cw + nt * 8 + (u & 1);
                    int ni = rh * 2 + (u >> 1);
                    pr[ni] = fmaf(acc[rh][nt][u] + s_bk[col],
                                  s_q[(4 * rb + ni) * QF + col], pr[ni]);
                }
        #pragma unroll
        for (int ni = 0; ni < 4; ni++) {
            pr[ni] += __shfl_xor_sync(0xffffffffu, pr[ni], 1);
            pr[ni] += __shfl_xor_sync(0xffffffffu, pr[ni], 2);
        }
        if ((lane & 3) == 0) {
            #pragma unroll
            for (int ni = 0; ni < 4; ni++) {
                float v = pr[ni];
                v = (v >= 0.f) ? v : 0.2f * v;
                s_att[((4 * rb + ni) * 8 + e) * 2 + cb] = v;
            }
        }
    }
    __syncthreads();

    if (tid < 32) {                                  // softmax: 16 nodes x 2 heads
        int n = tid >> 1, h = tid & 1;
        float mx = -1e30f;
        #pragma unroll
        for (int s = 0; s < MAIL; s++) mx = fmaxf(mx, s_att[(n * 8 + s) * 2 + h]);
        float ex[MAIL], sum = 0.f;
        #pragma unroll
        for (int s = 0; s < MAIL; s++) { ex[s] = __expf(s_att[(n * 8 + s) * 2 + h] - mx); sum += ex[s]; }
        float inv = 1.f / sum;
        #pragma unroll
        for (int s = 0; s < MAIL; s++) s_att[(n * 8 + s) * 2 + h] = ex[s] * inv;
    }
    __syncthreads();

    // ---- contract mailbox: A'[h*16+n, :] = sum_s attn[n,s,h] * Mcat[n*8+s, :]
    //      hi rows 0..31, lo rows 32..63 (overwrite A after all reads) ----
    {
        const int rr = tid >> 3;                     // 0..31
        const int n = rr >> 1, h = rr & 1;
        const int c0 = tid & 7;                      // half2 phase (stride 8)
        float att[8];
        #pragma unroll
        for (int s = 0; s < 8; s++) att[s] = s_att[(n * 8 + s) * 2 + h];
        float2 ws[16];
        #pragma unroll
        for (int t = 0; t < 16; t++) { ws[t].x = 0.f; ws[t].y = 0.f; }
        #pragma unroll
        for (int s = 0; s < 8; s++) {
            const __half2* arow = (const __half2*)(smem + OFF_A + (size_t)(n * 8 + s) * AH * 2);
            float a = att[s];
            #pragma unroll
            for (int t = 0; t < 16; t++) {
                float2 v = __half22float2(arow[c0 + t * 8]);
                ws[t].x = fmaf(a, v.x, ws[t].x);
                ws[t].y = fmaf(a, v.y, ws[t].y);
            }
        }
        __syncthreads();                             // all Mcat reads complete
        uint32_t hiB = (uint32_t)(h * 16 + n) * AH * 2;
        uint32_t loB = (uint32_t)(32 + h * 16 + n) * AH * 2;
        #pragma unroll
        for (int t = 0; t < 16; t++) {
            float hx = __half2float(__float2half_rn(ws[t].x));
            float hy = __half2float(__float2half_rn(ws[t].y));
            uint32_t off = (uint32_t)(c0 + t * 8) * 4;
            *(uint32_t*)(smem + OFF_A + hiB + off) = pack_h2(ws[t].x, ws[t].y);
            *(uint32_t*)(smem + OFF_A + loB + off) = pack_h2(ws[t].x - hx, ws[t].y - hy);
        }
    }
    __syncthreads();

    // ---- V GEMM on contracted rows: warp w -> head h=w>>2, cols j*16 ----
    {
        const int h = warp >> 2, j = warp & 3;
        const uint32_t aHi = sb + OFF_A + (((uint32_t)(h * 16) + mrow) * AH + mko) * 2;
        const uint32_t aLo = aHi + 32 * AH * 2;
        float qa0[4] = {0.f, 0.f, 0.f, 0.f}, qa1[4] = {0.f, 0.f, 0.f, 0.f};
        const uint2* wfv = (const uint2*)g_VF + (uint32_t)warp * 1024 + lane;
        #pragma unroll
        for (int ks = 0; ks < 16; ks++) {
            uint32_t h0, h1, h2, h3, l0, l1, l2, l3;
            ldsm4(aHi + (uint32_t)ks * 32, h0, h1, h2, h3);
            ldsm4(aLo + (uint32_t)ks * 32, l0, l1, l2, l3);
            uint2 b0 = __ldg(wfv + ks * 64);
            uint2 b1 = __ldg(wfv + ks * 64 + 32);
            mma16816(qa0, h0, h1, h2, h3, b0.x, b0.y);
            mma16816(qa0, l0, l1, l2, l3, b0.x, b0.y);
            mma16816(qa1, h0, h1, h2, h3, b1.x, b1.y);
            mma16816(qa1, l0, l1, l2, l3, b1.x, b1.y);
        }
        // epilogue: node = row, col = h*64 + j*16 + ...
        const int r = lane >> 2, cpos = 2 * (lane & 3);
        int col = h * 64 + j * 16 + cpos;
        #pragma unroll
        for (int half = 0; half < 2; half++) {
            int node = r + half * 8;
            float v0 = (half ? qa0[2] : qa0[0]) + s_bv[col]     + s_memf[node * 128 + col];
            float v1 = (half ? qa0[3] : qa0[1]) + s_bv[col + 1] + s_memf[node * 128 + col + 1];
            float v8 = (half ? qa1[2] : qa1[0]) + s_bv[col + 8] + s_memf[node * 128 + col + 8];
            float v9 = (half ? qa1[3] : qa1[1]) + s_bv[col + 9] + s_memf[node * 128 + col + 9];
            s_out[node * 128 + col]     = v0;
            s_out[node * 128 + col + 1] = v1;
            s_out[node * 128 + col + 8] = v8;
            s_out[node * 128 + col + 9] = v9;
        }
    }
    __syncthreads();

    // ---- LayerNorm: warp handles 2 nodes; writes hi fp16 into MH ----
    #pragma unroll
    for (int t = 0; t < 2; t++) {
        int n = warp * 2 + t;
        float4 x4 = ((float4*)(s_out + n * 128))[lane];
        float sum = x4.x + x4.y + x4.z + x4.w;
        float sq  = fmaf(x4.x, x4.x, fmaf(x4.y, x4.y, fmaf(x4.z, x4.z, x4.w * x4.w)));
        #pragma unroll
        for (int off = 16; off; off >>= 1) {
            sum += __shfl_xor_sync(0xffffffffu, sum, off);
            sq  += __shfl_xor_sync(0xffffffffu, sq, off);
        }
        float mu = sum * (1.f / 128.f);
        float rstd = rsqrtf(sq * (1.f / 128.f) - mu * mu + 1e-5f);
        float o[4] = {x4.x, x4.y, x4.z, x4.w};
        float y[4];
        #pragma unroll
        for (int u = 0; u < 4; u++) {
            int cc = lane * 4 + u;
            y[u] = (o[u] - mu) * rstd * __ldg(ln_g + cc) + __ldg(ln_b + cc);
        }
        uint32_t off0 = (uint32_t)(n * MHH + lane * 4) * 2;
        *(uint32_t*)(smem + OFF_MH + off0)     = pack_h2(y[0], y[1]);
        *(uint32_t*)(smem + OFF_MH + off0 + 4) = pack_h2(y[2], y[3]);
    }
    __syncthreads();

    // ---- MLP via MMA + ReLU + store ----
    {
        const int r = lane >> 2, cpos = 2 * (lane & 3);
        float qa0[4] = {0.f, 0.f, 0.f, 0.f}, qa1[4] = {0.f, 0.f, 0.f, 0.f};
        const uint2* wfm = (const uint2*)g_MlF + (uint32_t)warp * 512 + lane;
        #pragma unroll
        for (int ks = 0; ks < 8; ks++) {
            uint32_t ah0, ah1, ah2, ah3;
            ldsm4(mHa + (uint32_t)ks * 32, ah0, ah1, ah2, ah3);
            uint2 bh0 = __ldg(wfm + ks * 64);
            uint2 bh1 = __ldg(wfm + ks * 64 + 32);
            mma16816(qa0, ah0, ah1, ah2, ah3, bh0.x, bh0.y);
            mma16816(qa1, ah0, ah1, ah2, ah3, bh1.x, bh1.y);
        }
        int col = warp * 16 + cpos;
        float b0 = __ldg(mlp_b + col),     b1 = __ldg(mlp_b + col + 1);
        float b8 = __ldg(mlp_b + col + 8), b9 = __ldg(mlp_b + col + 9);
        int g0 = base + r, g1 = base + r + 8;
        if (g0 < size) {
            float2 v0 = { fmaxf(qa0[0] + b0, 0.f), fmaxf(qa0[1] + b1, 0.f) };
            float2 v1 = { fmaxf(qa1[0] + b8, 0.f), fmaxf(qa1[1] + b9, 0.f) };
            *(float2*)(out + (size_t)g0 * 128 + col)     = v0;
            *(float2*)(out + (size_t)g0 * 128 + col + 8) = v1;
        }
        if (g1 < size) {
            float2 v0 = { fmaxf(qa0[2] + b0, 0.f), fmaxf(qa0[3] + b1, 0.f) };
            float2 v1 = { fmaxf(qa1[2] + b8, 0.f), fmaxf(qa1[3] + b9, 0.f) };
            *(float2*)(out + (size_t)g1 * 128 + col)     = v0;
            *(float2*)(out + (size_t)g1 * 128 + col + 8) = v1;
        }
    }
}

extern "C" void kernel_launch(void* const* d_in, const int* in_sizes, int n_in,
                              void* d_out, int out_size) {
    const int*   nodes     = (const int*)  d_in[0];
    const float* times     = (const float*)d_in[1];
    const float* mem       = (const float*)d_in[2];
    const float* mail      = (const float*)d_in[3];
    const float* mail_time = (const float*)d_in[4];
    const float* time_w    = (const float*)d_in[5];
    const float* time_b    = (const float*)d_in[6];
    const float* wq_w      = (const float*)d_in[7];
    const float* wq_b      = (const float*)d_in[8];
    const float* wk_w      = (const float*)d_in[9];
    const float* wk_b      = (const float*)d_in[10];
    const float* wv_w      = (const float*)d_in[11];
    const float* wv_b      = (const float*)d_in[12];
    const float* mlp_w     = (const float*)d_in[13];
    const float* mlp_b     = (const float*)d_in[14];
    const float* ln_g      = (const float*)d_in[15];
    const float* ln_b      = (const float*)d_in[16];
    int size = in_sizes[0];

    cudaFuncSetAttribute(attn_mma_kernel,
                         cudaFuncAttributeMaxDynamicSharedMemorySize, SMEM_TOTAL);

    prep_weights<<<256, 256>>>(wq_w, wk_w, wv_w, mlp_w);

    int nblk = (size + NPB - 1) / NPB;
    attn_mma_kernel<<<nblk, NTHR, SMEM_TOTAL>>>(
        nodes, times, mem, mail, mail_time, time_w, time_b,
        wq_b, wk_b, wv_b, mlp_b, ln_g, ln_b,
        (float*)d_out, size);
}

// round 11
// speedup vs baseline: 12.3276x; 1.1198x over previous
#include <cuda_runtime.h>
#include <cuda_fp16.h>
#include <cstdint>
#include <math.h>

#define MAIL   8
#define DMEM   128
#define DCAT   256
#define NPB    16
#define ROWS   128
#define NTHR   256

#define AH 264             // A row stride in halves
#define MHH 136            // MH row stride in halves
#define QF 132             // s_q float row stride

// ---- smem byte offsets ----
#define OFF_NODE 0
#define OFF_TIME 64
#define OFF_BK   128
#define OFF_BV   640
#define OFF_ATT  1152
#define OFF_DT   1664
#define OFF_MEM  2176                     // 16 x 128 f32 -> 10368
#define OFF_Q    10368                    // 16 x 132 f32 (s_out overlays) -> 18816
#define OFF_OUT  10368
#define OFF_MH   18816                    // 16 x 136 halves -> 23168
#define OFF_A    23168                    // 128 x 264 halves -> 90752
#define SMEM_TOTAL 90752

// Wk in coalesced mma B-frag order: uint4 idx = ((cb*16+ks)*4+j)*32+lane, cb 0..1
__device__ __align__(16) uint32_t g_BKf[16384 + 2048];
// Wv frags: uint32 idx = ((w*16+ks)*2+nt)*64+lane*2+breg
__device__ __align__(16) uint32_t g_VF[16384];
// Wq / mlp_w hi-only B-frags: idx = ((w*8+ks)*2+nt)*64 + lane*2 + breg
__device__ __align__(16) uint32_t g_WqF[8192];
__device__ __align__(16) uint32_t g_MlF[8192];

__device__ __forceinline__ uint32_t smem_u32(const void* p) {
    uint32_t a;
    asm("{ .reg .u64 t; cvta.to.shared.u64 t, %1; cvt.u32.u64 %0, t; }"
        : "=r"(a) : "l"(p));
    return a;
}
__device__ __forceinline__ void ldsm4(uint32_t addr, uint32_t& r0, uint32_t& r1,
                                      uint32_t& r2, uint32_t& r3) {
    asm volatile("ldmatrix.sync.aligned.m8n8.x4.shared.b16 {%0,%1,%2,%3}, [%4];"
                 : "=r"(r0), "=r"(r1), "=r"(r2), "=r"(r3) : "r"(addr));
}
__device__ __forceinline__ void mma16816(float* c, uint32_t a0, uint32_t a1,
                                         uint32_t a2, uint32_t a3,
                                         uint32_t b0, uint32_t b1) {
    asm volatile("mma.sync.aligned.m16n8k16.row.col.f32.f16.f16.f32 "
                 "{%0,%1,%2,%3},{%4,%5,%6,%7},{%8,%9},{%0,%1,%2,%3};"
                 : "+f"(c[0]), "+f"(c[1]), "+f"(c[2]), "+f"(c[3])
                 : "r"(a0), "r"(a1), "r"(a2), "r"(a3), "r"(b0), "r"(b1));
}
__device__ __forceinline__ uint32_t pack_h2(float x, float y) {
    __half2 h = __halves2half2(__float2half_rn(x), __float2half_rn(y));
    return *(uint32_t*)&h;
}

__global__ void prep_weights(const float* __restrict__ wq,
                             const float* __restrict__ wk,
                             const float* __restrict__ wv,
                             const float* __restrict__ mlp) {
    int i = blockIdx.x * 256 + threadIdx.x;           // 0..65535
    if (i < 16384) {
        int c    = i & 3;
        int lane = (i >> 2) & 31;
        int j    = (i >> 7) & 3;
        int ks   = (i >> 9) & 15;
        int cb   = (i >> 13) & 1;
        int nt   = j * 2 + (c >> 1);
        int b    = c & 1;
        int o  = cb * 64 + nt * 8 + (lane >> 2);
        int k0 = ks * 16 + b * 8 + (lane & 3) * 2;
        g_BKf[i] = pack_h2(wk[o * 256 + k0], wk[o * 256 + k0 + 1]);
    } else if (i < 32768) {
        int jj = i - 16384;
        int breg = jj & 1, l = (jj >> 1) & 31;
        int nt = (jj >> 6) & 1, ks = (jj >> 7) & 15, w = (jj >> 11) & 7;
        int h = w >> 2, j = w & 3;
        int col = h * 64 + j * 16 + nt * 8 + (l >> 2);
        int k0  = ks * 16 + breg * 8 + (l & 3) * 2;
        g_VF[jj] = pack_h2(wv[col * 256 + k0], wv[col * 256 + k0 + 1]);
    } else if (i < 49152) {
        int j = i - 32768;
        const float* W = (j < 8192) ? wq : mlp;
        int jj = j & 8191;
        int breg = jj & 1, l = (jj >> 1) & 31;
        int nt = (jj >> 6) & 1, ks = (jj >> 7) & 7, w = (jj >> 10) & 7;
        int col = w * 16 + nt * 8 + (l >> 2);
        int k0  = ks * 16 + breg * 8 + (l & 3) * 2;
        uint32_t v = pack_h2(W[col * 128 + k0], W[col * 128 + k0 + 1]);
        if (j < 8192) g_WqF[jj] = v; else g_MlF[jj] = v;
    }
}

__global__ __launch_bounds__(NTHR, 2)
void attn_mma_kernel(
    const int*   __restrict__ nodes,
    const float* __restrict__ times,
    const float* __restrict__ mem,
    const float* __restrict__ mail,
    const float* __restrict__ mail_time,
    const float* __restrict__ time_w,
    const float* __restrict__ time_b,
    const float* __restrict__ wq_b,
    const float* __restrict__ wk_b,
    const float* __restrict__ wv_b,
    const float* __restrict__ mlp_b,
    const float* __restrict__ ln_g,
    const float* __restrict__ ln_b,
    float*       __restrict__ out,
    int size)
{
    extern __shared__ __align__(1024) char smem[];
    const uint32_t sb = smem_u32(smem);
    const int tid = threadIdx.x, warp = tid >> 5, lane = tid & 31;
    const int base = blockIdx.x * NPB;

    int*   s_node = (int*)(smem + OFF_NODE);
    float* s_time = (float*)(smem + OFF_TIME);
    float* s_bk   = (float*)(smem + OFF_BK);
    float* s_bv   = (float*)(smem + OFF_BV);
    float* s_att  = (float*)(smem + OFF_ATT);
    float* s_dt   = (float*)(smem + OFF_DT);
    float* s_memf = (float*)(smem + OFF_MEM);
    float* s_q    = (float*)(smem + OFF_Q);
    float* s_out  = (float*)(smem + OFF_OUT);

    if (tid < NPB) {
        int g = base + tid; if (g >= size) g = size - 1;
        s_node[tid] = nodes[g];
        s_time[tid] = times[g];
    }
    if (tid >= 128) { int c = tid - 128; s_bk[c] = wk_b[c]; s_bv[c] = wv_b[c]; }
    __syncthreads();

    if (tid < ROWS) {
        int n = tid >> 3, slot = tid & 7;
        s_dt[tid] = s_time[n] - __ldg(mail_time + (size_t)s_node[n] * MAIL + slot);
    }

    // gather mem rows (fp32) + hi fp16 copy into MH (16 rows)
    #pragma unroll
    for (int t = 0; t < 2; t++) {
        int idx = tid + t * NTHR;
        int n = idx >> 5, c4 = (idx & 31) * 4;
        float4 v = *(const float4*)(mem + (size_t)s_node[n] * DMEM + c4);
        ((float4*)s_memf)[idx] = v;
        uint32_t off = (uint32_t)(n * MHH + c4) * 2;
        *(uint32_t*)(smem + OFF_MH + off)     = pack_h2(v.x, v.y);
        *(uint32_t*)(smem + OFF_MH + off + 4) = pack_h2(v.z, v.w);
    }

    // mail half of A (fp16)
    {
        const int c4 = (tid & 31) * 4;
        #pragma unroll
        for (int t = 0; t < 16; t++) {
            int r = (tid >> 5) + t * 8;
            int n = r >> 3, slot = r & 7;
            float4 mv = *(const float4*)(mail + ((size_t)s_node[n] * MAIL + slot) * 128 + c4);
            uint32_t* dst = (uint32_t*)(smem + OFF_A + ((size_t)r * AH + c4) * 2);
            dst[0] = pack_h2(mv.x, mv.y);
            dst[1] = pack_h2(mv.z, mv.w);
        }
    }
    __syncthreads();

    // time-encode half of A
    {
        const int j = (tid & 63) * 2;
        const float tw0 = __ldg(time_w + j), tw1 = __ldg(time_w + j + 1);
        const float tb0 = __ldg(time_b + j), tb1 = __ldg(time_b + j + 1);
        #pragma unroll
        for (int t = 0; t < 32; t++) {
            int r = (tid >> 6) + t * 4;
            float dt = s_dt[r];
            float v0 = __cosf(fmaf(dt, tw0, tb0));
            float v1 = __cosf(fmaf(dt, tw1, tb1));
            *(uint32_t*)(smem + OFF_A + ((size_t)r * AH + 128 + j) * 2) = pack_h2(v0, v1);
        }
    }

    const int g8 = lane >> 3, lr = lane & 7;
    const uint32_t mrow = lr + ((g8 & 1) << 3);
    const uint32_t mko  = (uint32_t)((g8 >> 1) << 3);
    const uint32_t mHa  = sb + OFF_MH + (mrow * MHH + mko) * 2;

    // ---- Q via MMA: warp w -> cols [w*16, w*16+16) ----
    {
        const int r = lane >> 2, cpos = 2 * (lane & 3);
        float qa0[4] = {0.f, 0.f, 0.f, 0.f}, qa1[4] = {0.f, 0.f, 0.f, 0.f};
        const uint2* wfq = (const uint2*)g_WqF + (uint32_t)warp * 512 + lane;
        #pragma unroll
        for (int ks = 0; ks < 8; ks++) {
            uint32_t ah0, ah1, ah2, ah3;
            ldsm4(mHa + (uint32_t)ks * 32, ah0, ah1, ah2, ah3);
            uint2 bh0 = __ldg(wfq + ks * 64);
            uint2 bh1 = __ldg(wfq + ks * 64 + 32);
            mma16816(qa0, ah0, ah1, ah2, ah3, bh0.x, bh0.y);
            mma16816(qa1, ah0, ah1, ah2, ah3, bh1.x, bh1.y);
        }
        int col = warp * 16 + cpos;
        float b0 = __ldg(wq_b + col),     b1 = __ldg(wq_b + col + 1);
        float b8 = __ldg(wq_b + col + 8), b9 = __ldg(wq_b + col + 9);
        s_q[r * QF + col]           = qa0[0] + b0;
        s_q[r * QF + col + 1]       = qa0[1] + b1;
        s_q[(r + 8) * QF + col]     = qa0[2] + b0;
        s_q[(r + 8) * QF + col + 1] = qa0[3] + b1;
        s_q[r * QF + col + 8]       = qa1[0] + b8;
        s_q[r * QF + col + 9]       = qa1[1] + b9;
        s_q[(r + 8) * QF + col + 8] = qa1[2] + b8;
        s_q[(r + 8) * QF + col + 9] = qa1[3] + b9;
    }
    __syncthreads();

    // ---- K GEMM, single pass: rb = 32-row block, cb = head ----
    const int rb = warp >> 1, cb = warp & 1;
    const int m0 = rb * 32;
    const int a_row = m0 + lr + ((g8 & 1) << 3);
    const int a_koff = (g8 >> 1) << 3;
    const int cw = 2 * (lane & 3);
    const int e  = lane >> 2;

    {
        const uint32_t aB = sb + OFF_A + ((uint32_t)a_row * AH + a_koff) * 2;
        const uint4* bfp = (const uint4*)g_BKf + (uint32_t)(cb * 16) * 128 + lane;

        float acc[2][8][4];
        #pragma unroll
        for (int rh = 0; rh < 2; rh++)
            #pragma unroll
            for (int t = 0; t < 8; t++)
                #pragma unroll
                for (int u = 0; u < 4; u++) acc[rh][t][u] = 0.f;

        #pragma unroll 4
        for (int ks = 0; ks < 16; ks++) {
            uint4 q0 = __ldg(bfp + 0);
            uint4 q1 = __ldg(bfp + 32);
            uint4 q2 = __ldg(bfp + 64);
            uint4 q3 = __ldg(bfp + 96);
            bfp += 128;
            uint32_t a0, a1, a2, a3, a4, a5, a6, a7;
            ldsm4(aB + ((uint32_t)ks * 16) * 2,             a0, a1, a2, a3);
            ldsm4(aB + ((uint32_t)(16 * AH + ks * 16)) * 2, a4, a5, a6, a7);
            mma16816(acc[0][0], a0, a1, a2, a3, q0.x, q0.y);
            mma16816(acc[0][1], a0, a1, a2, a3, q0.z, q0.w);
            mma16816(acc[0][2], a0, a1, a2, a3, q1.x, q1.y);
            mma16816(acc[0][3], a0, a1, a2, a3, q1.z, q1.w);
            mma16816(acc[0][4], a0, a1, a2, a3, q2.x, q2.y);
            mma16816(acc[0][5], a0, a1, a2, a3, q2.z, q2.w);
            mma16816(acc[0][6], a0, a1, a2, a3, q3.x, q3.y);
            mma16816(acc[0][7], a0, a1, a2, a3, q3.z, q3.w);
            mma16816(acc[1][0], a4, a5, a6, a7, q0.x, q0.y);
            mma16816(acc[1][1], a4, a5, a6, a7, q0.z, q0.w);
            mma16816(acc[1][2], a4, a5, a6, a7, q1.x, q1.y);
            mma16816(acc[1][3], a4, a5, a6, a7, q1.z, q1.w);
            mma16816(acc[1][4], a4, a5, a6, a7, q2.x, q2.y);
            mma16816(acc[1][5], a4, a5, a6, a7, q2.z, q2.w);
            mma16816(acc[1][6], a4, a5, a6, a7, q3.x, q3.y);
            mma16816(acc[1][7], a4, a5, a6, a7, q3.z, q3.w);
        }

        float pr[4] = {0.f, 0.f, 0.f, 0.f};
        #pragma unroll
        for (int rh = 0; rh < 2; rh++)
            #pragma unroll
            for (int nt = 0; nt < 8; nt++)
                #pragma unroll
                for (int u = 0; u < 4; u++) {
                    int col = cb * 64 + cw + nt * 8 + (u & 1);
                    int ni = rh * 2 + (u >> 1);
                    pr[ni] = fmaf(acc[rh][nt][u] + s_bk[col],
                                  s_q[(4 * rb + ni) * QF + col], pr[ni]);
                }
        #pragma unroll
        for (int ni = 0; ni < 4; ni++) {
            pr[ni] += __shfl_xor_sync(0xffffffffu, pr[ni], 1);
            pr[ni] += __shfl_xor_sync(0xffffffffu, pr[ni], 2);
        }
        if ((lane & 3) == 0) {
            #pragma unroll
            for (int ni = 0; ni < 4; ni++) {
                float v = pr[ni];
                v = (v >= 0.f) ? v : 0.2f * v;
                s_att[((4 * rb + ni) * 8 + e) * 2 + cb] = v;
            }
        }
    }
    __syncthreads();

    if (tid < 32) {                                  // softmax: 16 nodes x 2 heads
        int n = tid >> 1, h = tid & 1;
        float mx = -1e30f;
        #pragma unroll
        for (int s = 0; s < MAIL; s++) mx = fmaxf(mx, s_att[(n * 8 + s) * 2 + h]);
        float ex[MAIL], sum = 0.f;
        #pragma unroll
        for (int s = 0; s < MAIL; s++) { ex[s] = __expf(s_att[(n * 8 + s) * 2 + h] - mx); sum += ex[s]; }
        float inv = 1.f / sum;
        #pragma unroll
        for (int s = 0; s < MAIL; s++) s_att[(n * 8 + s) * 2 + h] = ex[s] * inv;
    }
    __syncthreads();

    // ---- contract mailbox, BOTH heads per thread (Mcat read once):
    //      A'[h*16+n, :] = sum_s attn[n,s,h] * Mcat[n*8+s, :], hi fp16 only ----
    {
        const int n  = tid >> 4;                     // 0..15
        const int c0 = tid & 15;                     // half2 phase (stride 16)
        float a0[MAIL], a1[MAIL];
        #pragma unroll
        for (int s = 0; s < MAIL; s++) {
            a0[s] = s_att[(n * 8 + s) * 2 + 0];
            a1[s] = s_att[(n * 8 + s) * 2 + 1];
        }
        float2 w0[8], w1[8];
        #pragma unroll
        for (int t = 0; t < 8; t++) {
            w0[t].x = 0.f; w0[t].y = 0.f;
            w1[t].x = 0.f; w1[t].y = 0.f;
        }
        #pragma unroll
        for (int s = 0; s < MAIL; s++) {
            const __half2* arow = (const __half2*)(smem + OFF_A + (size_t)(n * 8 + s) * AH * 2);
            #pragma unroll
            for (int t = 0; t < 8; t++) {
                float2 v = __half22float2(arow[c0 + t * 16]);
                w0[t].x = fmaf(a0[s], v.x, w0[t].x);
                w0[t].y = fmaf(a0[s], v.y, w0[t].y);
                w1[t].x = fmaf(a1[s], v.x, w1[t].x);
                w1[t].y = fmaf(a1[s], v.y, w1[t].y);
            }
        }
        __syncthreads();                             // all Mcat reads complete
        uint32_t h0B = (uint32_t)n * AH * 2;
        uint32_t h1B = (uint32_t)(16 + n) * AH * 2;
        #pragma unroll
        for (int t = 0; t < 8; t++) {
            uint32_t off = (uint32_t)(c0 + t * 16) * 4;
            *(uint32_t*)(smem + OFF_A + h0B + off) = pack_h2(w0[t].x, w0[t].y);
            *(uint32_t*)(smem + OFF_A + h1B + off) = pack_h2(w1[t].x, w1[t].y);
        }
    }
    __syncthreads();

    // ---- V GEMM on contracted rows (hi only): warp w -> head h=w>>2, cols j*16 ----
    {
        const int h = warp >> 2, j = warp & 3;
        const uint32_t aHi = sb + OFF_A + (((uint32_t)(h * 16) + mrow) * AH + mko) * 2;
        float qa0[4] = {0.f, 0.f, 0.f, 0.f}, qa1[4] = {0.f, 0.f, 0.f, 0.f};
        const uint2* wfv = (const uint2*)g_VF + (uint32_t)warp * 1024 + lane;
        #pragma unroll
        for (int ks = 0; ks < 16; ks++) {
            uint32_t h0, h1, h2, h3;
            ldsm4(aHi + (uint32_t)ks * 32, h0, h1, h2, h3);
            uint2 b0 = __ldg(wfv + ks * 64);
            uint2 b1 = __ldg(wfv + ks * 64 + 32);
            mma16816(qa0, h0, h1, h2, h3, b0.x, b0.y);
            mma16816(qa1, h0, h1, h2, h3, b1.x, b1.y);
        }
        const int r = lane >> 2, cpos = 2 * (lane & 3);
        int col = h * 64 + j * 16 + cpos;
        #pragma unroll
        for (int half = 0; half < 2; half++) {
            int node = r + half * 8;
            float v0 = (half ? qa0[2] : qa0[0]) + s_bv[col]     + s_memf[node * 128 + col];
            float v1 = (half ? qa0[3] : qa0[1]) + s_bv[col + 1] + s_memf[node * 128 + col + 1];
            float v8 = (half ? qa1[2] : qa1[0]) + s_bv[col + 8] + s_memf[node * 128 + col + 8];
            float v9 = (half ? qa1[3] : qa1[1]) + s_bv[col + 9] + s_memf[node * 128 + col + 9];
            s_out[node * 128 + col]     = v0;
            s_out[node * 128 + col + 1] = v1;
            s_out[node * 128 + col + 8] = v8;
            s_out[node * 128 + col + 9] = v9;
        }
    }
    __syncthreads();

    // ---- LayerNorm: warp handles 2 nodes; writes hi fp16 into MH ----
    #pragma unroll
    for (int t = 0; t < 2; t++) {
        int n = warp * 2 + t;
        float4 x4 = ((float4*)(s_out + n * 128))[lane];
        float sum = x4.x + x4.y + x4.z + x4.w;
        float sq  = fmaf(x4.x, x4.x, fmaf(x4.y, x4.y, fmaf(x4.z, x4.z, x4.w * x4.w)));
        #pragma unroll
        for (int off = 16; off; off >>= 1) {
            sum += __shfl_xor_sync(0xffffffffu, sum, off);
            sq  += __shfl_xor_sync(0xffffffffu, sq, off);
        }
        float mu = sum * (1.f / 128.f);
        float rstd = rsqrtf(sq * (1.f / 128.f) - mu * mu + 1e-5f);
        float o[4] = {x4.x, x4.y, x4.z, x4.w};
        float y[4];
        #pragma unroll
        for (int u = 0; u < 4; u++) {
            int cc = lane * 4 + u;
            y[u] = (o[u] - mu) * rstd * __ldg(ln_g + cc) + __ldg(ln_b + cc);
        }
        uint32_t off0 = (uint32_t)(n * MHH + lane * 4) * 2;
        *(uint32_t*)(smem + OFF_MH + off0)     = pack_h2(y[0], y[1]);
        *(uint32_t*)(smem + OFF_MH + off0 + 4) = pack_h2(y[2], y[3]);
    }
    __syncthreads();

    // ---- MLP via MMA + ReLU + store ----
    {
        const int r = lane >> 2, cpos = 2 * (lane & 3);
        float qa0[4] = {0.f, 0.f, 0.f, 0.f}, qa1[4] = {0.f, 0.f, 0.f, 0.f};
        const uint2* wfm = (const uint2*)g_MlF + (uint32_t)warp * 512 + lane;
        #pragma unroll
        for (int ks = 0; ks < 8; ks++) {
            uint32_t ah0, ah1, ah2, ah3;
            ldsm4(mHa + (uint32_t)ks * 32, ah0, ah1, ah2, ah3);
            uint2 bh0 = __ldg(wfm + ks * 64);
            uint2 bh1 = __ldg(wfm + ks * 64 + 32);
            mma16816(qa0, ah0, ah1, ah2, ah3, bh0.x, bh0.y);
            mma16816(qa1, ah0, ah1, ah2, ah3, bh1.x, bh1.y);
        }
        int col = warp * 16 + cpos;
        float b0 = __ldg(mlp_b + col),     b1 = __ldg(mlp_b + col + 1);
        float b8 = __ldg(mlp_b + col + 8), b9 = __ldg(mlp_b + col + 9);
        int g0 = base + r, g1 = base + r + 8;
        if (g0 < size) {
            float2 v0 = { fmaxf(qa0[0] + b0, 0.f), fmaxf(qa0[1] + b1, 0.f) };
            float2 v1 = { fmaxf(qa1[0] + b8, 0.f), fmaxf(qa1[1] + b9, 0.f) };
            *(float2*)(out + (size_t)g0 * 128 + col)     = v0;
            *(float2*)(out + (size_t)g0 * 128 + col + 8) = v1;
        }
        if (g1 < size) {
            float2 v0 = { fmaxf(qa0[2] + b0, 0.f), fmaxf(qa0[3] + b1, 0.f) };
            float2 v1 = { fmaxf(qa1[2] + b8, 0.f), fmaxf(qa1[3] + b9, 0.f) };
            *(float2*)(out + (size_t)g1 * 128 + col)     = v0;
            *(float2*)(out + (size_t)g1 * 128 + col + 8) = v1;
        }
    }
}

extern "C" void kernel_launch(void* const* d_in, const int* in_sizes, int n_in,
                              void* d_out, int out_size) {
    const int*   nodes     = (const int*)  d_in[0];
    const float* times     = (const float*)d_in[1];
    const float* mem       = (const float*)d_in[2];
    const float* mail      = (const float*)d_in[3];
    const float* mail_time = (const float*)d_in[4];
    const float* time_w    = (const float*)d_in[5];
    const float* time_b    = (const float*)d_in[6];
    const float* wq_w      = (const float*)d_in[7];
    const float* wq_b      = (const float*)d_in[8];
    const float* wk_w      = (const float*)d_in[9];
    const float* wk_b      = (const float*)d_in[10];
    const float* wv_w      = (const float*)d_in[11];
    const float* wv_b      = (const float*)d_in[12];
    const float* mlp_w     = (const float*)d_in[13];
    const float* mlp_b     = (const float*)d_in[14];
    const float* ln_g      = (const float*)d_in[15];
    const float* ln_b      = (const float*)d_in[16];
    int size = in_sizes[0];

    cudaFuncSetAttribute(attn_mma_kernel,
                         cudaFuncAttributeMaxDynamicSharedMemorySize, SMEM_TOTAL);

    prep_weights<<<256, 256>>>(wq_w, wk_w, wv_w, mlp_w);

    int nblk = (size + NPB - 1) / NPB;
    attn_mma_kernel<<<nblk, NTHR, SMEM_TOTAL>>>(
        nodes, times, mem, mail, mail_time, time_w, time_b,
        wq_b, wk_b, wv_b, mlp_b, ln_g, ln_b,
        (float*)d_out, size);
}

// round 12
// speedup vs baseline: 13.7510x; 1.1155x over previous
#include <cuda_runtime.h>
#include <cuda_fp16.h>
#include <cstdint>
#include <math.h>

#define MAIL   8
#define DMEM   128
#define DCAT   256
#define NPB    16
#define ROWS   128
#define NTHR   256

#define AH 264             // A / QK row stride in halves
#define MHH 136            // MH row stride in halves
#define QHS 72             // QH row stride in halves

// ---- smem byte offsets ----
#define OFF_NODE 0
#define OFF_TIME 64
#define OFF_BV   128                      // 128 floats -> 640
#define OFF_ATT  640                      // 1024B -> 1664
#define OFF_DT   1664                     // 512B -> 2176
#define OFF_QB   2176                     // 32 floats -> 2304
#define OFF_MEM  2304                     // 16x128 f32 -> 10496
#define OFF_OUT  10496                    // 16x128 f32 -> 18688
#define OFF_MH   18688                    // 16x136 halves -> 23040
#define OFF_QH   23040                    // 2x16x72 halves -> 27648
#define OFF_QK   27648                    // 32x264 halves -> 44544
#define OFF_A    44544                    // 128x264 halves -> 112128
#define SMEM_TOTAL 112128

// Wk^T frags for Qk GEMM: uint32 idx = (((w*4+ks)*8+nt)*32+lane)*2+breg
__device__ __align__(16) uint32_t g_QKf[16384];
// Wv frags: uint32 idx = ((w*16+ks)*2+nt)*64+lane*2+breg
__device__ __align__(16) uint32_t g_VF[16384];
// Wq / mlp_w hi-only B-frags: idx = ((w*8+ks)*2+nt)*64 + lane*2 + breg
__device__ __align__(16) uint32_t g_WqF[8192];
__device__ __align__(16) uint32_t g_MlF[8192];

__device__ __forceinline__ uint32_t smem_u32(const void* p) {
    uint32_t a;
    asm("{ .reg .u64 t; cvta.to.shared.u64 t, %1; cvt.u32.u64 %0, t; }"
        : "=r"(a) : "l"(p));
    return a;
}
__device__ __forceinline__ void ldsm4(uint32_t addr, uint32_t& r0, uint32_t& r1,
                                      uint32_t& r2, uint32_t& r3) {
    asm volatile("ldmatrix.sync.aligned.m8n8.x4.shared.b16 {%0,%1,%2,%3}, [%4];"
                 : "=r"(r0), "=r"(r1), "=r"(r2), "=r"(r3) : "r"(addr));
}
__device__ __forceinline__ void mma16816(float* c, uint32_t a0, uint32_t a1,
                                         uint32_t a2, uint32_t a3,
                                         uint32_t b0, uint32_t b1) {
    asm volatile("mma.sync.aligned.m16n8k16.row.col.f32.f16.f16.f32 "
                 "{%0,%1,%2,%3},{%4,%5,%6,%7},{%8,%9},{%0,%1,%2,%3};"
                 : "+f"(c[0]), "+f"(c[1]), "+f"(c[2]), "+f"(c[3])
                 : "r"(a0), "r"(a1), "r"(a2), "r"(a3), "r"(b0), "r"(b1));
}
__device__ __forceinline__ uint32_t pack_h2(float x, float y) {
    __half2 h = __halves2half2(__float2half_rn(x), __float2half_rn(y));
    return *(uint32_t*)&h;
}

__global__ void prep_weights(const float* __restrict__ wq,
                             const float* __restrict__ wk,
                             const float* __restrict__ wv,
                             const float* __restrict__ mlp) {
    int i = blockIdx.x * 256 + threadIdx.x;           // 0..65535
    if (i < 16384) {
        // Wk^T frags: B[c, kappa] = Wk[h*64 + c, kappa]
        int breg = i & 1;
        int lane = (i >> 1) & 31;
        int nt   = (i >> 6) & 7;
        int ks   = (i >> 9) & 3;
        int w    = (i >> 11) & 7;
        int h  = w >> 2;
        int nc = (w & 3) * 64;
        int kr = ks * 16 + breg * 8 + (lane & 3) * 2;  // reduce dim c
        int kp = nc + nt * 8 + (lane >> 2);            // output kappa
        g_QKf[i] = pack_h2(wk[(h * 64 + kr) * 256 + kp],
                           wk[(h * 64 + kr + 1) * 256 + kp]);
    } else if (i < 32768) {
        int jj = i - 16384;
        int breg = jj & 1, l = (jj >> 1) & 31;
        int nt = (jj >> 6) & 1, ks = (jj >> 7) & 15, w = (jj >> 11) & 7;
        int h = w >> 2, j = w & 3;
        int col = h * 64 + j * 16 + nt * 8 + (l >> 2);
        int k0  = ks * 16 + breg * 8 + (l & 3) * 2;
        g_VF[jj] = pack_h2(wv[col * 256 + k0], wv[col * 256 + k0 + 1]);
    } else if (i < 49152) {
        int j = i - 32768;
        const float* W = (j < 8192) ? wq : mlp;
        int jj = j & 8191;
        int breg = jj & 1, l = (jj >> 1) & 31;
        int nt = (jj >> 6) & 1, ks = (jj >> 7) & 7, w = (jj >> 10) & 7;
        int col = w * 16 + nt * 8 + (l >> 2);
        int k0  = ks * 16 + breg * 8 + (l & 3) * 2;
        uint32_t v = pack_h2(W[col * 128 + k0], W[col * 128 + k0 + 1]);
        if (j < 8192) g_WqF[jj] = v; else g_MlF[jj] = v;
    }
}

__global__ __launch_bounds__(NTHR, 2)
void attn_mma_kernel(
    const int*   __restrict__ nodes,
    const float* __restrict__ times,
    const float* __restrict__ mem,
    const float* __restrict__ mail,
    const float* __restrict__ mail_time,
    const float* __restrict__ time_w,
    const float* __restrict__ time_b,
    const float* __restrict__ wq_b,
    const float* __restrict__ wk_b,
    const float* __restrict__ wv_b,
    const float* __restrict__ mlp_b,
    const float* __restrict__ ln_g,
    const float* __restrict__ ln_b,
    float*       __restrict__ out,
    int size)
{
    extern __shared__ __align__(1024) char smem[];
    const uint32_t sb = smem_u32(smem);
    const int tid = threadIdx.x, warp = tid >> 5, lane = tid & 31;
    const int base = blockIdx.x * NPB;

    int*   s_node = (int*)(smem + OFF_NODE);
    float* s_time = (float*)(smem + OFF_TIME);
    float* s_bv   = (float*)(smem + OFF_BV);
    float* s_att  = (float*)(smem + OFF_ATT);
    float* s_dt   = (float*)(smem + OFF_DT);
    float* s_qb   = (float*)(smem + OFF_QB);
    float* s_memf = (float*)(smem + OFF_MEM);
    float* s_out  = (float*)(smem + OFF_OUT);

    if (tid < NPB) {
        int g = base + tid; if (g >= size) g = size - 1;
        s_node[tid] = nodes[g];
        s_time[tid] = times[g];
    }
    if (tid >= 32 && tid < 64) s_qb[tid - 32] = 0.f;
    if (tid >= 128) s_bv[tid - 128] = wv_b[tid - 128];
    __syncthreads();

    if (tid < ROWS) {
        int n = tid >> 3, slot = tid & 7;
        s_dt[tid] = s_time[n] - __ldg(mail_time + (size_t)s_node[n] * MAIL + slot);
    }

    // gather mem rows (fp32) + hi fp16 copy into MH (16 rows)
    #pragma unroll
    for (int t = 0; t < 2; t++) {
        int idx = tid + t * NTHR;
        int n = idx >> 5, c4 = (idx & 31) * 4;
        float4 v = *(const float4*)(mem + (size_t)s_node[n] * DMEM + c4);
        ((float4*)s_memf)[idx] = v;
        uint32_t off = (uint32_t)(n * MHH + c4) * 2;
        *(uint32_t*)(smem + OFF_MH + off)     = pack_h2(v.x, v.y);
        *(uint32_t*)(smem + OFF_MH + off + 4) = pack_h2(v.z, v.w);
    }

    // mail half of A (fp16)
    {
        const int c4 = (tid & 31) * 4;
        #pragma unroll
        for (int t = 0; t < 16; t++) {
            int r = (tid >> 5) + t * 8;
            int n = r >> 3, slot = r & 7;
            float4 mv = *(const float4*)(mail + ((size_t)s_node[n] * MAIL + slot) * 128 + c4);
            uint32_t* dst = (uint32_t*)(smem + OFF_A + ((size_t)r * AH + c4) * 2);
            dst[0] = pack_h2(mv.x, mv.y);
            dst[1] = pack_h2(mv.z, mv.w);
        }
    }
    __syncthreads();                                 // s_dt, MH, s_qb ready

    // time-encode half of A
    {
        const int j = (tid & 63) * 2;
        const float tw0 = __ldg(time_w + j), tw1 = __ldg(time_w + j + 1);
        const float tb0 = __ldg(time_b + j), tb1 = __ldg(time_b + j + 1);
        #pragma unroll
        for (int t = 0; t < 32; t++) {
            int r = (tid >> 6) + t * 4;
            float dt = s_dt[r];
            float v0 = __cosf(fmaf(dt, tw0, tb0));
            float v1 = __cosf(fmaf(dt, tw1, tb1));
            *(uint32_t*)(smem + OFF_A + ((size_t)r * AH + 128 + j) * 2) = pack_h2(v0, v1);
        }
    }

    const int g8 = lane >> 3, lr = lane & 7;
    const uint32_t mrow = lr + ((g8 & 1) << 3);
    const uint32_t mko  = (uint32_t)((g8 >> 1) << 3);
    const uint32_t mHa  = sb + OFF_MH + (mrow * MHH + mko) * 2;
    const int r4 = lane >> 2, cpos = 2 * (lane & 3);

    // ---- Q via MMA: warp w -> cols [w*16, w*16+16); write QH fp16 + qb atomics ----
    {
        float qa0[4] = {0.f, 0.f, 0.f, 0.f}, qa1[4] = {0.f, 0.f, 0.f, 0.f};
        const uint2* wfq = (const uint2*)g_WqF + (uint32_t)warp * 512 + lane;
        #pragma unroll
        for (int ks = 0; ks < 8; ks++) {
            uint32_t ah0, ah1, ah2, ah3;
            ldsm4(mHa + (uint32_t)ks * 32, ah0, ah1, ah2, ah3);
            uint2 bh0 = __ldg(wfq + ks * 64);
            uint2 bh1 = __ldg(wfq + ks * 64 + 32);
            mma16816(qa0, ah0, ah1, ah2, ah3, bh0.x, bh0.y);
            mma16816(qa1, ah0, ah1, ah2, ah3, bh1.x, bh1.y);
        }
        int col = warp * 16 + cpos;
        int h = warp >> 2;
        int cl = (warp & 3) * 16 + cpos;
        float b0 = __ldg(wq_b + col),     b1 = __ldg(wq_b + col + 1);
        float b8 = __ldg(wq_b + col + 8), b9 = __ldg(wq_b + col + 9);
        float q00 = qa0[0] + b0, q01 = qa0[1] + b1;
        float q02 = qa0[2] + b0, q03 = qa0[3] + b1;
        float q10 = qa1[0] + b8, q11 = qa1[1] + b9;
        float q12 = qa1[2] + b8, q13 = qa1[3] + b9;
        uint32_t rowA = (uint32_t)(h * 16 + r4) * QHS * 2;
        uint32_t rowB = (uint32_t)(h * 16 + r4 + 8) * QHS * 2;
        *(uint32_t*)(smem + OFF_QH + rowA + (uint32_t)cl * 2)       = pack_h2(q00, q01);
        *(uint32_t*)(smem + OFF_QH + rowB + (uint32_t)cl * 2)       = pack_h2(q02, q03);
        *(uint32_t*)(smem + OFF_QH + rowA + (uint32_t)(cl + 8) * 2) = pack_h2(q10, q11);
        *(uint32_t*)(smem + OFF_QH + rowB + (uint32_t)(cl + 8) * 2) = pack_h2(q12, q13);
        // qb contribution: Q . bk over this warp's 4 columns
        float k0 = __ldg(wk_b + col),     k1 = __ldg(wk_b + col + 1);
        float k8 = __ldg(wk_b + col + 8), k9 = __ldg(wk_b + col + 9);
        float cA = q00 * k0 + q01 * k1 + q10 * k8 + q11 * k9;
        float cB = q02 * k0 + q03 * k1 + q12 * k8 + q13 * k9;
        atomicAdd(&s_qb[r4 * 2 + h], cA);
        atomicAdd(&s_qb[(r4 + 8) * 2 + h], cB);
    }
    __syncthreads();                                 // QH, qb, A(time) ready

    // ---- Qk GEMM: Qk[n*2+h, kappa] = Q_h[n,:] @ Wk_h^T, fp16 out ----
    {
        const int h = warp >> 2, nc = (warp & 3) * 64;
        const uint32_t aQ = sb + OFF_QH + (((uint32_t)(h * 16) + mrow) * QHS + mko) * 2;
        float acc[8][4];
        #pragma unroll
        for (int t = 0; t < 8; t++)
            #pragma unroll
            for (int u = 0; u < 4; u++) acc[t][u] = 0.f;
        const uint2* wf = (const uint2*)g_QKf + (uint32_t)warp * 1024 + lane;
        #pragma unroll
        for (int ks = 0; ks < 4; ks++) {
            uint32_t a0, a1, a2, a3;
            ldsm4(aQ + (uint32_t)ks * 32, a0, a1, a2, a3);
            #pragma unroll
            for (int nt = 0; nt < 8; nt++) {
                uint2 b = __ldg(wf + (ks * 8 + nt) * 32);
                mma16816(acc[nt], a0, a1, a2, a3, b.x, b.y);
            }
        }
        #pragma unroll
        for (int nt = 0; nt < 8; nt++) {
            int k0 = nc + nt * 8 + cpos;
            *(uint32_t*)(smem + OFF_QK + ((uint32_t)(r4 * 2 + h) * AH + k0) * 2) =
                pack_h2(acc[nt][0], acc[nt][1]);
            *(uint32_t*)(smem + OFF_QK + ((uint32_t)((r4 + 8) * 2 + h) * AH + k0) * 2) =
                pack_h2(acc[nt][2], acc[nt][3]);
        }
    }
    __syncthreads();                                 // QK ready

    // ---- logits GEMM: warp w -> rows 16w (nodes 2w,2w+1), B cols 8(w>>1) ----
    {
        const int t = warp >> 1;
        const uint32_t aL = sb + OFF_A + (((uint32_t)(warp * 16) + mrow) * AH + mko) * 2;
        const uint32_t bL = sb + OFF_QK +
            (((uint32_t)(8 * t + (lane & 7))) * AH + ((uint32_t)(lane >> 3) << 3)) * 2;
        float acc[4] = {0.f, 0.f, 0.f, 0.f};
        #pragma unroll
        for (int kp = 0; kp < 8; kp++) {
            uint32_t b0, b1, b2, b3;
            ldsm4(bL + (uint32_t)kp * 64, b0, b1, b2, b3);
            uint32_t a0, a1, a2, a3;
            ldsm4(aL + (uint32_t)kp * 64, a0, a1, a2, a3);
            mma16816(acc, a0, a1, a2, a3, b0, b1);
            ldsm4(aL + (uint32_t)kp * 64 + 32, a0, a1, a2, a3);
            mma16816(acc, a0, a1, a2, a3, b2, b3);
        }
        #pragma unroll
        for (int u = 0; u < 4; u++) {
            int row = (u >> 1) * 8 + r4;             // 0..15 within warp's rows
            int colg = 8 * t + cpos + (u & 1);
            int n = colg >> 1, h2 = colg & 1;
            if (n == 2 * warp + (row >> 3)) {
                float v = acc[u] + s_qb[n * 2 + h2];
                v = (v >= 0.f) ? v : 0.2f * v;
                s_att[(n * 8 + (row & 7)) * 2 + h2] = v;
            }
        }
    }
    __syncthreads();

    if (tid < 32) {                                  // softmax: 16 nodes x 2 heads
        int n = tid >> 1, h = tid & 1;
        float mx = -1e30f;
        #pragma unroll
        for (int s = 0; s < MAIL; s++) mx = fmaxf(mx, s_att[(n * 8 + s) * 2 + h]);
        float ex[MAIL], sum = 0.f;
        #pragma unroll
        for (int s = 0; s < MAIL; s++) { ex[s] = __expf(s_att[(n * 8 + s) * 2 + h] - mx); sum += ex[s]; }
        float inv = 1.f / sum;
        #pragma unroll
        for (int s = 0; s < MAIL; s++) s_att[(n * 8 + s) * 2 + h] = ex[s] * inv;
    }
    __syncthreads();

    // ---- contract mailbox, BOTH heads per thread (Mcat read once) ----
    {
        const int n  = tid >> 4;                     // 0..15
        const int c0 = tid & 15;
        float a0[MAIL], a1[MAIL];
        #pragma unroll
        for (int s = 0; s < MAIL; s++) {
            a0[s] = s_att[(n * 8 + s) * 2 + 0];
            a1[s] = s_att[(n * 8 + s) * 2 + 1];
        }
        float2 w0[8], w1[8];
        #pragma unroll
        for (int t = 0; t < 8; t++) {
            w0[t].x = 0.f; w0[t].y = 0.f;
            w1[t].x = 0.f; w1[t].y = 0.f;
        }
        #pragma unroll
        for (int s = 0; s < MAIL; s++) {
            const __half2* arow = (const __half2*)(smem + OFF_A + (size_t)(n * 8 + s) * AH * 2);
            #pragma unroll
            for (int t = 0; t < 8; t++) {
                float2 v = __half22float2(arow[c0 + t * 16]);
                w0[t].x = fmaf(a0[s], v.x, w0[t].x);
                w0[t].y = fmaf(a0[s], v.y, w0[t].y);
                w1[t].x = fmaf(a1[s], v.x, w1[t].x);
                w1[t].y = fmaf(a1[s], v.y, w1[t].y);
            }
        }
        __syncthreads();                             // all Mcat reads complete
        uint32_t h0B = (uint32_t)n * AH * 2;
        uint32_t h1B = (uint32_t)(16 + n) * AH * 2;
        #pragma unroll
        for (int t = 0; t < 8; t++) {
            uint32_t off = (uint32_t)(c0 + t * 16) * 4;
            *(uint32_t*)(smem + OFF_A + h0B + off) = pack_h2(w0[t].x, w0[t].y);
            *(uint32_t*)(smem + OFF_A + h1B + off) = pack_h2(w1[t].x, w1[t].y);
        }
    }
    __syncthreads();

    // ---- V GEMM on contracted rows: warp w -> head h=w>>2, cols j*16 ----
    {
        const int h = warp >> 2, j = warp & 3;
        const uint32_t aHi = sb + OFF_A + (((uint32_t)(h * 16) + mrow) * AH + mko) * 2;
        float qa0[4] = {0.f, 0.f, 0.f, 0.f}, qa1[4] = {0.f, 0.f, 0.f, 0.f};
        const uint2* wfv = (const uint2*)g_VF + (uint32_t)warp * 1024 + lane;
        #pragma unroll
        for (int ks = 0; ks < 16; ks++) {
            uint32_t h0, h1, h2, h3;
            ldsm4(aHi + (uint32_t)ks * 32, h0, h1, h2, h3);
            uint2 b0 = __ldg(wfv + ks * 64);
            uint2 b1 = __ldg(wfv + ks * 64 + 32);
            mma16816(qa0, h0, h1, h2, h3, b0.x, b0.y);
            mma16816(qa1, h0, h1, h2, h3, b1.x, b1.y);
        }
        int col = h * 64 + j * 16 + cpos;
        #pragma unroll
        for (int half = 0; half < 2; half++) {
            int node = r4 + half * 8;
            float v0 = (half ? qa0[2] : qa0[0]) + s_bv[col]     + s_memf[node * 128 + col];
            float v1 = (half ? qa0[3] : qa0[1]) + s_bv[col + 1] + s_memf[node * 128 + col + 1];
            float v8 = (half ? qa1[2] : qa1[0]) + s_bv[col + 8] + s_memf[node * 128 + col + 8];
            float v9 = (half ? qa1[3] : qa1[1]) + s_bv[col + 9] + s_memf[node * 128 + col + 9];
            s_out[node * 128 + col]     = v0;
            s_out[node * 128 + col + 1] = v1;
            s_out[node * 128 + col + 8] = v8;
            s_out[node * 128 + col + 9] = v9;
        }
    }
    __syncthreads();

    // ---- LayerNorm: warp handles 2 nodes; writes hi fp16 into MH ----
    #pragma unroll
    for (int t = 0; t < 2; t++) {
        int n = warp * 2 + t;
        float4 x4 = ((float4*)(s_out + n * 128))[lane];
        float sum = x4.x + x4.y + x4.z + x4.w;
        float sq  = fmaf(x4.x, x4.x, fmaf(x4.y, x4.y, fmaf(x4.z, x4.z, x4.w * x4.w)));
        #pragma unroll
        for (int off = 16; off; off >>= 1) {
            sum += __shfl_xor_sync(0xffffffffu, sum, off);
            sq  += __shfl_xor_sync(0xffffffffu, sq, off);
        }
        float mu = sum * (1.f / 128.f);
        float rstd = rsqrtf(sq * (1.f / 128.f) - mu * mu + 1e-5f);
        float o[4] = {x4.x, x4.y, x4.z, x4.w};
        float y[4];
        #pragma unroll
        for (int u = 0; u < 4; u++) {
            int cc = lane * 4 + u;
            y[u] = (o[u] - mu) * rstd * __ldg(ln_g + cc) + __ldg(ln_b + cc);
        }
        uint32_t off0 = (uint32_t)(n * MHH + lane * 4) * 2;
        *(uint32_t*)(smem + OFF_MH + off0)     = pack_h2(y[0], y[1]);
        *(uint32_t*)(smem + OFF_MH + off0 + 4) = pack_h2(y[2], y[3]);
    }
    __syncthreads();

    // ---- MLP via MMA + ReLU + store ----
    {
        float qa0[4] = {0.f, 0.f, 0.f, 0.f}, qa1[4] = {0.f, 0.f, 0.f, 0.f};
        const uint2* wfm = (const uint2*)g_MlF + (uint32_t)warp * 512 + lane;
        #pragma unroll
        for (int ks = 0; ks < 8; ks++) {
            uint32_t ah0, ah1, ah2, ah3;
            ldsm4(mHa + (uint32_t)ks * 32, ah0, ah1, ah2, ah3);
            uint2 bh0 = __ldg(wfm + ks * 64);
            uint2 bh1 = __ldg(wfm + ks * 64 + 32);
            mma16816(qa0, ah0, ah1, ah2, ah3, bh0.x, bh0.y);
            mma16816(qa1, ah0, ah1, ah2, ah3, bh1.x, bh1.y);
        }
        int col = warp * 16 + cpos;
        float b0 = __ldg(mlp_b + col),     b1 = __ldg(mlp_b + col + 1);
        float b8 = __ldg(mlp_b + col + 8), b9 = __ldg(mlp_b + col + 9);
        int g0 = base + r4, g1 = base + r4 + 8;
        if (g0 < size) {
            float2 v0 = { fmaxf(qa0[0] + b0, 0.f), fmaxf(qa0[1] + b1, 0.f) };
            float2 v1 = { fmaxf(qa1[0] + b8, 0.f), fmaxf(qa1[1] + b9, 0.f) };
            *(float2*)(out + (size_t)g0 * 128 + col)     = v0;
            *(float2*)(out + (size_t)g0 * 128 + col + 8) = v1;
        }
        if (g1 < size) {
            float2 v0 = { fmaxf(qa0[2] + b0, 0.f), fmaxf(qa0[3] + b1, 0.f) };
            float2 v1 = { fmaxf(qa1[2] + b8, 0.f), fmaxf(qa1[3] + b9, 0.f) };
            *(float2*)(out + (size_t)g1 * 128 + col)     = v0;
            *(float2*)(out + (size_t)g1 * 128 + col + 8) = v1;
        }
    }
}

extern "C" void kernel_launch(void* const* d_in, const int* in_sizes, int n_in,
                              void* d_out, int out_size) {
    const int*   nodes     = (const int*)  d_in[0];
    const float* times     = (const float*)d_in[1];
    const float* mem       = (const float*)d_in[2];
    const float* mail      = (const float*)d_in[3];
    const float* mail_time = (const float*)d_in[4];
    const float* time_w    = (const float*)d_in[5];
    const float* time_b    = (const float*)d_in[6];
    const float* wq_w      = (const float*)d_in[7];
    const float* wq_b      = (const float*)d_in[8];
    const float* wk_w      = (const float*)d_in[9];
    const float* wk_b      = (const float*)d_in[10];
    const float* wv_w      = (const float*)d_in[11];
    const float* wv_b      = (const float*)d_in[12];
    const float* mlp_w     = (const float*)d_in[13];
    const float* mlp_b     = (const float*)d_in[14];
    const float* ln_g      = (const float*)d_in[15];
    const float* ln_b      = (const float*)d_in[16];
    int size = in_sizes[0];

    cudaFuncSetAttribute(attn_mma_kernel,
                         cudaFuncAttributeMaxDynamicSharedMemorySize, SMEM_TOTAL);

    prep_weights<<<256, 256>>>(wq_w, wk_w, wv_w, mlp_w);

    int nblk = (size + NPB - 1) / NPB;
    attn_mma_kernel<<<nblk, NTHR, SMEM_TOTAL>>>(
        nodes, times, mem, mail, mail_time, time_w, time_b,
        wq_b, wk_b, wv_b, mlp_b, ln_g, ln_b,
        (float*)d_out, size);
}

// round 13
// speedup vs baseline: 14.0201x; 1.0196x over previous
#include <cuda_runtime.h>
#include <cuda_fp16.h>
#include <cstdint>
#include <math.h>

#define MAIL   8
#define DMEM   128
#define DCAT   256
#define NPB    16
#define ROWS   128
#define NTHR   256

#define AH 264             // A / QK row stride in halves
#define MHH 136            // MH row stride in halves
#define QHS 72             // QH / attn-tile row stride in halves

// ---- smem byte offsets ----
#define OFF_NODE 0
#define OFF_TIME 64
#define OFF_BV   128
#define OFF_ATT  640
#define OFF_DT   1664
#define OFF_QB   2176
#define OFF_MEM  2304                    // 16x128 f32 -> 10496
#define OFF_OUT  10496                   // 16x128 f32 -> 18688
#define OFF_MH   18688                   // 16x136 halves -> 23040
#define OFF_QH   23040                   // 2x16x72 halves -> 27648 (attn tiles overlay)
#define OFF_QK   27648                   // 32x264 halves -> 44544
#define OFF_A    44544                   // 128x264 halves -> 112128
#define SMEM_TOTAL 112128

// Wk^T frags for Qk GEMM
__device__ __align__(16) uint32_t g_QKf[16384];
// Wv frags
__device__ __align__(16) uint32_t g_VF[16384];
// Wq / mlp_w hi-only B-frags
__device__ __align__(16) uint32_t g_WqF[8192];
__device__ __align__(16) uint32_t g_MlF[8192];

__device__ __forceinline__ uint32_t smem_u32(const void* p) {
    uint32_t a;
    asm("{ .reg .u64 t; cvta.to.shared.u64 t, %1; cvt.u32.u64 %0, t; }"
        : "=r"(a) : "l"(p));
    return a;
}
__device__ __forceinline__ void ldsm4(uint32_t addr, uint32_t& r0, uint32_t& r1,
                                      uint32_t& r2, uint32_t& r3) {
    asm volatile("ldmatrix.sync.aligned.m8n8.x4.shared.b16 {%0,%1,%2,%3}, [%4];"
                 : "=r"(r0), "=r"(r1), "=r"(r2), "=r"(r3) : "r"(addr));
}
__device__ __forceinline__ void ldsm4t(uint32_t addr, uint32_t& r0, uint32_t& r1,
                                       uint32_t& r2, uint32_t& r3) {
    asm volatile("ldmatrix.sync.aligned.m8n8.x4.trans.shared.b16 {%0,%1,%2,%3}, [%4];"
                 : "=r"(r0), "=r"(r1), "=r"(r2), "=r"(r3) : "r"(addr));
}
__device__ __forceinline__ void mma16816(float* c, uint32_t a0, uint32_t a1,
                                         uint32_t a2, uint32_t a3,
                                         uint32_t b0, uint32_t b1) {
    asm volatile("mma.sync.aligned.m16n8k16.row.col.f32.f16.f16.f32 "
                 "{%0,%1,%2,%3},{%4,%5,%6,%7},{%8,%9},{%0,%1,%2,%3};"
                 : "+f"(c[0]), "+f"(c[1]), "+f"(c[2]), "+f"(c[3])
                 : "r"(a0), "r"(a1), "r"(a2), "r"(a3), "r"(b0), "r"(b1));
}
__device__ __forceinline__ uint32_t pack_h2(float x, float y) {
    __half2 h = __halves2half2(__float2half_rn(x), __float2half_rn(y));
    return *(uint32_t*)&h;
}

__global__ void prep_weights(const float* __restrict__ wq,
                             const float* __restrict__ wk,
                             const float* __restrict__ wv,
                             const float* __restrict__ mlp) {
    int i = blockIdx.x * 256 + threadIdx.x;           // 0..65535
    if (i < 16384) {
        int breg = i & 1;
        int lane = (i >> 1) & 31;
        int nt   = (i >> 6) & 7;
        int ks   = (i >> 9) & 3;
        int w    = (i >> 11) & 7;
        int h  = w >> 2;
        int nc = (w & 3) * 64;
        int kr = ks * 16 + breg * 8 + (lane & 3) * 2;
        int kp = nc + nt * 8 + (lane >> 2);
        g_QKf[i] = pack_h2(wk[(h * 64 + kr) * 256 + kp],
                           wk[(h * 64 + kr + 1) * 256 + kp]);
    } else if (i < 32768) {
        int jj = i - 16384;
        int breg = jj & 1, l = (jj >> 1) & 31;
        int nt = (jj >> 6) & 1, ks = (jj >> 7) & 15, w = (jj >> 11) & 7;
        int h = w >> 2, j = w & 3;
        int col = h * 64 + j * 16 + nt * 8 + (l >> 2);
        int k0  = ks * 16 + breg * 8 + (l & 3) * 2;
        g_VF[jj] = pack_h2(wv[col * 256 + k0], wv[col * 256 + k0 + 1]);
    } else if (i < 49152) {
        int j = i - 32768;
        const float* W = (j < 8192) ? wq : mlp;
        int jj = j & 8191;
        int breg = jj & 1, l = (jj >> 1) & 31;
        int nt = (jj >> 6) & 1, ks = (jj >> 7) & 7, w = (jj >> 10) & 7;
        int col = w * 16 + nt * 8 + (l >> 2);
        int k0  = ks * 16 + breg * 8 + (l & 3) * 2;
        uint32_t v = pack_h2(W[col * 128 + k0], W[col * 128 + k0 + 1]);
        if (j < 8192) g_WqF[jj] = v; else g_MlF[jj] = v;
    }
}

__global__ __launch_bounds__(NTHR, 2)
void attn_mma_kernel(
    const int*   __restrict__ nodes,
    const float* __restrict__ times,
    const float* __restrict__ mem,
    const float* __restrict__ mail,
    const float* __restrict__ mail_time,
    const float* __restrict__ time_w,
    const float* __restrict__ time_b,
    const float* __restrict__ wq_b,
    const float* __restrict__ wk_b,
    const float* __restrict__ wv_b,
    const float* __restrict__ mlp_b,
    const float* __restrict__ ln_g,
    const float* __restrict__ ln_b,
    float*       __restrict__ out,
    int size)
{
    extern __shared__ __align__(1024) char smem[];
    const uint32_t sb = smem_u32(smem);
    const int tid = threadIdx.x, warp = tid >> 5, lane = tid & 31;
    const int base = blockIdx.x * NPB;

    int*   s_node = (int*)(smem + OFF_NODE);
    float* s_time = (float*)(smem + OFF_TIME);
    float* s_bv   = (float*)(smem + OFF_BV);
    float* s_att  = (float*)(smem + OFF_ATT);
    float* s_dt   = (float*)(smem + OFF_DT);
    float* s_qb   = (float*)(smem + OFF_QB);
    float* s_memf = (float*)(smem + OFF_MEM);
    float* s_out  = (float*)(smem + OFF_OUT);

    if (tid < NPB) {
        int g = base + tid; if (g >= size) g = size - 1;
        s_node[tid] = nodes[g];
        s_time[tid] = times[g];
    }
    if (tid >= 32 && tid < 64) s_qb[tid - 32] = 0.f;
    if (tid >= 128) s_bv[tid - 128] = wv_b[tid - 128];
    __syncthreads();

    if (tid < ROWS) {
        int n = tid >> 3, slot = tid & 7;
        s_dt[tid] = s_time[n] - __ldg(mail_time + (size_t)s_node[n] * MAIL + slot);
    }

    // gather mem rows (fp32) + hi fp16 copy into MH
    #pragma unroll
    for (int t = 0; t < 2; t++) {
        int idx = tid + t * NTHR;
        int n = idx >> 5, c4 = (idx & 31) * 4;
        float4 v = *(const float4*)(mem + (size_t)s_node[n] * DMEM + c4);
        ((float4*)s_memf)[idx] = v;
        uint32_t off = (uint32_t)(n * MHH + c4) * 2;
        *(uint32_t*)(smem + OFF_MH + off)     = pack_h2(v.x, v.y);
        *(uint32_t*)(smem + OFF_MH + off + 4) = pack_h2(v.z, v.w);
    }

    // mail half of A (fp16)
    {
        const int c4 = (tid & 31) * 4;
        #pragma unroll
        for (int t = 0; t < 16; t++) {
            int r = (tid >> 5) + t * 8;
            int n = r >> 3, slot = r & 7;
            float4 mv = *(const float4*)(mail + ((size_t)s_node[n] * MAIL + slot) * 128 + c4);
            uint32_t* dst = (uint32_t*)(smem + OFF_A + ((size_t)r * AH + c4) * 2);
            dst[0] = pack_h2(mv.x, mv.y);
            dst[1] = pack_h2(mv.z, mv.w);
        }
    }
    __syncthreads();

    // time-encode half of A
    {
        const int j = (tid & 63) * 2;
        const float tw0 = __ldg(time_w + j), tw1 = __ldg(time_w + j + 1);
        const float tb0 = __ldg(time_b + j), tb1 = __ldg(time_b + j + 1);
        #pragma unroll
        for (int t = 0; t < 32; t++) {
            int r = (tid >> 6) + t * 4;
            float dt = s_dt[r];
            float v0 = __cosf(fmaf(dt, tw0, tb0));
            float v1 = __cosf(fmaf(dt, tw1, tb1));
            *(uint32_t*)(smem + OFF_A + ((size_t)r * AH + 128 + j) * 2) = pack_h2(v0, v1);
        }
    }

    const int g8 = lane >> 3, lr = lane & 7;
    const uint32_t mrow = lr + ((g8 & 1) << 3);
    const uint32_t mko  = (uint32_t)((g8 >> 1) << 3);
    const uint32_t mHa  = sb + OFF_MH + (mrow * MHH + mko) * 2;
    const int r4 = lane >> 2, cpos = 2 * (lane & 3);

    // ---- Q via MMA: warp w -> cols [w*16, w*16+16); write QH fp16 + qb atomics ----
    {
        float qa0[4] = {0.f, 0.f, 0.f, 0.f}, qa1[4] = {0.f, 0.f, 0.f, 0.f};
        const uint2* wfq = (const uint2*)g_WqF + (uint32_t)warp * 512 + lane;
        #pragma unroll
        for (int ks = 0; ks < 8; ks++) {
            uint32_t ah0, ah1, ah2, ah3;
            ldsm4(mHa + (uint32_t)ks * 32, ah0, ah1, ah2, ah3);
            uint2 bh0 = __ldg(wfq + ks * 64);
            uint2 bh1 = __ldg(wfq + ks * 64 + 32);
            mma16816(qa0, ah0, ah1, ah2, ah3, bh0.x, bh0.y);
            mma16816(qa1, ah0, ah1, ah2, ah3, bh1.x, bh1.y);
        }
        int col = warp * 16 + cpos;
        int h = warp >> 2;
        int cl = (warp & 3) * 16 + cpos;
        float b0 = __ldg(wq_b + col),     b1 = __ldg(wq_b + col + 1);
        float b8 = __ldg(wq_b + col + 8), b9 = __ldg(wq_b + col + 9);
        float q00 = qa0[0] + b0, q01 = qa0[1] + b1;
        float q02 = qa0[2] + b0, q03 = qa0[3] + b1;
        float q10 = qa1[0] + b8, q11 = qa1[1] + b9;
        float q12 = qa1[2] + b8, q13 = qa1[3] + b9;
        uint32_t rowA = (uint32_t)(h * 16 + r4) * QHS * 2;
        uint32_t rowB = (uint32_t)(h * 16 + r4 + 8) * QHS * 2;
        *(uint32_t*)(smem + OFF_QH + rowA + (uint32_t)cl * 2)       = pack_h2(q00, q01);
        *(uint32_t*)(smem + OFF_QH + rowB + (uint32_t)cl * 2)       = pack_h2(q02, q03);
        *(uint32_t*)(smem + OFF_QH + rowA + (uint32_t)(cl + 8) * 2) = pack_h2(q10, q11);
        *(uint32_t*)(smem + OFF_QH + rowB + (uint32_t)(cl + 8) * 2) = pack_h2(q12, q13);
        float k0 = __ldg(wk_b + col),     k1 = __ldg(wk_b + col + 1);
        float k8 = __ldg(wk_b + col + 8), k9 = __ldg(wk_b + col + 9);
        float cA = q00 * k0 + q01 * k1 + q10 * k8 + q11 * k9;
        float cB = q02 * k0 + q03 * k1 + q12 * k8 + q13 * k9;
        atomicAdd(&s_qb[r4 * 2 + h], cA);
        atomicAdd(&s_qb[(r4 + 8) * 2 + h], cB);
    }
    __syncthreads();

    // ---- Qk GEMM: Qk[n*2+h, kappa] = Q_h[n,:] @ Wk_h^T ----
    {
        const int h = warp >> 2, nc = (warp & 3) * 64;
        const uint32_t aQ = sb + OFF_QH + (((uint32_t)(h * 16) + mrow) * QHS + mko) * 2;
        float acc[8][4];
        #pragma unroll
        for (int t = 0; t < 8; t++)
            #pragma unroll
            for (int u = 0; u < 4; u++) acc[t][u] = 0.f;
        const uint2* wf = (const uint2*)g_QKf + (uint32_t)warp * 1024 + lane;
        #pragma unroll
        for (int ks = 0; ks < 4; ks++) {
            uint32_t a0, a1, a2, a3;
            ldsm4(aQ + (uint32_t)ks * 32, a0, a1, a2, a3);
            #pragma unroll
            for (int nt = 0; nt < 8; nt++) {
                uint2 b = __ldg(wf + (ks * 8 + nt) * 32);
                mma16816(acc[nt], a0, a1, a2, a3, b.x, b.y);
            }
        }
        #pragma unroll
        for (int nt = 0; nt < 8; nt++) {
            int k0 = nc + nt * 8 + cpos;
            *(uint32_t*)(smem + OFF_QK + ((uint32_t)(r4 * 2 + h) * AH + k0) * 2) =
                pack_h2(acc[nt][0], acc[nt][1]);
            *(uint32_t*)(smem + OFF_QK + ((uint32_t)((r4 + 8) * 2 + h) * AH + k0) * 2) =
                pack_h2(acc[nt][2], acc[nt][3]);
        }
    }
    __syncthreads();                                 // QK ready; QH now dead

    // ---- logits GEMM: warp w -> rows 16w, B cols 8(w>>1) ----
    {
        const int t = warp >> 1;
        const uint32_t aL = sb + OFF_A + (((uint32_t)(warp * 16) + mrow) * AH + mko) * 2;
        const uint32_t bL = sb + OFF_QK +
            (((uint32_t)(8 * t + (lane & 7))) * AH + ((uint32_t)(lane >> 3) << 3)) * 2;
        float acc[4] = {0.f, 0.f, 0.f, 0.f};
        #pragma unroll
        for (int kp = 0; kp < 8; kp++) {
            uint32_t b0, b1, b2, b3;
            ldsm4(bL + (uint32_t)kp * 64, b0, b1, b2, b3);
            uint32_t a0, a1, a2, a3;
            ldsm4(aL + (uint32_t)kp * 64, a0, a1, a2, a3);
            mma16816(acc, a0, a1, a2, a3, b0, b1);
            ldsm4(aL + (uint32_t)kp * 64 + 32, a0, a1, a2, a3);
            mma16816(acc, a0, a1, a2, a3, b2, b3);
        }
        #pragma unroll
        for (int u = 0; u < 4; u++) {
            int row = (u >> 1) * 8 + r4;
            int colg = 8 * t + cpos + (u & 1);
            int n = colg >> 1, h2 = colg & 1;
            if (n == 2 * warp + (row >> 3)) {
                float v = acc[u] + s_qb[n * 2 + h2];
                v = (v >= 0.f) ? v : 0.2f * v;
                s_att[(n * 8 + (row & 7)) * 2 + h2] = v;
            }
        }
    }
    __syncthreads();

    // ---- softmax + build fp16 attn tiles in QH region ----
    // tile t in {0,1}: [16 rows=(n&7)*2+h][72 halves], nonzero at k=8*(n&7)+s
    if (tid < 32) {
        int n = tid >> 1, h = tid & 1;
        float mx = -1e30f;
        #pragma unroll
        for (int s = 0; s < MAIL; s++) mx = fmaxf(mx, s_att[(n * 8 + s) * 2 + h]);
        float ex[MAIL], sum = 0.f;
        #pragma unroll
        for (int s = 0; s < MAIL; s++) { ex[s] = __expf(s_att[(n * 8 + s) * 2 + h] - mx); sum += ex[s]; }
        float inv = 1.f / sum;
        int t = n >> 3, rloc = (n & 7) * 2 + h;
        uint32_t rowB = (uint32_t)OFF_QH + (uint32_t)(t * 16 + rloc) * QHS * 2;
        int nz = n & 7;                              // nonzero word group 4*nz..4*nz+3
        #pragma unroll
        for (int w = 0; w < 32; w++) {               // zero k cols 0..63 (pad unread)
            uint32_t val = 0u;
            if ((w >> 2) == nz) {
                int s2 = (w & 3) * 2;
                val = pack_h2(ex[s2] * inv, ex[s2 + 1] * inv);
            }
            *(uint32_t*)(smem + rowB + (uint32_t)w * 4) = val;
        }
    }
    __syncthreads();

    // ---- contraction via MMA: weighted[h*16+n, c] = attnTile @ Mcat ----
    {
        const int t = warp >> 2, cchunk = (warp & 3) * 64;
        const uint32_t aT = sb + OFF_QH +
            (((uint32_t)(t * 16 + (lane & 15))) * QHS + ((uint32_t)(lane >> 4) << 3)) * 2;
        const uint32_t bT = sb + OFF_A +
            (((uint32_t)(64 * t + (lane & 15))) * AH + (uint32_t)cchunk + ((uint32_t)(lane >> 4) << 3)) * 2;
        float acc[8][4];
        #pragma unroll
        for (int q = 0; q < 8; q++)
            #pragma unroll
            for (int u = 0; u < 4; u++) acc[q][u] = 0.f;
        #pragma unroll
        for (int ks = 0; ks < 4; ks++) {
            uint32_t a0, a1, a2, a3;
            ldsm4(aT + (uint32_t)ks * 32, a0, a1, a2, a3);
            #pragma unroll
            for (int nn2 = 0; nn2 < 4; nn2++) {
                uint32_t r0, r1, r2, r3;
                ldsm4t(bT + ((uint32_t)(ks * 16) * AH + (uint32_t)(nn2 * 16)) * 2,
                       r0, r1, r2, r3);
                mma16816(acc[nn2 * 2],     a0, a1, a2, a3, r0, r1);
                mma16816(acc[nn2 * 2 + 1], a0, a1, a2, a3, r2, r3);
            }
        }
        // store weighted rows (hi fp16) into A rows h*16+n; column-disjoint per warp
        int n0 = 8 * t + (r4 >> 1), hh = r4 & 1;
        uint32_t ro0 = (uint32_t)(hh * 16 + n0) * AH * 2;
        uint32_t ro1 = (uint32_t)(hh * 16 + n0 + 4) * AH * 2;
        #pragma unroll
        for (int nn = 0; nn < 8; nn++) {
            uint32_t c2 = (uint32_t)(cchunk + nn * 8 + cpos) * 2;
            *(uint32_t*)(smem + OFF_A + ro0 + c2) = pack_h2(acc[nn][0], acc[nn][1]);
            *(uint32_t*)(smem + OFF_A + ro1 + c2) = pack_h2(acc[nn][2], acc[nn][3]);
        }
    }
    __syncthreads();

    // ---- V GEMM on contracted rows: warp w -> head h=w>>2, cols j*16 ----
    {
        const int h = warp >> 2, j = warp & 3;
        const uint32_t aHi = sb + OFF_A + (((uint32_t)(h * 16) + mrow) * AH + mko) * 2;
        float qa0[4] = {0.f, 0.f, 0.f, 0.f}, qa1[4] = {0.f, 0.f, 0.f, 0.f};
        const uint2* wfv = (const uint2*)g_VF + (uint32_t)warp * 1024 + lane;
        #pragma unroll
        for (int ks = 0; ks < 16; ks++) {
            uint32_t h0, h1, h2, h3;
            ldsm4(aHi + (uint32_t)ks * 32, h0, h1, h2, h3);
            uint2 b0 = __ldg(wfv + ks * 64);
            uint2 b1 = __ldg(wfv + ks * 64 + 32);
            mma16816(qa0, h0, h1, h2, h3, b0.x, b0.y);
            mma16816(qa1, h0, h1, h2, h3, b1.x, b1.y);
        }
        int col = h * 64 + j * 16 + cpos;
        #pragma unroll
        for (int half = 0; half < 2; half++) {
            int node = r4 + half * 8;
            float v0 = (half ? qa0[2] : qa0[0]) + s_bv[col]     + s_memf[node * 128 + col];
            float v1 = (half ? qa0[3] : qa0[1]) + s_bv[col + 1] + s_memf[node * 128 + col + 1];
            float v8 = (half ? qa1[2] : qa1[0]) + s_bv[col + 8] + s_memf[node * 128 + col + 8];
            float v9 = (half ? qa1[3] : qa1[1]) + s_bv[col + 9] + s_memf[node * 128 + col + 9];
            s_out[node * 128 + col]     = v0;
            s_out[node * 128 + col + 1] = v1;
            s_out[node * 128 + col + 8] = v8;
            s_out[node * 128 + col + 9] = v9;
        }
    }
    __syncthreads();

    // ---- LayerNorm: warp handles 2 nodes; writes hi fp16 into MH ----
    #pragma unroll
    for (int t = 0; t < 2; t++) {
        int n = warp * 2 + t;
        float4 x4 = ((float4*)(s_out + n * 128))[lane];
        float sum = x4.x + x4.y + x4.z + x4.w;
        float sq  = fmaf(x4.x, x4.x, fmaf(x4.y, x4.y, fmaf(x4.z, x4.z, x4.w * x4.w)));
        #pragma unroll
        for (int off = 16; off; off >>= 1) {
            sum += __shfl_xor_sync(0xffffffffu, sum, off);
            sq  += __shfl_xor_sync(0xffffffffu, sq, off);
        }
        float mu = sum * (1.f / 128.f);
        float rstd = rsqrtf(sq * (1.f / 128.f) - mu * mu + 1e-5f);
        float o[4] = {x4.x, x4.y, x4.z, x4.w};
        float y[4];
        #pragma unroll
        for (int u = 0; u < 4; u++) {
            int cc = lane * 4 + u;
            y[u] = (o[u] - mu) * rstd * __ldg(ln_g + cc) + __ldg(ln_b + cc);
        }
        uint32_t off0 = (uint32_t)(n * MHH + lane * 4) * 2;
        *(uint32_t*)(smem + OFF_MH + off0)     = pack_h2(y[0], y[1]);
        *(uint32_t*)(smem + OFF_MH + off0 + 4) = pack_h2(y[2], y[3]);
    }
    __syncthreads();

    // ---- MLP via MMA + ReLU + store ----
    {
        float qa0[4] = {0.f, 0.f, 0.f, 0.f}, qa1[4] = {0.f, 0.f, 0.f, 0.f};
        const uint2* wfm = (const uint2*)g_MlF + (uint32_t)warp * 512 + lane;
        #pragma unroll
        for (int ks = 0; ks < 8; ks++) {
            uint32_t ah0, ah1, ah2, ah3;
            ldsm4(mHa + (uint32_t)ks * 32, ah0, ah1, ah2, ah3);
            uint2 bh0 = __ldg(wfm + ks * 64);
            uint2 bh1 = __ldg(wfm + ks * 64 + 32);
            mma16816(qa0, ah0, ah1, ah2, ah3, bh0.x, bh0.y);
            mma16816(qa1, ah0, ah1, ah2, ah3, bh1.x, bh1.y);
        }
        int col = warp * 16 + cpos;
        float b0 = __ldg(mlp_b + col),     b1 = __ldg(mlp_b + col + 1);
        float b8 = __ldg(mlp_b + col + 8), b9 = __ldg(mlp_b + col + 9);
        int g0 = base + r4, g1 = base + r4 + 8;
        if (g0 < size) {
            float2 v0 = { fmaxf(qa0[0] + b0, 0.f), fmaxf(qa0[1] + b1, 0.f) };
            float2 v1 = { fmaxf(qa1[0] + b8, 0.f), fmaxf(qa1[1] + b9, 0.f) };
            *(float2*)(out + (size_t)g0 * 128 + col)     = v0;
            *(float2*)(out + (size_t)g0 * 128 + col + 8) = v1;
        }
        if (g1 < size) {
            float2 v0 = { fmaxf(qa0[2] + b0, 0.f), fmaxf(qa0[3] + b1, 0.f) };
            float2 v1 = { fmaxf(qa1[2] + b8, 0.f), fmaxf(qa1[3] + b9, 0.f) };
            *(float2*)(out + (size_t)g1 * 128 + col)     = v0;
            *(float2*)(out + (size_t)g1 * 128 + col + 8) = v1;
        }
    }
}

extern "C" void kernel_launch(void* const* d_in, const int* in_sizes, int n_in,
                              void* d_out, int out_size) {
    const int*   nodes     = (const int*)  d_in[0];
    const float* times     = (const float*)d_in[1];
    const float* mem       = (const float*)d_in[2];
    const float* mail      = (const float*)d_in[3];
    const float* mail_time = (const float*)d_in[4];
    const float* time_w    = (const float*)d_in[5];
    const float* time_b    = (const float*)d_in[6];
    const float* wq_w      = (const float*)d_in[7];
    const float* wq_b      = (const float*)d_in[8];
    const float* wk_w      = (const float*)d_in[9];
    const float* wk_b      = (const float*)d_in[10];
    const float* wv_w      = (const float*)d_in[11];
    const float* wv_b      = (const float*)d_in[12];
    const float* mlp_w     = (const float*)d_in[13];
    const float* mlp_b     = (const float*)d_in[14];
    const float* ln_g      = (const float*)d_in[15];
    const float* ln_b      = (const float*)d_in[16];
    int size = in_sizes[0];

    cudaFuncSetAttribute(attn_mma_kernel,
                         cudaFuncAttributeMaxDynamicSharedMemorySize, SMEM_TOTAL);

    prep_weights<<<256, 256>>>(wq_w, wk_w, wv_w, mlp_w);

    int nblk = (size + NPB - 1) / NPB;
    attn_mma_kernel<<<nblk, NTHR, SMEM_TOTAL>>>(
        nodes, times, mem, mail, mail_time, time_w, time_b,
        wq_b, wk_b, wv_b, mlp_b, ln_g, ln_b,
        (float*)d_out, size);
}

// round 14
// speedup vs baseline: 14.0247x; 1.0003x over previous
#include <cuda_runtime.h>
#include <cuda_fp16.h>
#include <cstdint>
#include <math.h>

#define MAIL   8
#define DMEM   128
#define DCAT   256
#define NPB    16
#define ROWS   128
#define NTHR   256

#define AH 264             // A / QK row stride in halves
#define MHH 136            // MH row stride in halves
#define QHS 72             // QH / attn-tile row stride in halves

// ---- smem byte offsets ----
#define OFF_NODE 0
#define OFF_TIME 64
#define OFF_BV   128
#define OFF_ATT  640
#define OFF_DT   1664
#define OFF_QB   2176
#define OFF_MEM  2304                    // 16x128 f32 -> 10496
#define OFF_OUT  10496                   // 16x128 f32 -> 18688
#define OFF_MH   18688                   // 16x136 halves -> 23040
#define OFF_QH   23040                   // 2x16x72 halves -> 27648 (attn tiles overlay)
#define OFF_QK   27648                   // 32x264 halves -> 44544
#define OFF_A    44544                   // 128x264 halves -> 112128
#define SMEM_TOTAL 112128

__device__ __align__(16) uint32_t g_QKf[16384];
__device__ __align__(16) uint32_t g_VF[16384];
__device__ __align__(16) uint32_t g_WqF[8192];
__device__ __align__(16) uint32_t g_MlF[8192];

__device__ __forceinline__ uint32_t smem_u32(const void* p) {
    uint32_t a;
    asm("{ .reg .u64 t; cvta.to.shared.u64 t, %1; cvt.u32.u64 %0, t; }"
        : "=r"(a) : "l"(p));
    return a;
}
__device__ __forceinline__ void ldsm4(uint32_t addr, uint32_t& r0, uint32_t& r1,
                                      uint32_t& r2, uint32_t& r3) {
    asm volatile("ldmatrix.sync.aligned.m8n8.x4.shared.b16 {%0,%1,%2,%3}, [%4];"
                 : "=r"(r0), "=r"(r1), "=r"(r2), "=r"(r3) : "r"(addr));
}
__device__ __forceinline__ void ldsm4t(uint32_t addr, uint32_t& r0, uint32_t& r1,
                                       uint32_t& r2, uint32_t& r3) {
    asm volatile("ldmatrix.sync.aligned.m8n8.x4.trans.shared.b16 {%0,%1,%2,%3}, [%4];"
                 : "=r"(r0), "=r"(r1), "=r"(r2), "=r"(r3) : "r"(addr));
}
__device__ __forceinline__ void mma16816(float* c, uint32_t a0, uint32_t a1,
                                         uint32_t a2, uint32_t a3,
                                         uint32_t b0, uint32_t b1) {
    asm volatile("mma.sync.aligned.m16n8k16.row.col.f32.f16.f16.f32 "
                 "{%0,%1,%2,%3},{%4,%5,%6,%7},{%8,%9},{%0,%1,%2,%3};"
                 : "+f"(c[0]), "+f"(c[1]), "+f"(c[2]), "+f"(c[3])
                 : "r"(a0), "r"(a1), "r"(a2), "r"(a3), "r"(b0), "r"(b1));
}
__device__ __forceinline__ uint32_t pack_h2(float x, float y) {
    __half2 h = __halves2half2(__float2half_rn(x), __float2half_rn(y));
    return *(uint32_t*)&h;
}

__global__ void prep_weights(const float* __restrict__ wq,
                             const float* __restrict__ wk,
                             const float* __restrict__ wv,
                             const float* __restrict__ mlp) {
    int i = blockIdx.x * 256 + threadIdx.x;           // 0..65535
    if (i < 16384) {
        int breg = i & 1;
        int lane = (i >> 1) & 31;
        int nt   = (i >> 6) & 7;
        int ks   = (i >> 9) & 3;
        int w    = (i >> 11) & 7;
        int h  = w >> 2;
        int nc = (w & 3) * 64;
        int kr = ks * 16 + breg * 8 + (lane & 3) * 2;
        int kp = nc + nt * 8 + (lane >> 2);
        g_QKf[i] = pack_h2(wk[(h * 64 + kr) * 256 + kp],
                           wk[(h * 64 + kr + 1) * 256 + kp]);
    } else if (i < 32768) {
        int jj = i - 16384;
        int breg = jj & 1, l = (jj >> 1) & 31;
        int nt = (jj >> 6) & 1, ks = (jj >> 7) & 15, w = (jj >> 11) & 7;
        int h = w >> 2, j = w & 3;
        int col = h * 64 + j * 16 + nt * 8 + (l >> 2);
        int k0  = ks * 16 + breg * 8 + (l & 3) * 2;
        g_VF[jj] = pack_h2(wv[col * 256 + k0], wv[col * 256 + k0 + 1]);
    } else if (i < 49152) {
        int j = i - 32768;
        const float* W = (j < 8192) ? wq : mlp;
        int jj = j & 8191;
        int breg = jj & 1, l = (jj >> 1) & 31;
        int nt = (jj >> 6) & 1, ks = (jj >> 7) & 7, w = (jj >> 10) & 7;
        int col = w * 16 + nt * 8 + (l >> 2);
        int k0  = ks * 16 + breg * 8 + (l & 3) * 2;
        uint32_t v = pack_h2(W[col * 128 + k0], W[col * 128 + k0 + 1]);
        if (j < 8192) g_WqF[jj] = v; else g_MlF[jj] = v;
    }
}

__global__ __launch_bounds__(NTHR, 2)
void attn_mma_kernel(
    const int*   __restrict__ nodes,
    const float* __restrict__ times,
    const float* __restrict__ mem,
    const float* __restrict__ mail,
    const float* __restrict__ mail_time,
    const float* __restrict__ time_w,
    const float* __restrict__ time_b,
    const float* __restrict__ wq_b,
    const float* __restrict__ wk_b,
    const float* __restrict__ wv_b,
    const float* __restrict__ mlp_b,
    const float* __restrict__ ln_g,
    const float* __restrict__ ln_b,
    float*       __restrict__ out,
    int size)
{
    extern __shared__ __align__(1024) char smem[];
    const uint32_t sb = smem_u32(smem);
    const int tid = threadIdx.x, warp = tid >> 5, lane = tid & 31;
    const int base = blockIdx.x * NPB;

    int*   s_node = (int*)(smem + OFF_NODE);
    float* s_time = (float*)(smem + OFF_TIME);
    float* s_bv   = (float*)(smem + OFF_BV);
    float* s_att  = (float*)(smem + OFF_ATT);
    float* s_dt   = (float*)(smem + OFF_DT);
    float* s_qb   = (float*)(smem + OFF_QB);
    float* s_memf = (float*)(smem + OFF_MEM);
    float* s_out  = (float*)(smem + OFF_OUT);

    if (tid < NPB) {
        int g = base + tid; if (g >= size) g = size - 1;
        s_node[tid] = nodes[g];
        s_time[tid] = times[g];
    }
    if (tid >= 32 && tid < 64) s_qb[tid - 32] = 0.f;
    if (tid >= 128) s_bv[tid - 128] = wv_b[tid - 128];
    __syncthreads();

    if (tid < ROWS) {
        int n = tid >> 3, slot = tid & 7;
        s_dt[tid] = s_time[n] - __ldg(mail_time + (size_t)s_node[n] * MAIL + slot);
    }

    // gather mem rows (fp32) + hi fp16 copy into MH
    #pragma unroll
    for (int t = 0; t < 2; t++) {
        int idx = tid + t * NTHR;
        int n = idx >> 5, c4 = (idx & 31) * 4;
        float4 v = *(const float4*)(mem + (size_t)s_node[n] * DMEM + c4);
        ((float4*)s_memf)[idx] = v;
        uint2 hv = { pack_h2(v.x, v.y), pack_h2(v.z, v.w) };
        *(uint2*)(smem + OFF_MH + (uint32_t)(n * MHH + c4) * 2) = hv;
    }

    // mail half of A (fp16), single 8B store per float4
    {
        const int c4 = (tid & 31) * 4;
        #pragma unroll
        for (int t = 0; t < 16; t++) {
            int r = (tid >> 5) + t * 8;
            int n = r >> 3, slot = r & 7;
            float4 mv = *(const float4*)(mail + ((size_t)s_node[n] * MAIL + slot) * 128 + c4);
            uint2 hv = { pack_h2(mv.x, mv.y), pack_h2(mv.z, mv.w) };
            *(uint2*)(smem + OFF_A + ((size_t)r * AH + c4) * 2) = hv;
        }
    }
    __syncthreads();

    // time-encode half of A
    {
        const int j = (tid & 63) * 2;
        const float tw0 = __ldg(time_w + j), tw1 = __ldg(time_w + j + 1);
        const float tb0 = __ldg(time_b + j), tb1 = __ldg(time_b + j + 1);
        #pragma unroll
        for (int t = 0; t < 32; t++) {
            int r = (tid >> 6) + t * 4;
            float dt = s_dt[r];
            float v0 = __cosf(fmaf(dt, tw0, tb0));
            float v1 = __cosf(fmaf(dt, tw1, tb1));
            *(uint32_t*)(smem + OFF_A + ((size_t)r * AH + 128 + j) * 2) = pack_h2(v0, v1);
        }
    }

    const int g8 = lane >> 3, lr = lane & 7;
    const uint32_t mrow = lr + ((g8 & 1) << 3);
    const uint32_t mko  = (uint32_t)((g8 >> 1) << 3);
    const uint32_t mHa  = sb + OFF_MH + (mrow * MHH + mko) * 2;
    const int r4 = lane >> 2, cpos = 2 * (lane & 3);

    // ---- Q via MMA: warp w -> cols [w*16, w*16+16); write QH fp16 + qb atomics ----
    {
        float qa0[4] = {0.f, 0.f, 0.f, 0.f}, qa1[4] = {0.f, 0.f, 0.f, 0.f};
        const uint2* wfq = (const uint2*)g_WqF + (uint32_t)warp * 512 + lane;
        #pragma unroll
        for (int ks = 0; ks < 8; ks++) {
            uint2 bh0 = __ldg(wfq + ks * 64);
            uint2 bh1 = __ldg(wfq + ks * 64 + 32);
            uint32_t ah0, ah1, ah2, ah3;
            ldsm4(mHa + (uint32_t)ks * 32, ah0, ah1, ah2, ah3);
            mma16816(qa0, ah0, ah1, ah2, ah3, bh0.x, bh0.y);
            mma16816(qa1, ah0, ah1, ah2, ah3, bh1.x, bh1.y);
        }
        int col = warp * 16 + cpos;
        int h = warp >> 2;
        int cl = (warp & 3) * 16 + cpos;
        float b0 = __ldg(wq_b + col),     b1 = __ldg(wq_b + col + 1);
        float b8 = __ldg(wq_b + col + 8), b9 = __ldg(wq_b + col + 9);
        float q00 = qa0[0] + b0, q01 = qa0[1] + b1;
        float q02 = qa0[2] + b0, q03 = qa0[3] + b1;
        float q10 = qa1[0] + b8, q11 = qa1[1] + b9;
        float q12 = qa1[2] + b8, q13 = qa1[3] + b9;
        uint32_t rowA = (uint32_t)(h * 16 + r4) * QHS * 2;
        uint32_t rowB = (uint32_t)(h * 16 + r4 + 8) * QHS * 2;
        *(uint32_t*)(smem + OFF_QH + rowA + (uint32_t)cl * 2)       = pack_h2(q00, q01);
        *(uint32_t*)(smem + OFF_QH + rowB + (uint32_t)cl * 2)       = pack_h2(q02, q03);
        *(uint32_t*)(smem + OFF_QH + rowA + (uint32_t)(cl + 8) * 2) = pack_h2(q10, q11);
        *(uint32_t*)(smem + OFF_QH + rowB + (uint32_t)(cl + 8) * 2) = pack_h2(q12, q13);
        float k0 = __ldg(wk_b + col),     k1 = __ldg(wk_b + col + 1);
        float k8 = __ldg(wk_b + col + 8), k9 = __ldg(wk_b + col + 9);
        float cA = q00 * k0 + q01 * k1 + q10 * k8 + q11 * k9;
        float cB = q02 * k0 + q03 * k1 + q12 * k8 + q13 * k9;
        atomicAdd(&s_qb[r4 * 2 + h], cA);
        atomicAdd(&s_qb[(r4 + 8) * 2 + h], cB);
    }
    __syncthreads();

    // ---- Qk GEMM: Qk[n*2+h, kappa] = Q_h[n,:] @ Wk_h^T ----
    {
        const int h = warp >> 2, nc = (warp & 3) * 64;
        const uint32_t aQ = sb + OFF_QH + (((uint32_t)(h * 16) + mrow) * QHS + mko) * 2;
        float acc[8][4];
        #pragma unroll
        for (int t = 0; t < 8; t++)
            #pragma unroll
            for (int u = 0; u < 4; u++) acc[t][u] = 0.f;
        const uint2* wf = (const uint2*)g_QKf + (uint32_t)warp * 1024 + lane;
        #pragma unroll
        for (int ks = 0; ks < 4; ks++) {
            uint32_t a0, a1, a2, a3;
            ldsm4(aQ + (uint32_t)ks * 32, a0, a1, a2, a3);
            #pragma unroll
            for (int nt = 0; nt < 8; nt++) {
                uint2 b = __ldg(wf + (ks * 8 + nt) * 32);
                mma16816(acc[nt], a0, a1, a2, a3, b.x, b.y);
            }
        }
        #pragma unroll
        for (int nt = 0; nt < 8; nt++) {
            int k0 = nc + nt * 8 + cpos;
            *(uint32_t*)(smem + OFF_QK + ((uint32_t)(r4 * 2 + h) * AH + k0) * 2) =
                pack_h2(acc[nt][0], acc[nt][1]);
            *(uint32_t*)(smem + OFF_QK + ((uint32_t)((r4 + 8) * 2 + h) * AH + k0) * 2) =
                pack_h2(acc[nt][2], acc[nt][3]);
        }
    }
    __syncthreads();                                 // QK ready; QH now dead

    // ---- logits GEMM (+ parallel zero of attn tiles in dead QH region) ----
    {
        // zero attn-tile k-words 0..31 of all 32 rows: 1024 words by 256 threads
        #pragma unroll
        for (int z = 0; z < 4; z++) {
            int idx = tid + z * NTHR;                // 0..1023
            int row = idx >> 5, wrd = idx & 31;
            *(uint32_t*)(smem + OFF_QH + (uint32_t)row * QHS * 2 + (uint32_t)wrd * 4) = 0u;
        }
        const int t = warp >> 1;
        const uint32_t aL = sb + OFF_A + (((uint32_t)(warp * 16) + mrow) * AH + mko) * 2;
        const uint32_t bL = sb + OFF_QK +
            (((uint32_t)(8 * t + (lane & 7))) * AH + ((uint32_t)(lane >> 3) << 3)) * 2;
        float acc[4] = {0.f, 0.f, 0.f, 0.f};
        #pragma unroll
        for (int kp = 0; kp < 8; kp++) {
            uint32_t b0, b1, b2, b3;
            ldsm4(bL + (uint32_t)kp * 64, b0, b1, b2, b3);
            uint32_t a0, a1, a2, a3;
            ldsm4(aL + (uint32_t)kp * 64, a0, a1, a2, a3);
            mma16816(acc, a0, a1, a2, a3, b0, b1);
            ldsm4(aL + (uint32_t)kp * 64 + 32, a0, a1, a2, a3);
            mma16816(acc, a0, a1, a2, a3, b2, b3);
        }
        #pragma unroll
        for (int u = 0; u < 4; u++) {
            int row = (u >> 1) * 8 + r4;
            int colg = 8 * t + cpos + (u & 1);
            int n = colg >> 1, h2 = colg & 1;
            if (n == 2 * warp + (row >> 3)) {
                float v = acc[u] + s_qb[n * 2 + h2];
                v = (v >= 0.f) ? v : 0.2f * v;
                s_att[(n * 8 + (row & 7)) * 2 + h2] = v;
            }
        }
    }
    __syncthreads();

    // ---- softmax: writes ONLY its 4 nonzero tile words ----
    if (tid < 32) {
        int n = tid >> 1, h = tid & 1;
        float mx = -1e30f;
        #pragma unroll
        for (int s = 0; s < MAIL; s++) mx = fmaxf(mx, s_att[(n * 8 + s) * 2 + h]);
        float ex[MAIL], sum = 0.f;
        #pragma unroll
        for (int s = 0; s < MAIL; s++) { ex[s] = __expf(s_att[(n * 8 + s) * 2 + h] - mx); sum += ex[s]; }
        float inv = 1.f / sum;
        int t = n >> 3, rloc = (n & 7) * 2 + h;
        uint32_t rowB = (uint32_t)OFF_QH + (uint32_t)(t * 16 + rloc) * QHS * 2
                      + (uint32_t)(n & 7) * 16;      // 4 words at nonzero group
        #pragma unroll
        for (int w = 0; w < 4; w++) {
            int s2 = w * 2;
            *(uint32_t*)(smem + rowB + (uint32_t)w * 4) =
                pack_h2(ex[s2] * inv, ex[s2 + 1] * inv);
        }
    }
    __syncthreads();

    // ---- contraction via MMA: weighted[h*16+n, c] = attnTile @ Mcat ----
    {
        const int t = warp >> 2, cchunk = (warp & 3) * 64;
        const uint32_t aT = sb + OFF_QH +
            (((uint32_t)(t * 16 + (lane & 15))) * QHS + ((uint32_t)(lane >> 4) << 3)) * 2;
        const uint32_t bT = sb + OFF_A +
            (((uint32_t)(64 * t + (lane & 15))) * AH + (uint32_t)cchunk + ((uint32_t)(lane >> 4) << 3)) * 2;
        float acc[8][4];
        #pragma unroll
        for (int q = 0; q < 8; q++)
            #pragma unroll
            for (int u = 0; u < 4; u++) acc[q][u] = 0.f;
        #pragma unroll
        for (int ks = 0; ks < 4; ks++) {
            uint32_t a0, a1, a2, a3;
            ldsm4(aT + (uint32_t)ks * 32, a0, a1, a2, a3);
            #pragma unroll
            for (int nn2 = 0; nn2 < 4; nn2++) {
                uint32_t r0, r1, r2, r3;
                ldsm4t(bT + ((uint32_t)(ks * 16) * AH + (uint32_t)(nn2 * 16)) * 2,
                       r0, r1, r2, r3);
                mma16816(acc[nn2 * 2],     a0, a1, a2, a3, r0, r1);
                mma16816(acc[nn2 * 2 + 1], a0, a1, a2, a3, r2, r3);
            }
        }
        int n0 = 8 * t + (r4 >> 1), hh = r4 & 1;
        uint32_t ro0 = (uint32_t)(hh * 16 + n0) * AH * 2;
        uint32_t ro1 = (uint32_t)(hh * 16 + n0 + 4) * AH * 2;
        #pragma unroll
        for (int nn = 0; nn < 8; nn++) {
            uint32_t c2 = (uint32_t)(cchunk + nn * 8 + cpos) * 2;
            *(uint32_t*)(smem + OFF_A + ro0 + c2) = pack_h2(acc[nn][0], acc[nn][1]);
            *(uint32_t*)(smem + OFF_A + ro1 + c2) = pack_h2(acc[nn][2], acc[nn][3]);
        }
    }
    __syncthreads();

    // ---- V GEMM on contracted rows (software-pipelined B prefetch) ----
    {
        const int h = warp >> 2, j = warp & 3;
        const uint32_t aHi = sb + OFF_A + (((uint32_t)(h * 16) + mrow) * AH + mko) * 2;
        float qa0[4] = {0.f, 0.f, 0.f, 0.f}, qa1[4] = {0.f, 0.f, 0.f, 0.f};
        const uint2* wfv = (const uint2*)g_VF + (uint32_t)warp * 1024 + lane;
        uint2 b0 = __ldg(wfv);
        uint2 b1 = __ldg(wfv + 32);
        #pragma unroll
        for (int ks = 0; ks < 16; ks++) {
            uint2 nb0, nb1;
            if (ks < 15) {
                nb0 = __ldg(wfv + (ks + 1) * 64);
                nb1 = __ldg(wfv + (ks + 1) * 64 + 32);
            }
            uint32_t h0, h1, h2, h3;
            ldsm4(aHi + (uint32_t)ks * 32, h0, h1, h2, h3);
            mma16816(qa0, h0, h1, h2, h3, b0.x, b0.y);
            mma16816(qa1, h0, h1, h2, h3, b1.x, b1.y);
            b0 = nb0; b1 = nb1;
        }
        int col = h * 64 + j * 16 + cpos;
        #pragma unroll
        for (int half = 0; half < 2; half++) {
            int node = r4 + half * 8;
            float v0 = (half ? qa0[2] : qa0[0]) + s_bv[col]     + s_memf[node * 128 + col];
            float v1 = (half ? qa0[3] : qa0[1]) + s_bv[col + 1] + s_memf[node * 128 + col + 1];
            float v8 = (half ? qa1[2] : qa1[0]) + s_bv[col + 8] + s_memf[node * 128 + col + 8];
            float v9 = (half ? qa1[3] : qa1[1]) + s_bv[col + 9] + s_memf[node * 128 + col + 9];
            s_out[node * 128 + col]     = v0;
            s_out[node * 128 + col + 1] = v1;
            s_out[node * 128 + col + 8] = v8;
            s_out[node * 128 + col + 9] = v9;
        }
    }
    __syncthreads();

    // ---- LayerNorm: warp handles 2 nodes; writes hi fp16 into MH ----
    #pragma unroll
    for (int t = 0; t < 2; t++) {
        int n = warp * 2 + t;
        float4 x4 = ((float4*)(s_out + n * 128))[lane];
        float sum = x4.x + x4.y + x4.z + x4.w;
        float sq  = fmaf(x4.x, x4.x, fmaf(x4.y, x4.y, fmaf(x4.z, x4.z, x4.w * x4.w)));
        #pragma unroll
        for (int off = 16; off; off >>= 1) {
            sum += __shfl_xor_sync(0xffffffffu, sum, off);
            sq  += __shfl_xor_sync(0xffffffffu, sq, off);
        }
        float mu = sum * (1.f / 128.f);
        float rstd = rsqrtf(sq * (1.f / 128.f) - mu * mu + 1e-5f);
        float o[4] = {x4.x, x4.y, x4.z, x4.w};
        float y[4];
        #pragma unroll
        for (int u = 0; u < 4; u++) {
            int cc = lane * 4 + u;
            y[u] = (o[u] - mu) * rstd * __ldg(ln_g + cc) + __ldg(ln_b + cc);
        }
        uint2 hv = { pack_h2(y[0], y[1]), pack_h2(y[2], y[3]) };
        *(uint2*)(smem + OFF_MH + (uint32_t)(n * MHH + lane * 4) * 2) = hv;
    }
    __syncthreads();

    // ---- MLP via MMA + ReLU + store ----
    {
        float qa0[4] = {0.f, 0.f, 0.f, 0.f}, qa1[4] = {0.f, 0.f, 0.f, 0.f};
        const uint2* wfm = (const uint2*)g_MlF + (uint32_t)warp * 512 + lane;
        #pragma unroll
        for (int ks = 0; ks < 8; ks++) {
            uint2 bh0 = __ldg(wfm + ks * 64);
            uint2 bh1 = __ldg(wfm + ks * 64 + 32);
            uint32_t ah0, ah1, ah2, ah3;
            ldsm4(mHa + (uint32_t)ks * 32, ah0, ah1, ah2, ah3);
            mma16816(qa0, ah0, ah1, ah2, ah3, bh0.x, bh0.y);
            mma16816(qa1, ah0, ah1, ah2, ah3, bh1.x, bh1.y);
        }
        int col = warp * 16 + cpos;
        float b0 = __ldg(mlp_b + col),     b1 = __ldg(mlp_b + col + 1);
        float b8 = __ldg(mlp_b + col + 8), b9 = __ldg(mlp_b + col + 9);
        int g0 = base + r4, g1 = base + r4 + 8;
        if (g0 < size) {
            float2 v0 = { fmaxf(qa0[0] + b0, 0.f), fmaxf(qa0[1] + b1, 0.f) };
            float2 v1 = { fmaxf(qa1[0] + b8, 0.f), fmaxf(qa1[1] + b9, 0.f) };
            *(float2*)(out + (size_t)g0 * 128 + col)     = v0;
            *(float2*)(out + (size_t)g0 * 128 + col + 8) = v1;
        }
        if (g1 < size) {
            float2 v0 = { fmaxf(qa0[2] + b0, 0.f), fmaxf(qa0[3] + b1, 0.f) };
            float2 v1 = { fmaxf(qa1[2] + b8, 0.f), fmaxf(qa1[3] + b9, 0.f) };
            *(float2*)(out + (size_t)g1 * 128 + col)     = v0;
            *(float2*)(out + (size_t)g1 * 128 + col + 8) = v1;
        }
    }
}

extern "C" void kernel_launch(void* const* d_in, const int* in_sizes, int n_in,
                              void* d_out, int out_size) {
    const int*   nodes     = (const int*)  d_in[0];
    const float* times     = (const float*)d_in[1];
    const float* mem       = (const float*)d_in[2];
    const float* mail      = (const float*)d_in[3];
    const float* mail_time = (const float*)d_in[4];
    const float* time_w    = (const float*)d_in[5];
    const float* time_b    = (const float*)d_in[6];
    const float* wq_w      = (const float*)d_in[7];
    const float* wq_b      = (const float*)d_in[8];
    const float* wk_w      = (const float*)d_in[9];
    const float* wk_b      = (const float*)d_in[10];
    const float* wv_w      = (const float*)d_in[11];
    const float* wv_b      = (const float*)d_in[12];
    const float* mlp_w     = (const float*)d_in[13];
    const float* mlp_b     = (const float*)d_in[14];
    const float* ln_g      = (const float*)d_in[15];
    const float* ln_b      = (const float*)d_in[16];
    int size = in_sizes[0];

    cudaFuncSetAttribute(attn_mma_kernel,
                         cudaFuncAttributeMaxDynamicSharedMemorySize, SMEM_TOTAL);

    prep_weights<<<256, 256>>>(wq_w, wk_w, wv_w, mlp_w);

    int nblk = (size + NPB - 1) / NPB;
    attn_mma_kernel<<<nblk, NTHR, SMEM_TOTAL>>>(
        nodes, times, mem, mail, mail_time, time_w, time_b,
        wq_b, wk_b, wv_b, mlp_b, ln_g, ln_b,
        (float*)d_out, size);
}